// round 3
// baseline (speedup 1.0000x reference)
#include <cuda_runtime.h>
#include <math.h>

// Problem constants
#define BB   2
#define SS   2048
#define DD   1024
#define HH   16
#define LL   4
#define VV   2000
#define DK   64
#define DFF  4096
#define MM   (BB*SS)          // 4096 rows

// ------------------------- scratch (static device memory) -------------------
__device__ float g_x[MM*DD];      // activations [B*S, D]
__device__ float g_q[MM*DD];      // [B,H,S,DK]
__device__ float g_k[MM*DD];
__device__ float g_v[MM*DD];
__device__ float g_o[MM*DD];      // attention out, [B,S,D]
__device__ float g_t[MM*DD];      // temp (pre-LN residual branch)
__device__ float g_f[MM*DFF];     // FFN hidden

// ------------------------- embedding + positional encoding ------------------
// Reference computes PE in float64 then casts to f32 -> do the same.
__global__ void embed_kernel(const int* __restrict__ idx,
                             const float* __restrict__ emb,
                             float* __restrict__ x) {
    int t = blockIdx.x * blockDim.x + threadIdx.x;      // over B*S*(D/2)
    if (t >= BB*SS*(DD/2)) return;
    int dp = t & 511;            // pair index within row (D/2 = 512)
    int bs = t >> 9;
    int s  = bs & (SS - 1);
    int d  = dp << 1;            // even dim of the pair
    double freq = exp((double)d * (-9.210340371976184 / 1024.0)); // 10000^{-d/D}
    double ang  = (double)s * freq;
    double sv, cv;
    sincos(ang, &sv, &cv);
    int tok = idx[bs];
    float2 e = ((const float2*)emb)[(size_t)tok * 512 + dp];
    ((float2*)x)[t] = make_float2(e.x + (float)sv, e.y + (float)cv);
}

// ------------------------- GEMM: C[M,N] = A[M,K] * B[N,K]^T -----------------
// ACT: 0 = none, 1 = relu.  OMODE: 0 = row-major C[m*N+n], 1 = QKV remap to [B,H,S,DK]
template<int ACT, int OMODE>
__global__ __launch_bounds__(256)
void gemm_tn(const float* __restrict__ A, const float* __restrict__ Bw,
             float* __restrict__ C, int M, int N, int K) {
    __shared__ __align__(16) float As[8][128];
    __shared__ __align__(16) float Bs[8][128];
    const int tid  = threadIdx.x;
    const int row0 = blockIdx.y * 128;
    const int col0 = blockIdx.x * 128;
    const int lr = tid >> 1;          // 0..127
    const int lc = (tid & 1) * 4;     // 0 or 4
    const float* Ap = A  + (size_t)(row0 + lr) * K + lc;
    const float* Bp = Bw + (size_t)(col0 + lr) * K + lc;
    const bool bval = (col0 + lr) < N;
    const int ty = tid >> 4, tx = tid & 15;

    float acc[8][8];
#pragma unroll
    for (int i = 0; i < 8; i++)
#pragma unroll
        for (int j = 0; j < 8; j++) acc[i][j] = 0.f;

    for (int k0 = 0; k0 < K; k0 += 8) {
        float4 a4 = *(const float4*)(Ap + k0);
        float4 b4 = bval ? *(const float4*)(Bp + k0) : make_float4(0.f,0.f,0.f,0.f);
        __syncthreads();
        As[lc+0][lr] = a4.x; As[lc+1][lr] = a4.y; As[lc+2][lr] = a4.z; As[lc+3][lr] = a4.w;
        Bs[lc+0][lr] = b4.x; Bs[lc+1][lr] = b4.y; Bs[lc+2][lr] = b4.z; Bs[lc+3][lr] = b4.w;
        __syncthreads();
#pragma unroll
        for (int k = 0; k < 8; k++) {
            float ar[8], br[8];
            *(float4*)(ar)     = *(const float4*)&As[k][ty*8];
            *(float4*)(ar + 4) = *(const float4*)&As[k][ty*8 + 4];
            *(float4*)(br)     = *(const float4*)&Bs[k][tx*8];
            *(float4*)(br + 4) = *(const float4*)&Bs[k][tx*8 + 4];
#pragma unroll
            for (int i = 0; i < 8; i++)
#pragma unroll
                for (int j = 0; j < 8; j++)
                    acc[i][j] += ar[i] * br[j];
        }
    }

#pragma unroll
    for (int i = 0; i < 8; i++) {
        int m = row0 + ty*8 + i;
#pragma unroll
        for (int j = 0; j < 8; j++) {
            int n = col0 + tx*8 + j;
            if (n < N) {
                float v = acc[i][j];
                if (ACT == 1) v = fmaxf(v, 0.f);
                if (OMODE == 0) {
                    C[(size_t)m * N + n] = v;
                } else {
                    int b = m >> 11, s = m & (SS - 1);
                    int h = n >> 6,  kk = n & (DK - 1);
                    C[(size_t)((b*HH + h)*SS + s) * DK + kk] = v;
                }
            }
        }
    }
}

// ------------------------- flash attention (fp32, causal) -------------------
// grid: (S/128, B*H), 128 threads. One query row per thread; key tiles of 64.
__global__ __launch_bounds__(128)
void flash_kernel(const float* __restrict__ Q, const float* __restrict__ Kg,
                  const float* __restrict__ Vg, float* __restrict__ O) {
    __shared__ __align__(16) float Ks[64][64];
    __shared__ __align__(16) float Vs[64][64];
    const int bh  = blockIdx.y;
    const int qt  = blockIdx.x;
    const int tid = threadIdx.x;
    const int qg  = qt * 128 + tid;

    float q[64];
    {
        const float4* qp = (const float4*)(Q + ((size_t)bh * SS + qg) * DK);
#pragma unroll
        for (int i = 0; i < 16; i++) {
            float4 tq = qp[i];
            q[4*i] = tq.x; q[4*i+1] = tq.y; q[4*i+2] = tq.z; q[4*i+3] = tq.w;
        }
    }
    float acc[64];
#pragma unroll
    for (int i = 0; i < 64; i++) acc[i] = 0.f;
    float mi = -1e30f, li = 0.f;

    const int ntiles = 2*qt + 2;
    for (int tIdx = 0; tIdx < ntiles; tIdx++) {
        int j0 = tIdx * 64;
        const float4* ks = (const float4*)(Kg + ((size_t)bh * SS + j0) * DK);
        const float4* vs = (const float4*)(Vg + ((size_t)bh * SS + j0) * DK);
        __syncthreads();
        float4* kd = (float4*)&Ks[0][0];
        float4* vd = (float4*)&Vs[0][0];
#pragma unroll
        for (int i = 0; i < 8; i++) {
            kd[i*128 + tid] = ks[i*128 + tid];
            vd[i*128 + tid] = vs[i*128 + tid];
        }
        __syncthreads();

        int nv = qg - j0 + 1;                 // valid keys in this tile (causal)
        if (nv > 64) nv = 64;
        if (nv > 0) {
            for (int c = 0; c < 64; c += 16) {
                if (c >= nv) break;
                float s[16];
#pragma unroll
                for (int j = 0; j < 16; j++) {
                    const float4* kr = (const float4*)&Ks[c + j][0];
                    float sum = 0.f;
#pragma unroll
                    for (int d4 = 0; d4 < 16; d4++) {
                        float4 kk = kr[d4];
                        sum += q[4*d4]*kk.x + q[4*d4+1]*kk.y
                             + q[4*d4+2]*kk.z + q[4*d4+3]*kk.w;
                    }
                    s[j] = sum * 0.125f;      // 1/sqrt(64)
                }
                float cmax = -1e30f;
#pragma unroll
                for (int j = 0; j < 16; j++) {
                    if (c + j >= nv) s[j] = -1e30f;
                    cmax = fmaxf(cmax, s[j]);
                }
                float mn = fmaxf(mi, cmax);
                float sc = __expf(mi - mn);
                mi = mn;
                li *= sc;
#pragma unroll
                for (int d = 0; d < 64; d++) acc[d] *= sc;
#pragma unroll
                for (int j = 0; j < 16; j++) {
                    float p = __expf(s[j] - mn);
                    li += p;
                    const float4* vr = (const float4*)&Vs[c + j][0];
#pragma unroll
                    for (int d4 = 0; d4 < 16; d4++) {
                        float4 vv = vr[d4];
                        acc[4*d4]   += p * vv.x;
                        acc[4*d4+1] += p * vv.y;
                        acc[4*d4+2] += p * vv.z;
                        acc[4*d4+3] += p * vv.w;
                    }
                }
            }
        }
    }

    const int b = bh >> 4, h = bh & (HH - 1);
    const float inv = 1.f / li;
    float4* op = (float4*)(O + ((size_t)(b*SS + qg)) * DD + h * DK);
#pragma unroll
    for (int i = 0; i < 16; i++)
        op[i] = make_float4(acc[4*i]*inv, acc[4*i+1]*inv, acc[4*i+2]*inv, acc[4*i+3]*inv);
}

// ------------------------- residual add + layernorm (in place on x) ---------
__global__ __launch_bounds__(128)
void add_ln_kernel(float* __restrict__ x, const float* __restrict__ r,
                   const float* __restrict__ w, const float* __restrict__ bias) {
    __shared__ float sh[4];
    const int row = blockIdx.x;
    const int tid = threadIdx.x;
    float4* xr = (float4*)(x + (size_t)row * DD);
    const float4* rr = (const float4*)(r + (size_t)row * DD);
    float4 v0 = xr[tid], v1 = xr[tid + 128];
    float4 a0 = rr[tid], a1 = rr[tid + 128];
    v0.x += a0.x; v0.y += a0.y; v0.z += a0.z; v0.w += a0.w;
    v1.x += a1.x; v1.y += a1.y; v1.z += a1.z; v1.w += a1.w;

    float s = v0.x+v0.y+v0.z+v0.w + v1.x+v1.y+v1.z+v1.w;
#pragma unroll
    for (int o = 16; o > 0; o >>= 1) s += __shfl_down_sync(0xffffffffu, s, o);
    if ((tid & 31) == 0) sh[tid >> 5] = s;
    __syncthreads();
    float mean = (sh[0]+sh[1]+sh[2]+sh[3]) * (1.f/DD);
    __syncthreads();

    float dx0 = v0.x-mean, dx1 = v0.y-mean, dx2 = v0.z-mean, dx3 = v0.w-mean;
    float dy0 = v1.x-mean, dy1 = v1.y-mean, dy2 = v1.z-mean, dy3 = v1.w-mean;
    float sq = dx0*dx0+dx1*dx1+dx2*dx2+dx3*dx3 + dy0*dy0+dy1*dy1+dy2*dy2+dy3*dy3;
#pragma unroll
    for (int o = 16; o > 0; o >>= 1) sq += __shfl_down_sync(0xffffffffu, sq, o);
    if ((tid & 31) == 0) sh[tid >> 5] = sq;
    __syncthreads();
    float var = (sh[0]+sh[1]+sh[2]+sh[3]) * (1.f/DD);
    float rs = rsqrtf(var + 1e-5f);

    float4 w0 = ((const float4*)w)[tid],     w1 = ((const float4*)w)[tid + 128];
    float4 b0 = ((const float4*)bias)[tid],  b1 = ((const float4*)bias)[tid + 128];
    xr[tid]       = make_float4(dx0*rs*w0.x+b0.x, dx1*rs*w0.y+b0.y,
                                dx2*rs*w0.z+b0.z, dx3*rs*w0.w+b0.w);
    xr[tid + 128] = make_float4(dy0*rs*w1.x+b1.x, dy1*rs*w1.y+b1.y,
                                dy2*rs*w1.z+b1.z, dy3*rs*w1.w+b1.w);
}

// ------------------------- launch ------------------------------------------
extern "C" void kernel_launch(void* const* d_in, const int* in_sizes, int n_in,
                              void* d_out, int out_size) {
    (void)in_sizes; (void)n_in; (void)out_size;
    const int*   idx  = (const int*)  d_in[0];
    const float* emb  = (const float*)d_in[1];
    const float* Wq   = (const float*)d_in[2];
    const float* Wk   = (const float*)d_in[3];
    const float* Wv   = (const float*)d_in[4];
    const float* Wo   = (const float*)d_in[5];
    const float* ln1w = (const float*)d_in[6];
    const float* ln1b = (const float*)d_in[7];
    const float* W1   = (const float*)d_in[8];
    const float* W2   = (const float*)d_in[9];
    const float* ln2w = (const float*)d_in[10];
    const float* ln2b = (const float*)d_in[11];
    const float* Wout = (const float*)d_in[12];

    float *x, *q, *k, *v, *o, *t, *f;
    cudaGetSymbolAddress((void**)&x, g_x);
    cudaGetSymbolAddress((void**)&q, g_q);
    cudaGetSymbolAddress((void**)&k, g_k);
    cudaGetSymbolAddress((void**)&v, g_v);
    cudaGetSymbolAddress((void**)&o, g_o);
    cudaGetSymbolAddress((void**)&t, g_t);
    cudaGetSymbolAddress((void**)&f, g_f);

    embed_kernel<<<(BB*SS*(DD/2) + 255) / 256, 256>>>(idx, emb, x);

    for (int l = 0; l < LL; l++) {
        const size_t ws = (size_t)l * DD * DD;
        gemm_tn<0,1><<<dim3(8, 32), 256>>>(x, Wq + ws, q, MM, DD, DD);
        gemm_tn<0,1><<<dim3(8, 32), 256>>>(x, Wk + ws, k, MM, DD, DD);
        gemm_tn<0,1><<<dim3(8, 32), 256>>>(x, Wv + ws, v, MM, DD, DD);
        flash_kernel<<<dim3(SS/128, BB*HH), 128>>>(q, k, v, o);
        gemm_tn<0,0><<<dim3(8, 32), 256>>>(o, Wo + ws, t, MM, DD, DD);
        add_ln_kernel<<<MM, 128>>>(x, t, ln1w + l*DD, ln1b + l*DD);
        gemm_tn<1,0><<<dim3(32, 32), 256>>>(x, W1 + (size_t)l*DFF*DD, f, MM, DFF, DD);
        gemm_tn<0,0><<<dim3(8, 32), 256>>>(f, W2 + (size_t)l*DD*DFF, t, MM, DD, DFF);
        add_ln_kernel<<<MM, 128>>>(x, t, ln2w + l*DD, ln2b + l*DD);
    }
    gemm_tn<0,0><<<dim3((VV + 127)/128, 32), 256>>>(x, Wout, (float*)d_out, MM, VV, DD);
}

// round 5
// speedup vs baseline: 1.9190x; 1.9190x over previous
#include <cuda_runtime.h>
#include <cuda_bf16.h>
#include <math.h>
#include <stdint.h>

// Problem constants
#define BB   2
#define SS   2048
#define DD   1024
#define HH   16
#define LL   4
#define VV   2000
#define DK   64
#define DFF  4096
#define MM   (BB*SS)          // 4096 rows

// ------------------------- scratch (static device memory) -------------------
__device__ float g_x[MM*DD];      // activations [B*S, D]
__device__ float g_q[MM*DD];      // [B,H,S,DK]
__device__ float g_k[MM*DD];
__device__ float g_v[MM*DD];
__device__ float g_t[MM*DD];      // temp (pre-LN residual branch)
__device__ float g_f[MM*DFF];     // FFN hidden (post-relu fp32)

// bf16 split scratch (value = hi + lo, both bf16)
#define WQO 0u
#define WKO 4194304u
#define WVO 8388608u
#define WOO 12582912u
#define W1O 16777216u
#define W2O 33554432u
#define WUO 50331648u
#define WTOT 52379648u
__device__ __nv_bfloat16 g_wh[WTOT];
__device__ __nv_bfloat16 g_wl[WTOT];
__device__ __nv_bfloat16 g_xh[MM*DD],  g_xl[MM*DD];
__device__ __nv_bfloat16 g_oh[MM*DD],  g_ol[MM*DD];
__device__ __nv_bfloat16 g_fh[MM*DFF], g_fl[MM*DFF];

// ------------------------- PTX helpers --------------------------------------
__device__ __forceinline__ uint32_t s2u(const void* p) {
    uint32_t a;
    asm("{ .reg .u64 t; cvta.to.shared.u64 t, %1; cvt.u32.u64 %0, t; }"
        : "=r"(a) : "l"(p));
    return a;
}
__device__ __forceinline__ void cpa16(uint32_t s, const void* g) {
    asm volatile("cp.async.cg.shared.global [%0], [%1], 16;" :: "r"(s), "l"(g));
}
__device__ __forceinline__ void ldsm4(uint32_t* r, uint32_t a) {
    asm volatile("ldmatrix.sync.aligned.m8n8.x4.shared.b16 {%0,%1,%2,%3}, [%4];"
                 : "=r"(r[0]), "=r"(r[1]), "=r"(r[2]), "=r"(r[3]) : "r"(a));
}
__device__ __forceinline__ void ldsm2(uint32_t* r, uint32_t a) {
    asm volatile("ldmatrix.sync.aligned.m8n8.x2.shared.b16 {%0,%1}, [%2];"
                 : "=r"(r[0]), "=r"(r[1]) : "r"(a));
}
__device__ __forceinline__ void mma16816(float* c, const uint32_t* a, const uint32_t* b) {
    asm volatile(
        "mma.sync.aligned.m16n8k16.row.col.f32.bf16.bf16.f32 "
        "{%0,%1,%2,%3}, {%4,%5,%6,%7}, {%8,%9}, {%0,%1,%2,%3};"
        : "+f"(c[0]), "+f"(c[1]), "+f"(c[2]), "+f"(c[3])
        : "r"(a[0]), "r"(a[1]), "r"(a[2]), "r"(a[3]), "r"(b[0]), "r"(b[1]));
}

// ------------------------- split helpers -------------------------------------
__device__ __forceinline__ void split2(float a, float b,
                                       __nv_bfloat162* H, __nv_bfloat162* L, int i) {
    __nv_bfloat16 ha = __float2bfloat16(a), hb = __float2bfloat16(b);
    H[i] = __halves2bfloat162(ha, hb);
    L[i] = __halves2bfloat162(__float2bfloat16(a - __bfloat162float(ha)),
                              __float2bfloat16(b - __bfloat162float(hb)));
}

__global__ void split_kernel(const float* __restrict__ s,
                             __nv_bfloat16* __restrict__ h,
                             __nv_bfloat16* __restrict__ l, int n4) {
    int i = blockIdx.x * blockDim.x + threadIdx.x;
    if (i >= n4) return;
    float4 v = ((const float4*)s)[i];
    split2(v.x, v.y, (__nv_bfloat162*)h, (__nv_bfloat162*)l, i * 2);
    split2(v.z, v.w, (__nv_bfloat162*)h, (__nv_bfloat162*)l, i * 2 + 1);
}

// ------------------------- embedding + positional encoding ------------------
__global__ void embed_kernel(const int* __restrict__ idx,
                             const float* __restrict__ emb,
                             float* __restrict__ x) {
    int t = blockIdx.x * blockDim.x + threadIdx.x;
    if (t >= BB*SS*(DD/2)) return;
    int dp = t & 511;
    int bs = t >> 9;
    int s  = bs & (SS - 1);
    int d  = dp << 1;
    double freq = exp((double)d * (-9.210340371976184 / 1024.0));
    double ang  = (double)s * freq;
    double sv, cv;
    sincos(ang, &sv, &cv);
    int tok = idx[bs];
    float2 e = ((const float2*)emb)[(size_t)tok * 512 + dp];
    ((float2*)x)[t] = make_float2(e.x + (float)sv, e.y + (float)cv);
}

// ------------------------- mma.sync split-bf16 GEMM --------------------------
// C[M,N] = A[M,K] * B[N,K]^T, A = Ah+Al, B = Bh+Bl (bf16), fp32 accum via
// 3-term split: Ah*Bh + Ah*Bl + Al*Bh.
// Tile 128x128, K-tile 32, 256 threads, 8 warps in 2x4 (64x32 warp tiles).
// Double-buffered cp.async smem. ldmatrix from padded smem (stride 40 elems).
#define LDSB   80          // smem row stride in bytes (40 bf16)
#define TILEB  10240       // one 128x40 bf16 tile
#define STAGEB (4*TILEB)   // Ah, Al, Bh, Bl
#define GSMEM  (2*STAGEB)  // 81920

template<int ACT, int OMODE>
__global__ __launch_bounds__(256)
void gemm_tc(const __nv_bfloat16* __restrict__ Ah, const __nv_bfloat16* __restrict__ Al,
             const __nv_bfloat16* __restrict__ Bh, const __nv_bfloat16* __restrict__ Bl,
             float* __restrict__ C, int M, int N, int K)
{
    extern __shared__ __align__(16) char smem[];
    const uint32_t sb = s2u(smem);
    const int tid = threadIdx.x;
    const int wid = tid >> 5, lane = tid & 31;
    const int wm = wid & 1, wn = wid >> 1;           // warp 64x32 tile at (wm*64, wn*32)
    const int row0 = blockIdx.y * 128, col0 = blockIdx.x * 128;

    // global load mapping: chunk = 16B of k, rr = row within tile (2 passes)
    const int chunk = tid & 3;          // k-offset chunk*8 elems
    const int rr    = tid >> 2;         // 0..63
    const int rA0 = row0 + rr, rA1 = row0 + rr + 64;
    int rB0 = col0 + rr;      if (rB0 > N - 1) rB0 = N - 1;
    int rB1 = col0 + rr + 64; if (rB1 > N - 1) rB1 = N - 1;
    const uint32_t s0 = (uint32_t)rr * LDSB + (uint32_t)chunk * 16;
    const uint32_t s1 = s0 + 64u * LDSB;

    auto issue = [&](int kt, int buf) {
        const int ko = kt * 32 + chunk * 8;
        const uint32_t base = sb + (uint32_t)buf * STAGEB;
        cpa16(base +             s0, Ah + (size_t)rA0 * K + ko);
        cpa16(base +             s1, Ah + (size_t)rA1 * K + ko);
        cpa16(base + TILEB     + s0, Al + (size_t)rA0 * K + ko);
        cpa16(base + TILEB     + s1, Al + (size_t)rA1 * K + ko);
        cpa16(base + 2*TILEB   + s0, Bh + (size_t)rB0 * K + ko);
        cpa16(base + 2*TILEB   + s1, Bh + (size_t)rB1 * K + ko);
        cpa16(base + 3*TILEB   + s0, Bl + (size_t)rB0 * K + ko);
        cpa16(base + 3*TILEB   + s1, Bl + (size_t)rB1 * K + ko);
        asm volatile("cp.async.commit_group;" ::: "memory");
    };

    float acc[4][4][4];
#pragma unroll
    for (int i = 0; i < 4; i++)
#pragma unroll
        for (int j = 0; j < 4; j++)
#pragma unroll
            for (int q = 0; q < 4; q++) acc[i][j][q] = 0.f;

    const int KT = K >> 5;
    issue(0, 0);
    issue(1, 1);

    // ldmatrix addresses (within a stage)
    const uint32_t aoff = (uint32_t)(wm*64 + (lane & 15)) * LDSB + ((lane >> 4) << 4);
    const uint32_t boff = (uint32_t)(wn*32 + (lane & 7))  * LDSB + (((lane >> 3) & 1) << 4);

#pragma unroll 1
    for (int kt = 0; kt < KT; kt++) {
        const int buf = kt & 1;
        if (kt == KT - 1) asm volatile("cp.async.wait_group 0;" ::: "memory");
        else              asm volatile("cp.async.wait_group 1;" ::: "memory");
        __syncthreads();
        const uint32_t base = sb + (uint32_t)buf * STAGEB;
#pragma unroll
        for (int ks = 0; ks < 2; ks++) {
            uint32_t ah[4][4], al[4][4], bh[4][2], bl[4][2];
            const uint32_t ka = base + (uint32_t)ks * 32 + aoff;
            const uint32_t kb = base + (uint32_t)ks * 32 + boff;
#pragma unroll
            for (int mt = 0; mt < 4; mt++) {
                ldsm4(ah[mt], ka + (uint32_t)mt * (16*LDSB));
                ldsm4(al[mt], ka + TILEB + (uint32_t)mt * (16*LDSB));
            }
#pragma unroll
            for (int nt = 0; nt < 4; nt++) {
                ldsm2(bh[nt], kb + 2*TILEB + (uint32_t)nt * (8*LDSB));
                ldsm2(bl[nt], kb + 3*TILEB + (uint32_t)nt * (8*LDSB));
            }
#pragma unroll
            for (int mt = 0; mt < 4; mt++)
#pragma unroll
                for (int nt = 0; nt < 4; nt++) {
                    mma16816(acc[mt][nt], ah[mt], bh[nt]);
                    mma16816(acc[mt][nt], ah[mt], bl[nt]);
                    mma16816(acc[mt][nt], al[mt], bh[nt]);
                }
        }
        __syncthreads();
        if (kt + 2 < KT) issue(kt + 2, buf);
    }

    // epilogue: thread holds c{0,1} at (r, c..c+1), c{2,3} at (r+8, c..c+1)
    const int base_m = row0 + wm*64;
    const int base_n = col0 + wn*32;
#pragma unroll
    for (int mt = 0; mt < 4; mt++) {
#pragma unroll
        for (int nt = 0; nt < 4; nt++) {
            float* c = acc[mt][nt];
            if (ACT == 1) {
                c[0] = fmaxf(c[0], 0.f); c[1] = fmaxf(c[1], 0.f);
                c[2] = fmaxf(c[2], 0.f); c[3] = fmaxf(c[3], 0.f);
            }
            const int r0 = base_m + mt*16 + (lane >> 2);
            const int cc = base_n + nt*8 + (lane & 3)*2;
            if (OMODE == 0) {
                if (cc < N) {
                    *(float2*)(C + (size_t)r0 * N + cc)       = make_float2(c[0], c[1]);
                    *(float2*)(C + (size_t)(r0 + 8) * N + cc) = make_float2(c[2], c[3]);
                }
            } else {
                // QKV remap: row m=(b,s), col n=(h,kk) -> [B,H,S,DK]
                const int h = cc >> 6, kk = cc & (DK - 1);
                const int b0 = r0 >> 11, s0r = r0 & (SS - 1);
                *(float2*)(C + ((size_t)((b0*HH + h)*SS + s0r)) * DK + kk)
                    = make_float2(c[0], c[1]);
                const int r1 = r0 + 8;
                const int b1 = r1 >> 11, s1r = r1 & (SS - 1);
                *(float2*)(C + ((size_t)((b1*HH + h)*SS + s1r)) * DK + kk)
                    = make_float2(c[2], c[3]);
            }
        }
    }
}

// ------------------------- flash attention (fp32, causal) -------------------
// Writes attention output directly as bf16 hi/lo split.
__global__ __launch_bounds__(128)
void flash_kernel(const float* __restrict__ Q, const float* __restrict__ Kg,
                  const float* __restrict__ Vg,
                  __nv_bfloat16* __restrict__ OH, __nv_bfloat16* __restrict__ OL) {
    __shared__ __align__(16) float Ks[64][64];
    __shared__ __align__(16) float Vs[64][64];
    const int bh  = blockIdx.y;
    const int qt  = gridDim.x - 1 - blockIdx.x;   // heavy blocks first
    const int tid = threadIdx.x;
    const int qg  = qt * 128 + tid;

    float q[64];
    {
        const float4* qp = (const float4*)(Q + ((size_t)bh * SS + qg) * DK);
#pragma unroll
        for (int i = 0; i < 16; i++) {
            float4 tq = qp[i];
            q[4*i] = tq.x; q[4*i+1] = tq.y; q[4*i+2] = tq.z; q[4*i+3] = tq.w;
        }
    }
    float acc[64];
#pragma unroll
    for (int i = 0; i < 64; i++) acc[i] = 0.f;
    float mi = -1e30f, li = 0.f;

    const int ntiles = 2*qt + 2;
    for (int tIdx = 0; tIdx < ntiles; tIdx++) {
        int j0 = tIdx * 64;
        const float4* ks = (const float4*)(Kg + ((size_t)bh * SS + j0) * DK);
        const float4* vs = (const float4*)(Vg + ((size_t)bh * SS + j0) * DK);
        __syncthreads();
        float4* kd = (float4*)&Ks[0][0];
        float4* vd = (float4*)&Vs[0][0];
#pragma unroll
        for (int i = 0; i < 8; i++) {
            kd[i*128 + tid] = ks[i*128 + tid];
            vd[i*128 + tid] = vs[i*128 + tid];
        }
        __syncthreads();

        int nv = qg - j0 + 1;
        if (nv > 64) nv = 64;
        if (nv > 0) {
            for (int c = 0; c < 64; c += 16) {
                if (c >= nv) break;
                float s[16];
#pragma unroll
                for (int j = 0; j < 16; j++) {
                    const float4* kr = (const float4*)&Ks[c + j][0];
                    float sum = 0.f;
#pragma unroll
                    for (int d4 = 0; d4 < 16; d4++) {
                        float4 kk = kr[d4];
                        sum += q[4*d4]*kk.x + q[4*d4+1]*kk.y
                             + q[4*d4+2]*kk.z + q[4*d4+3]*kk.w;
                    }
                    s[j] = sum * 0.125f;
                }
                float cmax = -1e30f;
#pragma unroll
                for (int j = 0; j < 16; j++) {
                    if (c + j >= nv) s[j] = -1e30f;
                    cmax = fmaxf(cmax, s[j]);
                }
                float mn = fmaxf(mi, cmax);
                float sc = __expf(mi - mn);
                mi = mn;
                li *= sc;
#pragma unroll
                for (int d = 0; d < 64; d++) acc[d] *= sc;
#pragma unroll
                for (int j = 0; j < 16; j++) {
                    float p = __expf(s[j] - mn);
                    li += p;
                    const float4* vr = (const float4*)&Vs[c + j][0];
#pragma unroll
                    for (int d4 = 0; d4 < 16; d4++) {
                        float4 vv = vr[d4];
                        acc[4*d4]   += p * vv.x;
                        acc[4*d4+1] += p * vv.y;
                        acc[4*d4+2] += p * vv.z;
                        acc[4*d4+3] += p * vv.w;
                    }
                }
            }
        }
    }

    const int b = bh >> 4, h = bh & (HH - 1);
    const float inv = 1.f / li;
    const size_t base = ((size_t)(b*SS + qg)) * DD + h * DK;
    __nv_bfloat162* oh2 = (__nv_bfloat162*)(OH + base);
    __nv_bfloat162* ol2 = (__nv_bfloat162*)(OL + base);
#pragma unroll
    for (int i = 0; i < 32; i++)
        split2(acc[2*i] * inv, acc[2*i+1] * inv, oh2, ol2, i);
}

// ------------------------- residual add + layernorm + split -----------------
__global__ __launch_bounds__(128)
void add_ln_kernel(float* __restrict__ x, const float* __restrict__ r,
                   const float* __restrict__ w, const float* __restrict__ bias,
                   __nv_bfloat16* __restrict__ xh, __nv_bfloat16* __restrict__ xl) {
    __shared__ float sh[4];
    const int row = blockIdx.x;
    const int tid = threadIdx.x;
    float4* xr = (float4*)(x + (size_t)row * DD);
    const float4* rr = (const float4*)(r + (size_t)row * DD);
    float4 v0 = xr[tid], v1 = xr[tid + 128];
    float4 a0 = rr[tid], a1 = rr[tid + 128];
    v0.x += a0.x; v0.y += a0.y; v0.z += a0.z; v0.w += a0.w;
    v1.x += a1.x; v1.y += a1.y; v1.z += a1.z; v1.w += a1.w;

    float s = v0.x+v0.y+v0.z+v0.w + v1.x+v1.y+v1.z+v1.w;
#pragma unroll
    for (int o = 16; o > 0; o >>= 1) s += __shfl_down_sync(0xffffffffu, s, o);
    if ((tid & 31) == 0) sh[tid >> 5] = s;
    __syncthreads();
    float mean = (sh[0]+sh[1]+sh[2]+sh[3]) * (1.f/DD);
    __syncthreads();

    float dx0 = v0.x-mean, dx1 = v0.y-mean, dx2 = v0.z-mean, dx3 = v0.w-mean;
    float dy0 = v1.x-mean, dy1 = v1.y-mean, dy2 = v1.z-mean, dy3 = v1.w-mean;
    float sq = dx0*dx0+dx1*dx1+dx2*dx2+dx3*dx3 + dy0*dy0+dy1*dy1+dy2*dy2+dy3*dy3;
#pragma unroll
    for (int o = 16; o > 0; o >>= 1) sq += __shfl_down_sync(0xffffffffu, sq, o);
    if ((tid & 31) == 0) sh[tid >> 5] = sq;
    __syncthreads();
    float var = (sh[0]+sh[1]+sh[2]+sh[3]) * (1.f/DD);
    float rs = rsqrtf(var + 1e-5f);

    float4 w0 = ((const float4*)w)[tid],     w1 = ((const float4*)w)[tid + 128];
    float4 b0 = ((const float4*)bias)[tid],  b1 = ((const float4*)bias)[tid + 128];
    float4 o0 = make_float4(dx0*rs*w0.x+b0.x, dx1*rs*w0.y+b0.y,
                            dx2*rs*w0.z+b0.z, dx3*rs*w0.w+b0.w);
    float4 o1 = make_float4(dy0*rs*w1.x+b1.x, dy1*rs*w1.y+b1.y,
                            dy2*rs*w1.z+b1.z, dy3*rs*w1.w+b1.w);
    xr[tid]       = o0;
    xr[tid + 128] = o1;

    __nv_bfloat162* H = (__nv_bfloat162*)(xh + (size_t)row * DD);
    __nv_bfloat162* L = (__nv_bfloat162*)(xl + (size_t)row * DD);
    split2(o0.x, o0.y, H, L, tid*2);
    split2(o0.z, o0.w, H, L, tid*2 + 1);
    split2(o1.x, o1.y, H, L, (tid+128)*2);
    split2(o1.z, o1.w, H, L, (tid+128)*2 + 1);
}

// ------------------------- launch ------------------------------------------
extern "C" void kernel_launch(void* const* d_in, const int* in_sizes, int n_in,
                              void* d_out, int out_size) {
    (void)in_sizes; (void)n_in; (void)out_size;
    const int*   idx  = (const int*)  d_in[0];
    const float* emb  = (const float*)d_in[1];
    const float* Wq   = (const float*)d_in[2];
    const float* Wk   = (const float*)d_in[3];
    const float* Wv   = (const float*)d_in[4];
    const float* Wo   = (const float*)d_in[5];
    const float* ln1w = (const float*)d_in[6];
    const float* ln1b = (const float*)d_in[7];
    const float* W1   = (const float*)d_in[8];
    const float* W2   = (const float*)d_in[9];
    const float* ln2w = (const float*)d_in[10];
    const float* ln2b = (const float*)d_in[11];
    const float* Wout = (const float*)d_in[12];

    float *x, *q, *k, *v, *t, *f;
    __nv_bfloat16 *wh, *wl, *xh, *xl, *oh, *ol, *fh, *fl;
    cudaGetSymbolAddress((void**)&x, g_x);
    cudaGetSymbolAddress((void**)&q, g_q);
    cudaGetSymbolAddress((void**)&k, g_k);
    cudaGetSymbolAddress((void**)&v, g_v);
    cudaGetSymbolAddress((void**)&t, g_t);
    cudaGetSymbolAddress((void**)&f, g_f);
    cudaGetSymbolAddress((void**)&wh, g_wh);
    cudaGetSymbolAddress((void**)&wl, g_wl);
    cudaGetSymbolAddress((void**)&xh, g_xh);
    cudaGetSymbolAddress((void**)&xl, g_xl);
    cudaGetSymbolAddress((void**)&oh, g_oh);
    cudaGetSymbolAddress((void**)&ol, g_ol);
    cudaGetSymbolAddress((void**)&fh, g_fh);
    cudaGetSymbolAddress((void**)&fl, g_fl);

    cudaFuncSetAttribute(gemm_tc<0,0>, cudaFuncAttributeMaxDynamicSharedMemorySize, GSMEM);
    cudaFuncSetAttribute(gemm_tc<0,1>, cudaFuncAttributeMaxDynamicSharedMemorySize, GSMEM);
    cudaFuncSetAttribute(gemm_tc<1,0>, cudaFuncAttributeMaxDynamicSharedMemorySize, GSMEM);

    // weight splits (once per launch)
    {
        int n4;
        n4 = (LL*DD*DD)/4;
        split_kernel<<<(n4+255)/256, 256>>>(Wq, wh+WQO, wl+WQO, n4);
        split_kernel<<<(n4+255)/256, 256>>>(Wk, wh+WKO, wl+WKO, n4);
        split_kernel<<<(n4+255)/256, 256>>>(Wv, wh+WVO, wl+WVO, n4);
        split_kernel<<<(n4+255)/256, 256>>>(Wo, wh+WOO, wl+WOO, n4);
        n4 = (LL*DFF*DD)/4;
        split_kernel<<<(n4+255)/256, 256>>>(W1, wh+W1O, wl+W1O, n4);
        split_kernel<<<(n4+255)/256, 256>>>(W2, wh+W2O, wl+W2O, n4);
        n4 = (VV*DD)/4;
        split_kernel<<<(n4+255)/256, 256>>>(Wout, wh+WUO, wl+WUO, n4);
    }

    embed_kernel<<<(BB*SS*(DD/2) + 255) / 256, 256>>>(idx, emb, x);
    split_kernel<<<(MM*DD/4 + 255)/256, 256>>>(x, xh, xl, MM*DD/4);

    for (int l = 0; l < LL; l++) {
        const size_t ws = (size_t)l * DD * DD;
        gemm_tc<0,1><<<dim3(8, 32), 256, GSMEM>>>(xh, xl, wh+WQO+ws, wl+WQO+ws, q, MM, DD, DD);
        gemm_tc<0,1><<<dim3(8, 32), 256, GSMEM>>>(xh, xl, wh+WKO+ws, wl+WKO+ws, k, MM, DD, DD);
        gemm_tc<0,1><<<dim3(8, 32), 256, GSMEM>>>(xh, xl, wh+WVO+ws, wl+WVO+ws, v, MM, DD, DD);
        flash_kernel<<<dim3(SS/128, BB*HH), 128>>>(q, k, v, oh, ol);
        gemm_tc<0,0><<<dim3(8, 32), 256, GSMEM>>>(oh, ol, wh+WOO+ws, wl+WOO+ws, t, MM, DD, DD);
        add_ln_kernel<<<MM, 128>>>(x, t, ln1w + l*DD, ln1b + l*DD, xh, xl);
        const size_t wf = (size_t)l * DFF * DD;
        gemm_tc<1,0><<<dim3(32, 32), 256, GSMEM>>>(xh, xl, wh+W1O+wf, wl+W1O+wf, f, MM, DFF, DD);
        split_kernel<<<(MM*DFF/4 + 255)/256, 256>>>(f, fh, fl, MM*DFF/4);
        gemm_tc<0,0><<<dim3(8, 32), 256, GSMEM>>>(fh, fl, wh+W2O+wf, wl+W2O+wf, t, MM, DD, DFF);
        add_ln_kernel<<<MM, 128>>>(x, t, ln2w + l*DD, ln2b + l*DD, xh, xl);
    }
    gemm_tc<0,0><<<dim3(16, 32), 256, GSMEM>>>(xh, xl, wh+WUO, wl+WUO, (float*)d_out, MM, VV, DD);
}

// round 8
// speedup vs baseline: 1.9447x; 1.0134x over previous
#include <cuda_runtime.h>
#include <cuda_bf16.h>
#include <math.h>
#include <stdint.h>

// Problem constants
#define BB   2
#define SS   2048
#define DD   1024
#define HH   16
#define LL   4
#define VV   2000
#define DK   64
#define DFF  4096
#define MM   (BB*SS)          // 4096 rows

// ------------------------- scratch (static device memory) -------------------
__device__ float g_x[MM*DD];      // activations [B*S, D]
__device__ float g_q[MM*DD];      // [B,H,S,DK]
__device__ float g_k[MM*DD];
__device__ float g_v[MM*DD];
__device__ float g_t[MM*DD];      // temp (pre-LN residual branch)

// bf16 split scratch (value = hi + lo, both bf16)
#define WQO 0u
#define WKO 4194304u
#define WVO 8388608u
#define WOO 12582912u
#define W1O 16777216u
#define W2O 33554432u
#define WUO 50331648u
#define WTOT 52379648u
__device__ __nv_bfloat16 g_wh[WTOT];
__device__ __nv_bfloat16 g_wl[WTOT];
__device__ __nv_bfloat16 g_xh[MM*DD],  g_xl[MM*DD];
__device__ __nv_bfloat16 g_oh[MM*DD],  g_ol[MM*DD];
__device__ __nv_bfloat16 g_fh[MM*DFF], g_fl[MM*DFF];

// ------------------------- PTX helpers --------------------------------------
__device__ __forceinline__ uint32_t s2u(const void* p) {
    uint32_t a;
    asm("{ .reg .u64 t; cvta.to.shared.u64 t, %1; cvt.u32.u64 %0, t; }"
        : "=r"(a) : "l"(p));
    return a;
}
__device__ __forceinline__ void cpa16(uint32_t s, const void* g) {
    asm volatile("cp.async.cg.shared.global [%0], [%1], 16;" :: "r"(s), "l"(g));
}
__device__ __forceinline__ void ldsm4(uint32_t* r, uint32_t a) {
    asm volatile("ldmatrix.sync.aligned.m8n8.x4.shared.b16 {%0,%1,%2,%3}, [%4];"
                 : "=r"(r[0]), "=r"(r[1]), "=r"(r[2]), "=r"(r[3]) : "r"(a));
}
__device__ __forceinline__ void mma16816(float* c, const uint32_t* a, const uint32_t* b) {
    asm volatile(
        "mma.sync.aligned.m16n8k16.row.col.f32.bf16.bf16.f32 "
        "{%0,%1,%2,%3}, {%4,%5,%6,%7}, {%8,%9}, {%0,%1,%2,%3};"
        : "+f"(c[0]), "+f"(c[1]), "+f"(c[2]), "+f"(c[3])
        : "r"(a[0]), "r"(a[1]), "r"(a[2]), "r"(a[3]), "r"(b[0]), "r"(b[1]));
}

// ------------------------- split helpers -------------------------------------
__device__ __forceinline__ void split2(float a, float b,
                                       __nv_bfloat162* H, __nv_bfloat162* L, int i) {
    __nv_bfloat16 ha = __float2bfloat16(a), hb = __float2bfloat16(b);
    H[i] = __halves2bfloat162(ha, hb);
    L[i] = __halves2bfloat162(__float2bfloat16(a - __bfloat162float(ha)),
                              __float2bfloat16(b - __bfloat162float(hb)));
}

__global__ void split_kernel(const float* __restrict__ s,
                             __nv_bfloat16* __restrict__ h,
                             __nv_bfloat16* __restrict__ l, int n4) {
    int i = blockIdx.x * blockDim.x + threadIdx.x;
    if (i >= n4) return;
    float4 v = ((const float4*)s)[i];
    split2(v.x, v.y, (__nv_bfloat162*)h, (__nv_bfloat162*)l, i * 2);
    split2(v.z, v.w, (__nv_bfloat162*)h, (__nv_bfloat162*)l, i * 2 + 1);
}

// ------------------------- embedding + positional encoding ------------------
__global__ void embed_kernel(const int* __restrict__ idx,
                             const float* __restrict__ emb,
                             float* __restrict__ x) {
    int t = blockIdx.x * blockDim.x + threadIdx.x;
    if (t >= BB*SS*(DD/2)) return;
    int dp = t & 511;
    int bs = t >> 9;
    int s  = bs & (SS - 1);
    int d  = dp << 1;
    double freq = exp((double)d * (-9.210340371976184 / 1024.0));
    double ang  = (double)s * freq;
    double sv, cv;
    sincos(ang, &sv, &cv);
    int tok = idx[bs];
    float2 e = ((const float2*)emb)[(size_t)tok * 512 + dp];
    ((float2*)x)[t] = make_float2(e.x + (float)sv, e.y + (float)cv);
}

// ------------------------- mma.sync split-bf16 GEMM --------------------------
// C[M,N] = A[M,K] * B[N,K]^T, A = Ah+Al, B = Bh+Bl (bf16), fp32 accum via
// 3-term split: Ah*Bh + Ah*Bl + Al*Bh.
// CTA tile 128x256, K-tile 32, 256 threads, 8 warps in 2x4 (64x64 warp tiles).
// 3-stage cp.async pipeline. ldmatrix from padded smem (stride 40 elems).
// OMODE: 0 = fp32 row-major, 1 = QKV remap [B,H,S,DK], 2 = bf16 hi/lo split out.
#define LDSB   80            // smem row stride in bytes (40 bf16)
#define ATILE  (128*LDSB)    // 10240
#define BTILE  (256*LDSB)    // 20480
#define STAGEB (2*ATILE + 2*BTILE)   // 61440: Ah, Al, Bh, Bl
#define NSTAGE 3
#define GSMEM  (NSTAGE*STAGEB)       // 184320

template<int ACT, int OMODE>
__global__ __launch_bounds__(256)
void gemm_tc(const __nv_bfloat16* __restrict__ Ah, const __nv_bfloat16* __restrict__ Al,
             const __nv_bfloat16* __restrict__ Bh, const __nv_bfloat16* __restrict__ Bl,
             float* __restrict__ C,
             __nv_bfloat16* __restrict__ CH, __nv_bfloat16* __restrict__ CL,
             int M, int N, int K)
{
    extern __shared__ __align__(16) char smem[];
    const uint32_t sb = s2u(smem);
    const int tid = threadIdx.x;
    const int wid = tid >> 5, lane = tid & 31;
    const int wm = wid & 1, wn = wid >> 1;           // warp 64x64 tile at (wm*64, wn*64)
    const int row0 = blockIdx.y * 128, col0 = blockIdx.x * 256;

    // global load mapping
    const int chunk = tid & 3;          // 16B chunk within 64B row
    const int rr    = tid >> 2;         // 0..63
    const int rA0 = row0 + rr, rA1 = rA0 + 64;
    int rB0 = col0 + rr;       if (rB0 > N - 1) rB0 = N - 1;
    int rB1 = col0 + rr + 64;  if (rB1 > N - 1) rB1 = N - 1;
    int rB2 = col0 + rr + 128; if (rB2 > N - 1) rB2 = N - 1;
    int rB3 = col0 + rr + 192; if (rB3 > N - 1) rB3 = N - 1;
    const uint32_t sA0 = (uint32_t)rr * LDSB + (uint32_t)chunk * 16;

    auto issue = [&](int kt, int buf) {
        const int ko = kt * 32 + chunk * 8;
        const uint32_t base = sb + (uint32_t)buf * STAGEB;
        // A hi/lo (rows rr, rr+64)
        cpa16(base +          sA0,             Ah + (size_t)rA0 * K + ko);
        cpa16(base +          sA0 + 64u*LDSB,  Ah + (size_t)rA1 * K + ko);
        cpa16(base + ATILE +  sA0,             Al + (size_t)rA0 * K + ko);
        cpa16(base + ATILE +  sA0 + 64u*LDSB,  Al + (size_t)rA1 * K + ko);
        // B hi/lo (rows rr, +64, +128, +192)
        const uint32_t bb = base + 2*ATILE;
        cpa16(bb +           sA0,              Bh + (size_t)rB0 * K + ko);
        cpa16(bb +           sA0 +  64u*LDSB,  Bh + (size_t)rB1 * K + ko);
        cpa16(bb +           sA0 + 128u*LDSB,  Bh + (size_t)rB2 * K + ko);
        cpa16(bb +           sA0 + 192u*LDSB,  Bh + (size_t)rB3 * K + ko);
        cpa16(bb + BTILE +   sA0,              Bl + (size_t)rB0 * K + ko);
        cpa16(bb + BTILE +   sA0 +  64u*LDSB,  Bl + (size_t)rB1 * K + ko);
        cpa16(bb + BTILE +   sA0 + 128u*LDSB,  Bl + (size_t)rB2 * K + ko);
        cpa16(bb + BTILE +   sA0 + 192u*LDSB,  Bl + (size_t)rB3 * K + ko);
        asm volatile("cp.async.commit_group;" ::: "memory");
    };

    float acc[4][8][4];
#pragma unroll
    for (int i = 0; i < 4; i++)
#pragma unroll
        for (int j = 0; j < 8; j++)
#pragma unroll
            for (int q = 0; q < 4; q++) acc[i][j][q] = 0.f;

    const int KT = K >> 5;
    issue(0, 0);
    issue(1, 1);
    issue(2, 2);

    // ldmatrix base offsets (within a stage)
    // A: x4 -> one 16x16 m-tile.  lanes 0-15: rows m0-15 k-chunk0; 16-31: k-chunk1
    const uint32_t aoff = (uint32_t)(wm*64 + (lane & 15)) * LDSB + ((lane >> 4) << 4);
    // B: x4 -> two adjacent 8-wide n-tiles (16 rows of B).
    // lanes 0-7: n0-7 k0; 8-15: n0-7 k8; 16-23: n8-15 k0; 24-31: n8-15 k8
    const uint32_t boff = (uint32_t)(wn*64 + (lane & 7) + ((lane >> 4) << 3)) * LDSB
                        + (((lane >> 3) & 1) << 4);

    int buf = 0;
#pragma unroll 1
    for (int kt = 0; kt < KT; kt++) {
        if (kt + 2 < KT)      asm volatile("cp.async.wait_group 2;" ::: "memory");
        else if (kt + 1 < KT) asm volatile("cp.async.wait_group 1;" ::: "memory");
        else                  asm volatile("cp.async.wait_group 0;" ::: "memory");
        __syncthreads();
        const uint32_t base = sb + (uint32_t)buf * STAGEB;
#pragma unroll
        for (int ks = 0; ks < 2; ks++) {
            const uint32_t ka = base + (uint32_t)ks * 32 + aoff;
            const uint32_t kb = base + 2*ATILE + (uint32_t)ks * 32 + boff;
            uint32_t ah[4][4], al[4][4];
#pragma unroll
            for (int mt = 0; mt < 4; mt++) {
                ldsm4(ah[mt], ka +         (uint32_t)mt * (16*LDSB));
                ldsm4(al[mt], ka + ATILE + (uint32_t)mt * (16*LDSB));
            }
#pragma unroll
            for (int p = 0; p < 4; p++) {
                uint32_t bh4[4], bl4[4];
                ldsm4(bh4, kb +         (uint32_t)p * (16*LDSB));
                ldsm4(bl4, kb + BTILE + (uint32_t)p * (16*LDSB));
#pragma unroll
                for (int mt = 0; mt < 4; mt++) {
                    mma16816(acc[mt][2*p],   ah[mt], bh4);
                    mma16816(acc[mt][2*p],   ah[mt], bl4);
                    mma16816(acc[mt][2*p],   al[mt], bh4);
                    mma16816(acc[mt][2*p+1], ah[mt], bh4 + 2);
                    mma16816(acc[mt][2*p+1], ah[mt], bl4 + 2);
                    mma16816(acc[mt][2*p+1], al[mt], bh4 + 2);
                }
            }
        }
        __syncthreads();
        if (kt + 3 < KT) issue(kt + 3, buf);
        buf = (buf == 2) ? 0 : buf + 1;
    }

    // epilogue: thread holds c{0,1} at (r, c..c+1), c{2,3} at (r+8, c..c+1)
    const int base_m = row0 + wm*64;
    const int base_n = col0 + wn*64;
#pragma unroll
    for (int mt = 0; mt < 4; mt++) {
#pragma unroll
        for (int nt = 0; nt < 8; nt++) {
            float* c = acc[mt][nt];
            if (ACT == 1) {
                c[0] = fmaxf(c[0], 0.f); c[1] = fmaxf(c[1], 0.f);
                c[2] = fmaxf(c[2], 0.f); c[3] = fmaxf(c[3], 0.f);
            }
            const int r0 = base_m + mt*16 + (lane >> 2);
            const int cc = base_n + nt*8 + (lane & 3)*2;
            if (OMODE == 0) {
                if (cc < N) {
                    *(float2*)(C + (size_t)r0 * N + cc)       = make_float2(c[0], c[1]);
                    *(float2*)(C + (size_t)(r0 + 8) * N + cc) = make_float2(c[2], c[3]);
                }
            } else if (OMODE == 1) {
                const int h = cc >> 6, kk = cc & (DK - 1);
                const int b0 = r0 >> 11, s0r = r0 & (SS - 1);
                *(float2*)(C + ((size_t)((b0*HH + h)*SS + s0r)) * DK + kk)
                    = make_float2(c[0], c[1]);
                const int r1 = r0 + 8;
                const int b1 = r1 >> 11, s1r = r1 & (SS - 1);
                *(float2*)(C + ((size_t)((b1*HH + h)*SS + s1r)) * DK + kk)
                    = make_float2(c[2], c[3]);
            } else {
                if (cc < N) {
                    split2(c[0], c[1], (__nv_bfloat162*)CH, (__nv_bfloat162*)CL,
                           ((size_t)r0 * N + cc) >> 1);
                    split2(c[2], c[3], (__nv_bfloat162*)CH, (__nv_bfloat162*)CL,
                           ((size_t)(r0 + 8) * N + cc) >> 1);
                }
            }
        }
    }
}

// ------------------------- flash attention (fp32, causal) -------------------
// Writes attention output directly as bf16 hi/lo split.
__global__ __launch_bounds__(128)
void flash_kernel(const float* __restrict__ Q, const float* __restrict__ Kg,
                  const float* __restrict__ Vg,
                  __nv_bfloat16* __restrict__ OH, __nv_bfloat16* __restrict__ OL) {
    __shared__ __align__(16) float Ks[64][64];
    __shared__ __align__(16) float Vs[64][64];
    const int bh  = blockIdx.y;
    const int qt  = gridDim.x - 1 - blockIdx.x;   // heavy blocks first
    const int tid = threadIdx.x;
    const int qg  = qt * 128 + tid;

    float q[64];
    {
        const float4* qp = (const float4*)(Q + ((size_t)bh * SS + qg) * DK);
#pragma unroll
        for (int i = 0; i < 16; i++) {
            float4 tq = qp[i];
            q[4*i] = tq.x; q[4*i+1] = tq.y; q[4*i+2] = tq.z; q[4*i+3] = tq.w;
        }
    }
    float acc[64];
#pragma unroll
    for (int i = 0; i < 64; i++) acc[i] = 0.f;
    float mi = -1e30f, li = 0.f;

    const int ntiles = 2*qt + 2;
    for (int tIdx = 0; tIdx < ntiles; tIdx++) {
        int j0 = tIdx * 64;
        const float4* ks = (const float4*)(Kg + ((size_t)bh * SS + j0) * DK);
        const float4* vs = (const float4*)(Vg + ((size_t)bh * SS + j0) * DK);
        __syncthreads();
        float4* kd = (float4*)&Ks[0][0];
        float4* vd = (float4*)&Vs[0][0];
#pragma unroll
        for (int i = 0; i < 8; i++) {
            kd[i*128 + tid] = ks[i*128 + tid];
            vd[i*128 + tid] = vs[i*128 + tid];
        }
        __syncthreads();

        int nv = qg - j0 + 1;
        if (nv > 64) nv = 64;
        if (nv > 0) {
            for (int c = 0; c < 64; c += 16) {
                if (c >= nv) break;
                float s[16];
#pragma unroll
                for (int j = 0; j < 16; j++) {
                    const float4* kr = (const float4*)&Ks[c + j][0];
                    float sum = 0.f;
#pragma unroll
                    for (int d4 = 0; d4 < 16; d4++) {
                        float4 kk = kr[d4];
                        sum += q[4*d4]*kk.x + q[4*d4+1]*kk.y
                             + q[4*d4+2]*kk.z + q[4*d4+3]*kk.w;
                    }
                    s[j] = sum * 0.125f;
                }
                float cmax = -1e30f;
#pragma unroll
                for (int j = 0; j < 16; j++) {
                    if (c + j >= nv) s[j] = -1e30f;
                    cmax = fmaxf(cmax, s[j]);
                }
                float mn = fmaxf(mi, cmax);
                float sc = __expf(mi - mn);
                mi = mn;
                li *= sc;
#pragma unroll
                for (int d = 0; d < 64; d++) acc[d] *= sc;
#pragma unroll
                for (int j = 0; j < 16; j++) {
                    float p = __expf(s[j] - mn);
                    li += p;
                    const float4* vr = (const float4*)&Vs[c + j][0];
#pragma unroll
                    for (int d4 = 0; d4 < 16; d4++) {
                        float4 vv = vr[d4];
                        acc[4*d4]   += p * vv.x;
                        acc[4*d4+1] += p * vv.y;
                        acc[4*d4+2] += p * vv.z;
                        acc[4*d4+3] += p * vv.w;
                    }
                }
            }
        }
    }

    const int b = bh >> 4, h = bh & (HH - 1);
    const float inv = 1.f / li;
    const size_t base = ((size_t)(b*SS + qg)) * DD + h * DK;
    __nv_bfloat162* oh2 = (__nv_bfloat162*)(OH + base);
    __nv_bfloat162* ol2 = (__nv_bfloat162*)(OL + base);
#pragma unroll
    for (int i = 0; i < 32; i++)
        split2(acc[2*i] * inv, acc[2*i+1] * inv, oh2, ol2, i);
}

// ------------------------- residual add + layernorm + split -----------------
__global__ __launch_bounds__(128)
void add_ln_kernel(float* __restrict__ x, const float* __restrict__ r,
                   const float* __restrict__ w, const float* __restrict__ bias,
                   __nv_bfloat16* __restrict__ xh, __nv_bfloat16* __restrict__ xl) {
    __shared__ float sh[4];
    const int row = blockIdx.x;
    const int tid = threadIdx.x;
    float4* xr = (float4*)(x + (size_t)row * DD);
    const float4* rr = (const float4*)(r + (size_t)row * DD);
    float4 v0 = xr[tid], v1 = xr[tid + 128];
    float4 a0 = rr[tid], a1 = rr[tid + 128];
    v0.x += a0.x; v0.y += a0.y; v0.z += a0.z; v0.w += a0.w;
    v1.x += a1.x; v1.y += a1.y; v1.z += a1.z; v1.w += a1.w;

    float s = v0.x+v0.y+v0.z+v0.w + v1.x+v1.y+v1.z+v1.w;
#pragma unroll
    for (int o = 16; o > 0; o >>= 1) s += __shfl_down_sync(0xffffffffu, s, o);
    if ((tid & 31) == 0) sh[tid >> 5] = s;
    __syncthreads();
    float mean = (sh[0]+sh[1]+sh[2]+sh[3]) * (1.f/DD);
    __syncthreads();

    float dx0 = v0.x-mean, dx1 = v0.y-mean, dx2 = v0.z-mean, dx3 = v0.w-mean;
    float dy0 = v1.x-mean, dy1 = v1.y-mean, dy2 = v1.z-mean, dy3 = v1.w-mean;
    float sq = dx0*dx0+dx1*dx1+dx2*dx2+dx3*dx3 + dy0*dy0+dy1*dy1+dy2*dy2+dy3*dy3;
#pragma unroll
    for (int o = 16; o > 0; o >>= 1) sq += __shfl_down_sync(0xffffffffu, sq, o);
    if ((tid & 31) == 0) sh[tid >> 5] = sq;
    __syncthreads();
    float var = (sh[0]+sh[1]+sh[2]+sh[3]) * (1.f/DD);
    float rs = rsqrtf(var + 1e-5f);

    float4 w0 = ((const float4*)w)[tid],     w1 = ((const float4*)w)[tid + 128];
    float4 b0 = ((const float4*)bias)[tid],  b1 = ((const float4*)bias)[tid + 128];
    float4 o0 = make_float4(dx0*rs*w0.x+b0.x, dx1*rs*w0.y+b0.y,
                            dx2*rs*w0.z+b0.z, dx3*rs*w0.w+b0.w);
    float4 o1 = make_float4(dy0*rs*w1.x+b1.x, dy1*rs*w1.y+b1.y,
                            dy2*rs*w1.z+b1.z, dy3*rs*w1.w+b1.w);
    xr[tid]       = o0;
    xr[tid + 128] = o1;

    __nv_bfloat162* H = (__nv_bfloat162*)(xh + (size_t)row * DD);
    __nv_bfloat162* L = (__nv_bfloat162*)(xl + (size_t)row * DD);
    split2(o0.x, o0.y, H, L, tid*2);
    split2(o0.z, o0.w, H, L, tid*2 + 1);
    split2(o1.x, o1.y, H, L, (tid+128)*2);
    split2(o1.z, o1.w, H, L, (tid+128)*2 + 1);
}

// ------------------------- launch ------------------------------------------
extern "C" void kernel_launch(void* const* d_in, const int* in_sizes, int n_in,
                              void* d_out, int out_size) {
    (void)in_sizes; (void)n_in; (void)out_size;
    const int*   idx  = (const int*)  d_in[0];
    const float* emb  = (const float*)d_in[1];
    const float* Wq   = (const float*)d_in[2];
    const float* Wk   = (const float*)d_in[3];
    const float* Wv   = (const float*)d_in[4];
    const float* Wo   = (const float*)d_in[5];
    const float* ln1w = (const float*)d_in[6];
    const float* ln1b = (const float*)d_in[7];
    const float* W1   = (const float*)d_in[8];
    const float* W2   = (const float*)d_in[9];
    const float* ln2w = (const float*)d_in[10];
    const float* ln2b = (const float*)d_in[11];
    const float* Wout = (const float*)d_in[12];

    float *x, *q, *k, *v, *t;
    __nv_bfloat16 *wh, *wl, *xh, *xl, *oh, *ol, *fh, *fl;
    cudaGetSymbolAddress((void**)&x, g_x);
    cudaGetSymbolAddress((void**)&q, g_q);
    cudaGetSymbolAddress((void**)&k, g_k);
    cudaGetSymbolAddress((void**)&v, g_v);
    cudaGetSymbolAddress((void**)&t, g_t);
    cudaGetSymbolAddress((void**)&wh, g_wh);
    cudaGetSymbolAddress((void**)&wl, g_wl);
    cudaGetSymbolAddress((void**)&xh, g_xh);
    cudaGetSymbolAddress((void**)&xl, g_xl);
    cudaGetSymbolAddress((void**)&oh, g_oh);
    cudaGetSymbolAddress((void**)&ol, g_ol);
    cudaGetSymbolAddress((void**)&fh, g_fh);
    cudaGetSymbolAddress((void**)&fl, g_fl);

    cudaFuncSetAttribute(gemm_tc<0,0>, cudaFuncAttributeMaxDynamicSharedMemorySize, GSMEM);
    cudaFuncSetAttribute(gemm_tc<0,1>, cudaFuncAttributeMaxDynamicSharedMemorySize, GSMEM);
    cudaFuncSetAttribute(gemm_tc<1,2>, cudaFuncAttributeMaxDynamicSharedMemorySize, GSMEM);

    // weight splits (once per launch)
    {
        int n4;
        n4 = (LL*DD*DD)/4;
        split_kernel<<<(n4+255)/256, 256>>>(Wq, wh+WQO, wl+WQO, n4);
        split_kernel<<<(n4+255)/256, 256>>>(Wk, wh+WKO, wl+WKO, n4);
        split_kernel<<<(n4+255)/256, 256>>>(Wv, wh+WVO, wl+WVO, n4);
        split_kernel<<<(n4+255)/256, 256>>>(Wo, wh+WOO, wl+WOO, n4);
        n4 = (LL*DFF*DD)/4;
        split_kernel<<<(n4+255)/256, 256>>>(W1, wh+W1O, wl+W1O, n4);
        split_kernel<<<(n4+255)/256, 256>>>(W2, wh+W2O, wl+W2O, n4);
        n4 = (VV*DD)/4;
        split_kernel<<<(n4+255)/256, 256>>>(Wout, wh+WUO, wl+WUO, n4);
    }

    embed_kernel<<<(BB*SS*(DD/2) + 255) / 256, 256>>>(idx, emb, x);
    split_kernel<<<(MM*DD/4 + 255)/256, 256>>>(x, xh, xl, MM*DD/4);

    for (int l = 0; l < LL; l++) {
        const size_t ws = (size_t)l * DD * DD;
        gemm_tc<0,1><<<dim3(4, 32), 256, GSMEM>>>(xh, xl, wh+WQO+ws, wl+WQO+ws,
                                                  q, nullptr, nullptr, MM, DD, DD);
        gemm_tc<0,1><<<dim3(4, 32), 256, GSMEM>>>(xh, xl, wh+WKO+ws, wl+WKO+ws,
                                                  k, nullptr, nullptr, MM, DD, DD);
        gemm_tc<0,1><<<dim3(4, 32), 256, GSMEM>>>(xh, xl, wh+WVO+ws, wl+WVO+ws,
                                                  v, nullptr, nullptr, MM, DD, DD);
        flash_kernel<<<dim3(SS/128, BB*HH), 128>>>(q, k, v, oh, ol);
        gemm_tc<0,0><<<dim3(4, 32), 256, GSMEM>>>(oh, ol, wh+WOO+ws, wl+WOO+ws,
                                                  t, nullptr, nullptr, MM, DD, DD);
        add_ln_kernel<<<MM, 128>>>(x, t, ln1w + l*DD, ln1b + l*DD, xh, xl);
        const size_t wf = (size_t)l * DFF * DD;
        gemm_tc<1,2><<<dim3(16, 32), 256, GSMEM>>>(xh, xl, wh+W1O+wf, wl+W1O+wf,
                                                   nullptr, fh, fl, MM, DFF, DD);
        gemm_tc<0,0><<<dim3(4, 32), 256, GSMEM>>>(fh, fl, wh+W2O+wf, wl+W2O+wf,
                                                  t, nullptr, nullptr, MM, DD, DFF);
        add_ln_kernel<<<MM, 128>>>(x, t, ln2w + l*DD, ln2b + l*DD, xh, xl);
    }
    gemm_tc<0,0><<<dim3(8, 32), 256, GSMEM>>>(xh, xl, wh+WUO, wl+WUO,
                                              (float*)d_out, nullptr, nullptr, MM, VV, DD);
}

// round 9
// speedup vs baseline: 3.0658x; 1.5765x over previous
#include <cuda_runtime.h>
#include <cuda_bf16.h>
#include <math.h>
#include <stdint.h>

// Problem constants
#define BB   2
#define SS   2048
#define DD   1024
#define HH   16
#define LL   4
#define VV   2000
#define DK   64
#define DFF  4096
#define MM   (BB*SS)          // 4096 rows

// ------------------------- scratch (static device memory) -------------------
__device__ float g_x[MM*DD];      // activations [B*S, D]
__device__ float g_t[MM*DD];      // temp (pre-LN residual branch)

// bf16 split scratch (value = hi + lo, both bf16)
#define WQO 0u
#define WKO 4194304u
#define WVO 8388608u
#define WOO 12582912u
#define W1O 16777216u
#define W2O 33554432u
#define WUO 50331648u
#define WTOT 52379648u
__device__ __nv_bfloat16 g_wh[WTOT];
__device__ __nv_bfloat16 g_wl[WTOT];
__device__ __nv_bfloat16 g_xh[MM*DD],  g_xl[MM*DD];
__device__ __nv_bfloat16 g_oh[MM*DD],  g_ol[MM*DD];
__device__ __nv_bfloat16 g_fh[MM*DFF], g_fl[MM*DFF];
// QKV in [B,H,S,DK] bf16 hi/lo
__device__ __nv_bfloat16 g_qh[MM*DD], g_ql[MM*DD];
__device__ __nv_bfloat16 g_kh[MM*DD], g_kl[MM*DD];
__device__ __nv_bfloat16 g_vh[MM*DD], g_vl[MM*DD];

// ------------------------- PTX helpers --------------------------------------
__device__ __forceinline__ uint32_t s2u(const void* p) {
    uint32_t a;
    asm("{ .reg .u64 t; cvta.to.shared.u64 t, %1; cvt.u32.u64 %0, t; }"
        : "=r"(a) : "l"(p));
    return a;
}
__device__ __forceinline__ void cpa16(uint32_t s, const void* g) {
    asm volatile("cp.async.cg.shared.global [%0], [%1], 16;" :: "r"(s), "l"(g));
}
__device__ __forceinline__ void ldsm4(uint32_t* r, uint32_t a) {
    asm volatile("ldmatrix.sync.aligned.m8n8.x4.shared.b16 {%0,%1,%2,%3}, [%4];"
                 : "=r"(r[0]), "=r"(r[1]), "=r"(r[2]), "=r"(r[3]) : "r"(a));
}
__device__ __forceinline__ void ldsm4t(uint32_t* r, uint32_t a) {
    asm volatile("ldmatrix.sync.aligned.m8n8.x4.trans.shared.b16 {%0,%1,%2,%3}, [%4];"
                 : "=r"(r[0]), "=r"(r[1]), "=r"(r[2]), "=r"(r[3]) : "r"(a));
}
__device__ __forceinline__ void mma16816(float* c, const uint32_t* a, const uint32_t* b) {
    asm volatile(
        "mma.sync.aligned.m16n8k16.row.col.f32.bf16.bf16.f32 "
        "{%0,%1,%2,%3}, {%4,%5,%6,%7}, {%8,%9}, {%0,%1,%2,%3};"
        : "+f"(c[0]), "+f"(c[1]), "+f"(c[2]), "+f"(c[3])
        : "r"(a[0]), "r"(a[1]), "r"(a[2]), "r"(a[3]), "r"(b[0]), "r"(b[1]));
}

// ------------------------- split helpers -------------------------------------
__device__ __forceinline__ void split2(float a, float b,
                                       __nv_bfloat162* H, __nv_bfloat162* L, int i) {
    __nv_bfloat16 ha = __float2bfloat16(a), hb = __float2bfloat16(b);
    H[i] = __halves2bfloat162(ha, hb);
    L[i] = __halves2bfloat162(__float2bfloat16(a - __bfloat162float(ha)),
                              __float2bfloat16(b - __bfloat162float(hb)));
}
__device__ __forceinline__ uint32_t packsplit(float a, float b, uint32_t& lo) {
    __nv_bfloat16 ha = __float2bfloat16(a), hb = __float2bfloat16(b);
    __nv_bfloat162 h2 = __halves2bfloat162(ha, hb);
    __nv_bfloat162 l2 = __halves2bfloat162(__float2bfloat16(a - __bfloat162float(ha)),
                                           __float2bfloat16(b - __bfloat162float(hb)));
    lo = *(uint32_t*)&l2;
    return *(uint32_t*)&h2;
}

__global__ void split_kernel(const float* __restrict__ s,
                             __nv_bfloat16* __restrict__ h,
                             __nv_bfloat16* __restrict__ l, int n4) {
    int i = blockIdx.x * blockDim.x + threadIdx.x;
    if (i >= n4) return;
    float4 v = ((const float4*)s)[i];
    split2(v.x, v.y, (__nv_bfloat162*)h, (__nv_bfloat162*)l, i * 2);
    split2(v.z, v.w, (__nv_bfloat162*)h, (__nv_bfloat162*)l, i * 2 + 1);
}

// ------------------------- embedding + positional encoding ------------------
__global__ void embed_kernel(const int* __restrict__ idx,
                             const float* __restrict__ emb,
                             float* __restrict__ x) {
    int t = blockIdx.x * blockDim.x + threadIdx.x;
    if (t >= BB*SS*(DD/2)) return;
    int dp = t & 511;
    int bs = t >> 9;
    int s  = bs & (SS - 1);
    int d  = dp << 1;
    double freq = exp((double)d * (-9.210340371976184 / 1024.0));
    double ang  = (double)s * freq;
    double sv, cv;
    sincos(ang, &sv, &cv);
    int tok = idx[bs];
    float2 e = ((const float2*)emb)[(size_t)tok * 512 + dp];
    ((float2*)x)[t] = make_float2(e.x + (float)sv, e.y + (float)cv);
}

// ------------------------- mma.sync split-bf16 GEMM --------------------------
// C[M,N] = A[M,K] * B[N,K]^T, 3-term split: Ah*Bh + Ah*Bl + Al*Bh.
// CTA tile 128x256, K-tile 32, 256 threads, 8 warps (64x64 warp tiles).
// OMODE: 0 = fp32 row-major, 1 = bf16 hi/lo split, QKV remap [B,H,S,DK],
//        2 = bf16 hi/lo split row-major.
#define LDSB   80            // smem row stride in bytes (40 bf16)
#define ATILE  (128*LDSB)    // 10240
#define BTILE  (256*LDSB)    // 20480
#define STAGEB (2*ATILE + 2*BTILE)   // 61440
#define NSTAGE 3
#define GSMEM  (NSTAGE*STAGEB)       // 184320

template<int ACT, int OMODE>
__global__ __launch_bounds__(256)
void gemm_tc(const __nv_bfloat16* __restrict__ Ah, const __nv_bfloat16* __restrict__ Al,
             const __nv_bfloat16* __restrict__ Bh, const __nv_bfloat16* __restrict__ Bl,
             float* __restrict__ C,
             __nv_bfloat16* __restrict__ CH, __nv_bfloat16* __restrict__ CL,
             int M, int N, int K)
{
    extern __shared__ __align__(16) char smem[];
    const uint32_t sb = s2u(smem);
    const int tid = threadIdx.x;
    const int wid = tid >> 5, lane = tid & 31;
    const int wm = wid & 1, wn = wid >> 1;
    const int row0 = blockIdx.y * 128, col0 = blockIdx.x * 256;

    const int chunk = tid & 3;
    const int rr    = tid >> 2;
    const int rA0 = row0 + rr, rA1 = rA0 + 64;
    int rB0 = col0 + rr;       if (rB0 > N - 1) rB0 = N - 1;
    int rB1 = col0 + rr + 64;  if (rB1 > N - 1) rB1 = N - 1;
    int rB2 = col0 + rr + 128; if (rB2 > N - 1) rB2 = N - 1;
    int rB3 = col0 + rr + 192; if (rB3 > N - 1) rB3 = N - 1;
    const uint32_t sA0 = (uint32_t)rr * LDSB + (uint32_t)chunk * 16;

    auto issue = [&](int kt, int buf) {
        const int ko = kt * 32 + chunk * 8;
        const uint32_t base = sb + (uint32_t)buf * STAGEB;
        cpa16(base +          sA0,             Ah + (size_t)rA0 * K + ko);
        cpa16(base +          sA0 + 64u*LDSB,  Ah + (size_t)rA1 * K + ko);
        cpa16(base + ATILE +  sA0,             Al + (size_t)rA0 * K + ko);
        cpa16(base + ATILE +  sA0 + 64u*LDSB,  Al + (size_t)rA1 * K + ko);
        const uint32_t bb = base + 2*ATILE;
        cpa16(bb +           sA0,              Bh + (size_t)rB0 * K + ko);
        cpa16(bb +           sA0 +  64u*LDSB,  Bh + (size_t)rB1 * K + ko);
        cpa16(bb +           sA0 + 128u*LDSB,  Bh + (size_t)rB2 * K + ko);
        cpa16(bb +           sA0 + 192u*LDSB,  Bh + (size_t)rB3 * K + ko);
        cpa16(bb + BTILE +   sA0,              Bl + (size_t)rB0 * K + ko);
        cpa16(bb + BTILE +   sA0 +  64u*LDSB,  Bl + (size_t)rB1 * K + ko);
        cpa16(bb + BTILE +   sA0 + 128u*LDSB,  Bl + (size_t)rB2 * K + ko);
        cpa16(bb + BTILE +   sA0 + 192u*LDSB,  Bl + (size_t)rB3 * K + ko);
        asm volatile("cp.async.commit_group;" ::: "memory");
    };

    float acc[4][8][4];
#pragma unroll
    for (int i = 0; i < 4; i++)
#pragma unroll
        for (int j = 0; j < 8; j++)
#pragma unroll
            for (int q = 0; q < 4; q++) acc[i][j][q] = 0.f;

    const int KT = K >> 5;
    issue(0, 0);
    issue(1, 1);
    issue(2, 2);

    const uint32_t aoff = (uint32_t)(wm*64 + (lane & 15)) * LDSB + ((lane >> 4) << 4);
    const uint32_t boff = (uint32_t)(wn*64 + (lane & 7) + ((lane >> 4) << 3)) * LDSB
                        + (((lane >> 3) & 1) << 4);

    int buf = 0;
#pragma unroll 1
    for (int kt = 0; kt < KT; kt++) {
        if (kt + 2 < KT)      asm volatile("cp.async.wait_group 2;" ::: "memory");
        else if (kt + 1 < KT) asm volatile("cp.async.wait_group 1;" ::: "memory");
        else                  asm volatile("cp.async.wait_group 0;" ::: "memory");
        __syncthreads();
        const uint32_t base = sb + (uint32_t)buf * STAGEB;
#pragma unroll
        for (int ks = 0; ks < 2; ks++) {
            const uint32_t ka = base + (uint32_t)ks * 32 + aoff;
            const uint32_t kb = base + 2*ATILE + (uint32_t)ks * 32 + boff;
            uint32_t ah[4][4], al[4][4];
#pragma unroll
            for (int mt = 0; mt < 4; mt++) {
                ldsm4(ah[mt], ka +         (uint32_t)mt * (16*LDSB));
                ldsm4(al[mt], ka + ATILE + (uint32_t)mt * (16*LDSB));
            }
#pragma unroll
            for (int p = 0; p < 4; p++) {
                uint32_t bh4[4], bl4[4];
                ldsm4(bh4, kb +         (uint32_t)p * (16*LDSB));
                ldsm4(bl4, kb + BTILE + (uint32_t)p * (16*LDSB));
#pragma unroll
                for (int mt = 0; mt < 4; mt++) {
                    mma16816(acc[mt][2*p],   ah[mt], bh4);
                    mma16816(acc[mt][2*p],   ah[mt], bl4);
                    mma16816(acc[mt][2*p],   al[mt], bh4);
                    mma16816(acc[mt][2*p+1], ah[mt], bh4 + 2);
                    mma16816(acc[mt][2*p+1], ah[mt], bl4 + 2);
                    mma16816(acc[mt][2*p+1], al[mt], bh4 + 2);
                }
            }
        }
        __syncthreads();
        if (kt + 3 < KT) issue(kt + 3, buf);
        buf = (buf == 2) ? 0 : buf + 1;
    }

    const int base_m = row0 + wm*64;
    const int base_n = col0 + wn*64;
#pragma unroll
    for (int mt = 0; mt < 4; mt++) {
#pragma unroll
        for (int nt = 0; nt < 8; nt++) {
            float* c = acc[mt][nt];
            if (ACT == 1) {
                c[0] = fmaxf(c[0], 0.f); c[1] = fmaxf(c[1], 0.f);
                c[2] = fmaxf(c[2], 0.f); c[3] = fmaxf(c[3], 0.f);
            }
            const int r0 = base_m + mt*16 + (lane >> 2);
            const int cc = base_n + nt*8 + (lane & 3)*2;
            if (OMODE == 0) {
                if (cc < N) {
                    *(float2*)(C + (size_t)r0 * N + cc)       = make_float2(c[0], c[1]);
                    *(float2*)(C + (size_t)(r0 + 8) * N + cc) = make_float2(c[2], c[3]);
                }
            } else if (OMODE == 1) {
                const int h = cc >> 6, kk = cc & (DK - 1);
                const int b0i = r0 >> 11, s0r = r0 & (SS - 1);
                split2(c[0], c[1], (__nv_bfloat162*)CH, (__nv_bfloat162*)CL,
                       (int)((((size_t)(b0i*HH + h)*SS + s0r)*DK + kk) >> 1));
                const int r1 = r0 + 8;
                const int b1i = r1 >> 11, s1r = r1 & (SS - 1);
                split2(c[2], c[3], (__nv_bfloat162*)CH, (__nv_bfloat162*)CL,
                       (int)((((size_t)(b1i*HH + h)*SS + s1r)*DK + kk) >> 1));
            } else {
                if (cc < N) {
                    split2(c[0], c[1], (__nv_bfloat162*)CH, (__nv_bfloat162*)CL,
                           (int)(((size_t)r0 * N + cc) >> 1));
                    split2(c[2], c[3], (__nv_bfloat162*)CH, (__nv_bfloat162*)CL,
                           (int)(((size_t)(r0 + 8) * N + cc) >> 1));
                }
            }
        }
    }
}

// ------------------------- tensor-core flash attention ----------------------
// Q,K,V as bf16 hi/lo in [B,H,S,DK]. Causal. CTA = 64 q-rows, 4 warps
// (16 q-rows each). 3-term split for QK^T and PV. Output bf16 hi/lo [B,S,D].
#define FSTR   144                 // smem row stride bytes (64 bf16 + pad)
#define FQH    0
#define FQL    (64*FSTR)           // 9216
#define FKV0   (2*64*FSTR)         // 18432
#define FKOFF  0
#define FKLOFF 9216
#define FVOFF  18432
#define FVLOFF 27648
#define FSTAGE 36864
#define FSMEM  (FKV0 + 2*FSTAGE)   // 92160

__global__ __launch_bounds__(128)
void flash_tc(const __nv_bfloat16* __restrict__ Qh, const __nv_bfloat16* __restrict__ Ql,
              const __nv_bfloat16* __restrict__ Kh, const __nv_bfloat16* __restrict__ Kl,
              const __nv_bfloat16* __restrict__ Vh, const __nv_bfloat16* __restrict__ Vl,
              __nv_bfloat16* __restrict__ OH, __nv_bfloat16* __restrict__ OL)
{
    extern __shared__ __align__(16) char smem[];
    const uint32_t sb = s2u(smem);
    const int bh  = blockIdx.y;
    const int qt  = gridDim.x - 1 - blockIdx.x;   // heavy blocks first
    const int tid = threadIdx.x, wid = tid >> 5, lane = tid & 31;
    const int q0  = qt * 64;

    // Q tile load (hi/lo)
    {
        const size_t g = ((size_t)bh * SS + q0) * DK;
#pragma unroll
        for (int c = tid; c < 512; c += 128) {
            const int row = c >> 3, ch = c & 7;
            const uint32_t so = (uint32_t)row * FSTR + (uint32_t)ch * 16;
            cpa16(sb + FQH + so, Qh + g + row * DK + ch * 8);
            cpa16(sb + FQL + so, Ql + g + row * DK + ch * 8);
        }
        asm volatile("cp.async.commit_group;" ::: "memory");
    }

    auto loadkv = [&](int kt, int bufi) {
        const uint32_t base = sb + FKV0 + (uint32_t)bufi * FSTAGE;
        const size_t g = ((size_t)bh * SS + kt * 64) * DK;
#pragma unroll
        for (int c = tid; c < 512; c += 128) {
            const int row = c >> 3, ch = c & 7;
            const uint32_t so = (uint32_t)row * FSTR + (uint32_t)ch * 16;
            const size_t go = g + row * DK + ch * 8;
            cpa16(base + FKOFF  + so, Kh + go);
            cpa16(base + FKLOFF + so, Kl + go);
            cpa16(base + FVOFF  + so, Vh + go);
            cpa16(base + FVLOFF + so, Vl + go);
        }
        asm volatile("cp.async.commit_group;" ::: "memory");
    };

    loadkv(0, 0);
    if (qt >= 1) loadkv(1, 1);

    if (qt >= 1) asm volatile("cp.async.wait_group 1;" ::: "memory");
    else         asm volatile("cp.async.wait_group 0;" ::: "memory");
    __syncthreads();

    // Q fragments
    uint32_t qfh[4][4], qfl[4][4];
    {
        const uint32_t a0 = sb + (uint32_t)(wid*16 + (lane & 15)) * FSTR + ((lane >> 4) << 4);
#pragma unroll
        for (int kc = 0; kc < 4; kc++) {
            ldsm4(qfh[kc], a0 + FQH + kc*32);
            ldsm4(qfl[kc], a0 + FQL + kc*32);
        }
    }

    float o[8][4];
#pragma unroll
    for (int i = 0; i < 8; i++)
#pragma unroll
        for (int j = 0; j < 4; j++) o[i][j] = 0.f;
    float mi0 = -1e30f, mi1 = -1e30f, li0 = 0.f, li1 = 0.f;

    const uint32_t kboff = (uint32_t)((lane & 7) + ((lane >> 4) << 3)) * FSTR
                         + (((lane >> 3) & 1) << 4);
    const uint32_t vboff = (uint32_t)((((lane >> 3) & 1) << 3) + (lane & 7)) * FSTR
                         + ((lane >> 4) << 4);

#pragma unroll 1
    for (int kt = 0; kt <= qt; kt++) {
        const int bufi = kt & 1;
        if (kt > 0) {
            if (kt < qt) asm volatile("cp.async.wait_group 1;" ::: "memory");
            else         asm volatile("cp.async.wait_group 0;" ::: "memory");
            __syncthreads();
        }
        const uint32_t base = sb + FKV0 + (uint32_t)bufi * FSTAGE;

        // S = Q K^T (3-term split)
        float s[8][4];
#pragma unroll
        for (int i = 0; i < 8; i++)
#pragma unroll
            for (int j = 0; j < 4; j++) s[i][j] = 0.f;
#pragma unroll
        for (int kc = 0; kc < 4; kc++) {
#pragma unroll
            for (int np = 0; np < 4; np++) {
                uint32_t bh4[4], bl4[4];
                ldsm4(bh4, base + FKOFF  + kboff + kc*32 + (uint32_t)np * (16*FSTR));
                ldsm4(bl4, base + FKLOFF + kboff + kc*32 + (uint32_t)np * (16*FSTR));
                mma16816(s[2*np],   qfh[kc], bh4);
                mma16816(s[2*np],   qfh[kc], bl4);
                mma16816(s[2*np],   qfl[kc], bh4);
                mma16816(s[2*np+1], qfh[kc], bh4 + 2);
                mma16816(s[2*np+1], qfh[kc], bl4 + 2);
                mma16816(s[2*np+1], qfl[kc], bh4 + 2);
            }
        }

        // scale + causal mask (diagonal tile only)
        if (kt == qt) {
            const int r = wid*16 + (lane >> 2);
            const int cb = (lane & 3) * 2;
#pragma unroll
            for (int nt = 0; nt < 8; nt++) {
                const int k0 = nt*8 + cb;
                s[nt][0] = (k0     <= r    ) ? s[nt][0]*0.125f : -1e30f;
                s[nt][1] = (k0 + 1 <= r    ) ? s[nt][1]*0.125f : -1e30f;
                s[nt][2] = (k0     <= r + 8) ? s[nt][2]*0.125f : -1e30f;
                s[nt][3] = (k0 + 1 <= r + 8) ? s[nt][3]*0.125f : -1e30f;
            }
        } else {
#pragma unroll
            for (int nt = 0; nt < 8; nt++) {
                s[nt][0] *= 0.125f; s[nt][1] *= 0.125f;
                s[nt][2] *= 0.125f; s[nt][3] *= 0.125f;
            }
        }

        // online softmax
        float m0 = -1e30f, m1 = -1e30f;
#pragma unroll
        for (int nt = 0; nt < 8; nt++) {
            m0 = fmaxf(m0, fmaxf(s[nt][0], s[nt][1]));
            m1 = fmaxf(m1, fmaxf(s[nt][2], s[nt][3]));
        }
        m0 = fmaxf(m0, __shfl_xor_sync(0xffffffffu, m0, 1));
        m0 = fmaxf(m0, __shfl_xor_sync(0xffffffffu, m0, 2));
        m1 = fmaxf(m1, __shfl_xor_sync(0xffffffffu, m1, 1));
        m1 = fmaxf(m1, __shfl_xor_sync(0xffffffffu, m1, 2));
        const float mn0 = fmaxf(mi0, m0), mn1 = fmaxf(mi1, m1);
        const float rs0 = __expf(mi0 - mn0), rs1 = __expf(mi1 - mn1);
        mi0 = mn0; mi1 = mn1;
        li0 *= rs0; li1 *= rs1;
#pragma unroll
        for (int nt = 0; nt < 8; nt++) {
            o[nt][0] *= rs0; o[nt][1] *= rs0;
            o[nt][2] *= rs1; o[nt][3] *= rs1;
        }
        float ls0 = 0.f, ls1 = 0.f;
#pragma unroll
        for (int nt = 0; nt < 8; nt++) {
            s[nt][0] = __expf(s[nt][0] - mn0);
            s[nt][1] = __expf(s[nt][1] - mn0);
            s[nt][2] = __expf(s[nt][2] - mn1);
            s[nt][3] = __expf(s[nt][3] - mn1);
            ls0 += s[nt][0] + s[nt][1];
            ls1 += s[nt][2] + s[nt][3];
        }
        li0 += ls0; li1 += ls1;

        // O += P V (3-term split); P A-frags built from S fragments
#pragma unroll
        for (int kc = 0; kc < 4; kc++) {
            uint32_t pa[4], plo[4];
            pa[0] = packsplit(s[2*kc][0],   s[2*kc][1],   plo[0]);
            pa[1] = packsplit(s[2*kc][2],   s[2*kc][3],   plo[1]);
            pa[2] = packsplit(s[2*kc+1][0], s[2*kc+1][1], plo[2]);
            pa[3] = packsplit(s[2*kc+1][2], s[2*kc+1][3], plo[3]);
#pragma unroll
            for (int np = 0; np < 4; np++) {
                uint32_t vh4[4], vl4[4];
                ldsm4t(vh4, base + FVOFF  + vboff + (uint32_t)kc * (16*FSTR) + np*32);
                ldsm4t(vl4, base + FVLOFF + vboff + (uint32_t)kc * (16*FSTR) + np*32);
                mma16816(o[2*np],   pa,  vh4);
                mma16816(o[2*np],   pa,  vl4);
                mma16816(o[2*np],   plo, vh4);
                mma16816(o[2*np+1], pa,  vh4 + 2);
                mma16816(o[2*np+1], pa,  vl4 + 2);
                mma16816(o[2*np+1], plo, vh4 + 2);
            }
        }

        __syncthreads();
        if (kt + 2 <= qt) loadkv(kt + 2, bufi);
    }

    // final row sums + write O as bf16 hi/lo split in [B,S,D]
    li0 += __shfl_xor_sync(0xffffffffu, li0, 1);
    li0 += __shfl_xor_sync(0xffffffffu, li0, 2);
    li1 += __shfl_xor_sync(0xffffffffu, li1, 1);
    li1 += __shfl_xor_sync(0xffffffffu, li1, 2);
    const float inv0 = 1.f / li0, inv1 = 1.f / li1;
    const int b = bh >> 4, h = bh & (HH - 1);
    const int qr = q0 + wid*16 + (lane >> 2);
    const size_t rowA = ((size_t)(b*SS + qr)) * DD + h * DK;
    const size_t rowB = rowA + 8 * DD;
    __nv_bfloat162* OH2 = (__nv_bfloat162*)OH;
    __nv_bfloat162* OL2 = (__nv_bfloat162*)OL;
#pragma unroll
    for (int nt = 0; nt < 8; nt++) {
        const int dk = nt*8 + (lane & 3)*2;
        split2(o[nt][0]*inv0, o[nt][1]*inv0, OH2, OL2, (int)((rowA + dk) >> 1));
        split2(o[nt][2]*inv1, o[nt][3]*inv1, OH2, OL2, (int)((rowB + dk) >> 1));
    }
}

// ------------------------- residual add + layernorm + split -----------------
__global__ __launch_bounds__(128)
void add_ln_kernel(float* __restrict__ x, const float* __restrict__ r,
                   const float* __restrict__ w, const float* __restrict__ bias,
                   __nv_bfloat16* __restrict__ xh, __nv_bfloat16* __restrict__ xl) {
    __shared__ float sh[4];
    const int row = blockIdx.x;
    const int tid = threadIdx.x;
    float4* xr = (float4*)(x + (size_t)row * DD);
    const float4* rr = (const float4*)(r + (size_t)row * DD);
    float4 v0 = xr[tid], v1 = xr[tid + 128];
    float4 a0 = rr[tid], a1 = rr[tid + 128];
    v0.x += a0.x; v0.y += a0.y; v0.z += a0.z; v0.w += a0.w;
    v1.x += a1.x; v1.y += a1.y; v1.z += a1.z; v1.w += a1.w;

    float s = v0.x+v0.y+v0.z+v0.w + v1.x+v1.y+v1.z+v1.w;
#pragma unroll
    for (int o = 16; o > 0; o >>= 1) s += __shfl_down_sync(0xffffffffu, s, o);
    if ((tid & 31) == 0) sh[tid >> 5] = s;
    __syncthreads();
    float mean = (sh[0]+sh[1]+sh[2]+sh[3]) * (1.f/DD);
    __syncthreads();

    float dx0 = v0.x-mean, dx1 = v0.y-mean, dx2 = v0.z-mean, dx3 = v0.w-mean;
    float dy0 = v1.x-mean, dy1 = v1.y-mean, dy2 = v1.z-mean, dy3 = v1.w-mean;
    float sq = dx0*dx0+dx1*dx1+dx2*dx2+dx3*dx3 + dy0*dy0+dy1*dy1+dy2*dy2+dy3*dy3;
#pragma unroll
    for (int o = 16; o > 0; o >>= 1) sq += __shfl_down_sync(0xffffffffu, sq, o);
    if ((tid & 31) == 0) sh[tid >> 5] = sq;
    __syncthreads();
    float var = (sh[0]+sh[1]+sh[2]+sh[3]) * (1.f/DD);
    float rs = rsqrtf(var + 1e-5f);

    float4 w0 = ((const float4*)w)[tid],     w1 = ((const float4*)w)[tid + 128];
    float4 b0 = ((const float4*)bias)[tid],  b1 = ((const float4*)bias)[tid + 128];
    float4 o0 = make_float4(dx0*rs*w0.x+b0.x, dx1*rs*w0.y+b0.y,
                            dx2*rs*w0.z+b0.z, dx3*rs*w0.w+b0.w);
    float4 o1 = make_float4(dy0*rs*w1.x+b1.x, dy1*rs*w1.y+b1.y,
                            dy2*rs*w1.z+b1.z, dy3*rs*w1.w+b1.w);
    xr[tid]       = o0;
    xr[tid + 128] = o1;

    __nv_bfloat162* H = (__nv_bfloat162*)(xh + (size_t)row * DD);
    __nv_bfloat162* L = (__nv_bfloat162*)(xl + (size_t)row * DD);
    split2(o0.x, o0.y, H, L, tid*2);
    split2(o0.z, o0.w, H, L, tid*2 + 1);
    split2(o1.x, o1.y, H, L, (tid+128)*2);
    split2(o1.z, o1.w, H, L, (tid+128)*2 + 1);
}

// ------------------------- launch ------------------------------------------
extern "C" void kernel_launch(void* const* d_in, const int* in_sizes, int n_in,
                              void* d_out, int out_size) {
    (void)in_sizes; (void)n_in; (void)out_size;
    const int*   idx  = (const int*)  d_in[0];
    const float* emb  = (const float*)d_in[1];
    const float* Wq   = (const float*)d_in[2];
    const float* Wk   = (const float*)d_in[3];
    const float* Wv   = (const float*)d_in[4];
    const float* Wo   = (const float*)d_in[5];
    const float* ln1w = (const float*)d_in[6];
    const float* ln1b = (const float*)d_in[7];
    const float* W1   = (const float*)d_in[8];
    const float* W2   = (const float*)d_in[9];
    const float* ln2w = (const float*)d_in[10];
    const float* ln2b = (const float*)d_in[11];
    const float* Wout = (const float*)d_in[12];

    float *x, *t;
    __nv_bfloat16 *wh, *wl, *xh, *xl, *oh, *ol, *fh, *fl;
    __nv_bfloat16 *qh, *ql, *kh, *kl, *vh, *vl;
    cudaGetSymbolAddress((void**)&x, g_x);
    cudaGetSymbolAddress((void**)&t, g_t);
    cudaGetSymbolAddress((void**)&wh, g_wh);
    cudaGetSymbolAddress((void**)&wl, g_wl);
    cudaGetSymbolAddress((void**)&xh, g_xh);
    cudaGetSymbolAddress((void**)&xl, g_xl);
    cudaGetSymbolAddress((void**)&oh, g_oh);
    cudaGetSymbolAddress((void**)&ol, g_ol);
    cudaGetSymbolAddress((void**)&fh, g_fh);
    cudaGetSymbolAddress((void**)&fl, g_fl);
    cudaGetSymbolAddress((void**)&qh, g_qh);
    cudaGetSymbolAddress((void**)&ql, g_ql);
    cudaGetSymbolAddress((void**)&kh, g_kh);
    cudaGetSymbolAddress((void**)&kl, g_kl);
    cudaGetSymbolAddress((void**)&vh, g_vh);
    cudaGetSymbolAddress((void**)&vl, g_vl);

    cudaFuncSetAttribute(gemm_tc<0,0>, cudaFuncAttributeMaxDynamicSharedMemorySize, GSMEM);
    cudaFuncSetAttribute(gemm_tc<0,1>, cudaFuncAttributeMaxDynamicSharedMemorySize, GSMEM);
    cudaFuncSetAttribute(gemm_tc<1,2>, cudaFuncAttributeMaxDynamicSharedMemorySize, GSMEM);
    cudaFuncSetAttribute(flash_tc, cudaFuncAttributeMaxDynamicSharedMemorySize, FSMEM);

    // weight splits (once per launch)
    {
        int n4;
        n4 = (LL*DD*DD)/4;
        split_kernel<<<(n4+255)/256, 256>>>(Wq, wh+WQO, wl+WQO, n4);
        split_kernel<<<(n4+255)/256, 256>>>(Wk, wh+WKO, wl+WKO, n4);
        split_kernel<<<(n4+255)/256, 256>>>(Wv, wh+WVO, wl+WVO, n4);
        split_kernel<<<(n4+255)/256, 256>>>(Wo, wh+WOO, wl+WOO, n4);
        n4 = (LL*DFF*DD)/4;
        split_kernel<<<(n4+255)/256, 256>>>(W1, wh+W1O, wl+W1O, n4);
        split_kernel<<<(n4+255)/256, 256>>>(W2, wh+W2O, wl+W2O, n4);
        n4 = (VV*DD)/4;
        split_kernel<<<(n4+255)/256, 256>>>(Wout, wh+WUO, wl+WUO, n4);
    }

    embed_kernel<<<(BB*SS*(DD/2) + 255) / 256, 256>>>(idx, emb, x);
    split_kernel<<<(MM*DD/4 + 255)/256, 256>>>(x, xh, xl, MM*DD/4);

    for (int l = 0; l < LL; l++) {
        const size_t ws = (size_t)l * DD * DD;
        gemm_tc<0,1><<<dim3(4, 32), 256, GSMEM>>>(xh, xl, wh+WQO+ws, wl+WQO+ws,
                                                  nullptr, qh, ql, MM, DD, DD);
        gemm_tc<0,1><<<dim3(4, 32), 256, GSMEM>>>(xh, xl, wh+WKO+ws, wl+WKO+ws,
                                                  nullptr, kh, kl, MM, DD, DD);
        gemm_tc<0,1><<<dim3(4, 32), 256, GSMEM>>>(xh, xl, wh+WVO+ws, wl+WVO+ws,
                                                  nullptr, vh, vl, MM, DD, DD);
        flash_tc<<<dim3(SS/64, BB*HH), 128, FSMEM>>>(qh, ql, kh, kl, vh, vl, oh, ol);
        gemm_tc<0,0><<<dim3(4, 32), 256, GSMEM>>>(oh, ol, wh+WOO+ws, wl+WOO+ws,
                                                  t, nullptr, nullptr, MM, DD, DD);
        add_ln_kernel<<<MM, 128>>>(x, t, ln1w + l*DD, ln1b + l*DD, xh, xl);
        const size_t wf = (size_t)l * DFF * DD;
        gemm_tc<1,2><<<dim3(16, 32), 256, GSMEM>>>(xh, xl, wh+W1O+wf, wl+W1O+wf,
                                                   nullptr, fh, fl, MM, DFF, DD);
        gemm_tc<0,0><<<dim3(4, 32), 256, GSMEM>>>(fh, fl, wh+W2O+wf, wl+W2O+wf,
                                                  t, nullptr, nullptr, MM, DD, DFF);
        add_ln_kernel<<<MM, 128>>>(x, t, ln2w + l*DD, ln2b + l*DD, xh, xl);
    }
    gemm_tc<0,0><<<dim3(8, 32), 256, GSMEM>>>(xh, xl, wh+WUO, wl+WUO,
                                              (float*)d_out, nullptr, nullptr, MM, VV, DD);
}

// round 10
// speedup vs baseline: 4.1942x; 1.3680x over previous
#include <cuda_runtime.h>
#include <cuda_fp16.h>
#include <math.h>
#include <stdint.h>

// Problem constants
#define BB   2
#define SS   2048
#define DD   1024
#define HH   16
#define LL   4
#define VV   2000
#define DK   64
#define DFF  4096
#define MM   (BB*SS)          // 4096 rows

// ------------------------- scratch (static device memory) -------------------
__device__ float g_x[MM*DD];      // activations [B*S, D] fp32 (residual path)
__device__ float g_t[MM*DD];      // temp (pre-LN residual branch)

// fp16 weight split (value = hi + lo)
#define WQKV 0u                    // [L][Wq;Wk;Wv] each 1024x1024
#define WOO  12582912u
#define W1O  16777216u
#define W2O  33554432u
#define WUO  50331648u
#define WTOT 52379648u
__device__ __half g_wh[WTOT];
__device__ __half g_wl[WTOT];
// single-fp16 activations
__device__ __half g_xa[MM*DD];     // LN output
__device__ __half g_oa[MM*DD];     // attention out [B,S,D]
__device__ __half g_fa[MM*DFF];    // FFN hidden (post-relu)
__device__ __half g_qa[MM*DD];     // [B,H,S,DK]
__device__ __half g_kh[MM*DD], g_kl[MM*DD];
__device__ __half g_va[MM*DD];

// ------------------------- PTX helpers --------------------------------------
__device__ __forceinline__ uint32_t s2u(const void* p) {
    uint32_t a;
    asm("{ .reg .u64 t; cvta.to.shared.u64 t, %1; cvt.u32.u64 %0, t; }"
        : "=r"(a) : "l"(p));
    return a;
}
__device__ __forceinline__ void cpa16(uint32_t s, const void* g) {
    asm volatile("cp.async.cg.shared.global [%0], [%1], 16;" :: "r"(s), "l"(g));
}
__device__ __forceinline__ void ldsm4(uint32_t* r, uint32_t a) {
    asm volatile("ldmatrix.sync.aligned.m8n8.x4.shared.b16 {%0,%1,%2,%3}, [%4];"
                 : "=r"(r[0]), "=r"(r[1]), "=r"(r[2]), "=r"(r[3]) : "r"(a));
}
__device__ __forceinline__ void ldsm4t(uint32_t* r, uint32_t a) {
    asm volatile("ldmatrix.sync.aligned.m8n8.x4.trans.shared.b16 {%0,%1,%2,%3}, [%4];"
                 : "=r"(r[0]), "=r"(r[1]), "=r"(r[2]), "=r"(r[3]) : "r"(a));
}
__device__ __forceinline__ void mma16816(float* c, const uint32_t* a, const uint32_t* b) {
    asm volatile(
        "mma.sync.aligned.m16n8k16.row.col.f32.f16.f16.f32 "
        "{%0,%1,%2,%3}, {%4,%5,%6,%7}, {%8,%9}, {%0,%1,%2,%3};"
        : "+f"(c[0]), "+f"(c[1]), "+f"(c[2]), "+f"(c[3])
        : "r"(a[0]), "r"(a[1]), "r"(a[2]), "r"(a[3]), "r"(b[0]), "r"(b[1]));
}

// ------------------------- split helpers -------------------------------------
__device__ __forceinline__ void hsplit2(float a, float b, __half2* H, __half2* L,
                                        size_t i) {
    __half ha = __float2half_rn(a), hb = __float2half_rn(b);
    H[i] = __halves2half2(ha, hb);
    L[i] = __halves2half2(__float2half_rn(a - __half2float(ha)),
                          __float2half_rn(b - __half2float(hb)));
}
__device__ __forceinline__ uint32_t packsplit(float a, float b, uint32_t& lo) {
    __half ha = __float2half_rn(a), hb = __float2half_rn(b);
    __half2 h2 = __halves2half2(ha, hb);
    __half2 l2 = __halves2half2(__float2half_rn(a - __half2float(ha)),
                                __float2half_rn(b - __half2float(hb)));
    lo = *(uint32_t*)&l2;
    return *(uint32_t*)&h2;
}

__global__ void wsplit_kernel(const float* __restrict__ s,
                              __half* __restrict__ h,
                              __half* __restrict__ l, int n4) {
    int i = blockIdx.x * blockDim.x + threadIdx.x;
    if (i >= n4) return;
    float4 v = ((const float4*)s)[i];
    hsplit2(v.x, v.y, (__half2*)h, (__half2*)l, (size_t)i * 2);
    hsplit2(v.z, v.w, (__half2*)h, (__half2*)l, (size_t)i * 2 + 1);
}

// ------------------------- embedding + positional encoding ------------------
__global__ void embed_kernel(const int* __restrict__ idx,
                             const float* __restrict__ emb,
                             float* __restrict__ x, __half* __restrict__ xa) {
    int t = blockIdx.x * blockDim.x + threadIdx.x;
    if (t >= BB*SS*(DD/2)) return;
    int dp = t & 511;
    int bs = t >> 9;
    int s  = bs & (SS - 1);
    int d  = dp << 1;
    double freq = exp((double)d * (-9.210340371976184 / 1024.0));
    double ang  = (double)s * freq;
    double sv, cv;
    sincos(ang, &sv, &cv);
    int tok = idx[bs];
    float2 e = ((const float2*)emb)[(size_t)tok * 512 + dp];
    float vx = e.x + (float)sv, vy = e.y + (float)cv;
    ((float2*)x)[t] = make_float2(vx, vy);
    ((__half2*)xa)[t] = __floats2half2_rn(vx, vy);
}

// ------------------------- mma.sync fp16 2-term GEMM -------------------------
// C[M,N] = A[M,K] * B[N,K]^T, A single fp16, B = Bh+Bl (fp16), fp32 accum.
// 2 terms: A*Bh + A*Bl.  CTA tile 128x256, K-tile 32, 256 thr, 8 warps 64x64.
// OMODE: 0 = fp32 row-major out
//        1 = fused QKV (N=3072): q/v single fp16, k hi/lo, remap [B,H,S,DK]
//        2 = fp16 single row-major out (with optional relu)
#define LDSB   80            // smem row stride in bytes (40 fp16)
#define ATILE  (128*LDSB)    // 10240
#define BTILE  (256*LDSB)    // 20480
#define STAGEB (ATILE + 2*BTILE)     // 51200
#define NSTAGE 3
#define GSMEM  (NSTAGE*STAGEB)       // 153600

template<int ACT, int OMODE>
__global__ __launch_bounds__(256)
void gemm_tc(const __half* __restrict__ Aq,
             const __half* __restrict__ Bh, const __half* __restrict__ Bl,
             float* __restrict__ C,
             __half* __restrict__ P0, __half* __restrict__ P1,
             __half* __restrict__ P2, __half* __restrict__ P3,
             int M, int N, int K)
{
    extern __shared__ __align__(16) char smem[];
    const uint32_t sb = s2u(smem);
    const int tid = threadIdx.x;
    const int wid = tid >> 5, lane = tid & 31;
    const int wm = wid & 1, wn = wid >> 1;
    const int row0 = blockIdx.y * 128, col0 = blockIdx.x * 256;

    const int chunk = tid & 3;
    const int rr    = tid >> 2;
    const int rA0 = row0 + rr, rA1 = rA0 + 64;
    int rB0 = col0 + rr;       if (rB0 > N - 1) rB0 = N - 1;
    int rB1 = col0 + rr + 64;  if (rB1 > N - 1) rB1 = N - 1;
    int rB2 = col0 + rr + 128; if (rB2 > N - 1) rB2 = N - 1;
    int rB3 = col0 + rr + 192; if (rB3 > N - 1) rB3 = N - 1;
    const uint32_t sA0 = (uint32_t)rr * LDSB + (uint32_t)chunk * 16;

    auto issue = [&](int kt, int buf) {
        const int ko = kt * 32 + chunk * 8;
        const uint32_t base = sb + (uint32_t)buf * STAGEB;
        cpa16(base + sA0,            Aq + (size_t)rA0 * K + ko);
        cpa16(base + sA0 + 64u*LDSB, Aq + (size_t)rA1 * K + ko);
        const uint32_t bb = base + ATILE;
        cpa16(bb +         sA0,              Bh + (size_t)rB0 * K + ko);
        cpa16(bb +         sA0 +  64u*LDSB,  Bh + (size_t)rB1 * K + ko);
        cpa16(bb +         sA0 + 128u*LDSB,  Bh + (size_t)rB2 * K + ko);
        cpa16(bb +         sA0 + 192u*LDSB,  Bh + (size_t)rB3 * K + ko);
        cpa16(bb + BTILE + sA0,              Bl + (size_t)rB0 * K + ko);
        cpa16(bb + BTILE + sA0 +  64u*LDSB,  Bl + (size_t)rB1 * K + ko);
        cpa16(bb + BTILE + sA0 + 128u*LDSB,  Bl + (size_t)rB2 * K + ko);
        cpa16(bb + BTILE + sA0 + 192u*LDSB,  Bl + (size_t)rB3 * K + ko);
        asm volatile("cp.async.commit_group;" ::: "memory");
    };

    float acc[4][8][4];
#pragma unroll
    for (int i = 0; i < 4; i++)
#pragma unroll
        for (int j = 0; j < 8; j++)
#pragma unroll
            for (int q = 0; q < 4; q++) acc[i][j][q] = 0.f;

    const int KT = K >> 5;
    issue(0, 0);
    issue(1, 1);
    issue(2, 2);

    const uint32_t aoff = (uint32_t)(wm*64 + (lane & 15)) * LDSB + ((lane >> 4) << 4);
    const uint32_t boff = (uint32_t)(wn*64 + (lane & 7) + ((lane >> 4) << 3)) * LDSB
                        + (((lane >> 3) & 1) << 4);

    int buf = 0;
#pragma unroll 1
    for (int kt = 0; kt < KT; kt++) {
        if (kt + 2 < KT)      asm volatile("cp.async.wait_group 2;" ::: "memory");
        else if (kt + 1 < KT) asm volatile("cp.async.wait_group 1;" ::: "memory");
        else                  asm volatile("cp.async.wait_group 0;" ::: "memory");
        __syncthreads();
        const uint32_t base = sb + (uint32_t)buf * STAGEB;
#pragma unroll
        for (int ks = 0; ks < 2; ks++) {
            const uint32_t ka = base + (uint32_t)ks * 32 + aoff;
            const uint32_t kb = base + ATILE + (uint32_t)ks * 32 + boff;
            uint32_t ah[4][4];
#pragma unroll
            for (int mt = 0; mt < 4; mt++)
                ldsm4(ah[mt], ka + (uint32_t)mt * (16*LDSB));
#pragma unroll
            for (int p = 0; p < 4; p++) {
                uint32_t bh4[4], bl4[4];
                ldsm4(bh4, kb +         (uint32_t)p * (16*LDSB));
                ldsm4(bl4, kb + BTILE + (uint32_t)p * (16*LDSB));
#pragma unroll
                for (int mt = 0; mt < 4; mt++) {
                    mma16816(acc[mt][2*p],   ah[mt], bh4);
                    mma16816(acc[mt][2*p],   ah[mt], bl4);
                    mma16816(acc[mt][2*p+1], ah[mt], bh4 + 2);
                    mma16816(acc[mt][2*p+1], ah[mt], bl4 + 2);
                }
            }
        }
        __syncthreads();
        if (kt + 3 < KT) issue(kt + 3, buf);
        buf = (buf == 2) ? 0 : buf + 1;
    }

    const int base_m = row0 + wm*64;
    const int base_n = col0 + wn*64;
#pragma unroll
    for (int mt = 0; mt < 4; mt++) {
#pragma unroll
        for (int nt = 0; nt < 8; nt++) {
            float* c = acc[mt][nt];
            if (ACT == 1) {
                c[0] = fmaxf(c[0], 0.f); c[1] = fmaxf(c[1], 0.f);
                c[2] = fmaxf(c[2], 0.f); c[3] = fmaxf(c[3], 0.f);
            }
            const int r0 = base_m + mt*16 + (lane >> 2);
            const int cc = base_n + nt*8 + (lane & 3)*2;
            if (OMODE == 0) {
                if (cc < N) {
                    *(float2*)(C + (size_t)r0 * N + cc)       = make_float2(c[0], c[1]);
                    *(float2*)(C + (size_t)(r0 + 8) * N + cc) = make_float2(c[2], c[3]);
                }
            } else if (OMODE == 1) {
                // fused QKV: n in [0,3072)
                const int sect = cc >> 10;
                const int nc = cc & 1023;
                const int h = nc >> 6, kk = nc & (DK - 1);
                const int b0i = r0 >> 11, s0r = r0 & (SS - 1);
                const size_t i0 = (((size_t)(b0i*HH + h)*SS + s0r)*DK + kk) >> 1;
                const int r1 = r0 + 8;
                const int b1i = r1 >> 11, s1r = r1 & (SS - 1);
                const size_t i1 = (((size_t)(b1i*HH + h)*SS + s1r)*DK + kk) >> 1;
                if (sect == 0) {
                    ((__half2*)P0)[i0] = __floats2half2_rn(c[0], c[1]);
                    ((__half2*)P0)[i1] = __floats2half2_rn(c[2], c[3]);
                } else if (sect == 1) {
                    hsplit2(c[0], c[1], (__half2*)P1, (__half2*)P2, i0);
                    hsplit2(c[2], c[3], (__half2*)P1, (__half2*)P2, i1);
                } else {
                    ((__half2*)P3)[i0] = __floats2half2_rn(c[0], c[1]);
                    ((__half2*)P3)[i1] = __floats2half2_rn(c[2], c[3]);
                }
            } else {
                if (cc < N) {
                    ((__half2*)P0)[((size_t)r0 * N + cc) >> 1]
                        = __floats2half2_rn(c[0], c[1]);
                    ((__half2*)P0)[((size_t)(r0 + 8) * N + cc) >> 1]
                        = __floats2half2_rn(c[2], c[3]);
                }
            }
        }
    }
}

// ------------------------- tensor-core flash attention ----------------------
// Q single fp16, K hi/lo fp16, V single fp16 in [B,H,S,DK]. Causal.
// CTA = 64 q-rows, 4 warps. 2-term QK^T (Q*(Kh+Kl)); 2-term PV ((Ph+Pl)*V).
// Output single fp16 [B,S,D].
#define FSTR   144                 // smem row stride bytes (64 fp16 + pad)
#define FKV0   9216                // after Q tile
#define FKOFF  0
#define FKLOFF 9216
#define FVOFF  18432
#define FSTAGE 27648
#define FSMEM  (FKV0 + 2*FSTAGE)   // 64512

__global__ __launch_bounds__(128)
void flash_tc(const __half* __restrict__ Qa,
              const __half* __restrict__ Kh, const __half* __restrict__ Kl,
              const __half* __restrict__ Va, __half* __restrict__ OA)
{
    extern __shared__ __align__(16) char smem[];
    const uint32_t sb = s2u(smem);
    const int bh  = blockIdx.y;
    const int qt  = gridDim.x - 1 - blockIdx.x;   // heavy blocks first
    const int tid = threadIdx.x, wid = tid >> 5, lane = tid & 31;
    const int q0  = qt * 64;

    // Q tile load
    {
        const size_t g = ((size_t)bh * SS + q0) * DK;
#pragma unroll
        for (int c = tid; c < 512; c += 128) {
            const int row = c >> 3, ch = c & 7;
            cpa16(sb + (uint32_t)row * FSTR + (uint32_t)ch * 16,
                  Qa + g + row * DK + ch * 8);
        }
        asm volatile("cp.async.commit_group;" ::: "memory");
    }

    auto loadkv = [&](int kt, int bufi) {
        const uint32_t base = sb + FKV0 + (uint32_t)bufi * FSTAGE;
        const size_t g = ((size_t)bh * SS + kt * 64) * DK;
#pragma unroll
        for (int c = tid; c < 512; c += 128) {
            const int row = c >> 3, ch = c & 7;
            const uint32_t so = (uint32_t)row * FSTR + (uint32_t)ch * 16;
            const size_t go = g + row * DK + ch * 8;
            cpa16(base + FKOFF  + so, Kh + go);
            cpa16(base + FKLOFF + so, Kl + go);
            cpa16(base + FVOFF  + so, Va + go);
        }
        asm volatile("cp.async.commit_group;" ::: "memory");
    };

    loadkv(0, 0);
    if (qt >= 1) loadkv(1, 1);

    if (qt >= 1) asm volatile("cp.async.wait_group 1;" ::: "memory");
    else         asm volatile("cp.async.wait_group 0;" ::: "memory");
    __syncthreads();

    // Q fragments
    uint32_t qf[4][4];
    {
        const uint32_t a0 = sb + (uint32_t)(wid*16 + (lane & 15)) * FSTR + ((lane >> 4) << 4);
#pragma unroll
        for (int kc = 0; kc < 4; kc++)
            ldsm4(qf[kc], a0 + kc*32);
    }

    float o[8][4];
#pragma unroll
    for (int i = 0; i < 8; i++)
#pragma unroll
        for (int j = 0; j < 4; j++) o[i][j] = 0.f;
    float mi0 = -1e30f, mi1 = -1e30f, li0 = 0.f, li1 = 0.f;

    const uint32_t kboff = (uint32_t)((lane & 7) + ((lane >> 4) << 3)) * FSTR
                         + (((lane >> 3) & 1) << 4);
    const uint32_t vboff = (uint32_t)((((lane >> 3) & 1) << 3) + (lane & 7)) * FSTR
                         + ((lane >> 4) << 4);

#pragma unroll 1
    for (int kt = 0; kt <= qt; kt++) {
        const int bufi = kt & 1;
        if (kt > 0) {
            if (kt < qt) asm volatile("cp.async.wait_group 1;" ::: "memory");
            else         asm volatile("cp.async.wait_group 0;" ::: "memory");
            __syncthreads();
        }
        const uint32_t base = sb + FKV0 + (uint32_t)bufi * FSTAGE;

        // S = Q K^T (2-term: Q*(Kh+Kl))
        float s[8][4];
#pragma unroll
        for (int i = 0; i < 8; i++)
#pragma unroll
            for (int j = 0; j < 4; j++) s[i][j] = 0.f;
#pragma unroll
        for (int kc = 0; kc < 4; kc++) {
#pragma unroll
            for (int np = 0; np < 4; np++) {
                uint32_t kh4[4], kl4[4];
                ldsm4(kh4, base + FKOFF  + kboff + kc*32 + (uint32_t)np * (16*FSTR));
                ldsm4(kl4, base + FKLOFF + kboff + kc*32 + (uint32_t)np * (16*FSTR));
                mma16816(s[2*np],   qf[kc], kh4);
                mma16816(s[2*np],   qf[kc], kl4);
                mma16816(s[2*np+1], qf[kc], kh4 + 2);
                mma16816(s[2*np+1], qf[kc], kl4 + 2);
            }
        }

        // scale + causal mask (diagonal tile only)
        if (kt == qt) {
            const int r = wid*16 + (lane >> 2);
            const int cb = (lane & 3) * 2;
#pragma unroll
            for (int nt = 0; nt < 8; nt++) {
                const int k0 = nt*8 + cb;
                s[nt][0] = (k0     <= r    ) ? s[nt][0]*0.125f : -1e30f;
                s[nt][1] = (k0 + 1 <= r    ) ? s[nt][1]*0.125f : -1e30f;
                s[nt][2] = (k0     <= r + 8) ? s[nt][2]*0.125f : -1e30f;
                s[nt][3] = (k0 + 1 <= r + 8) ? s[nt][3]*0.125f : -1e30f;
            }
        } else {
#pragma unroll
            for (int nt = 0; nt < 8; nt++) {
                s[nt][0] *= 0.125f; s[nt][1] *= 0.125f;
                s[nt][2] *= 0.125f; s[nt][3] *= 0.125f;
            }
        }

        // online softmax
        float m0 = -1e30f, m1 = -1e30f;
#pragma unroll
        for (int nt = 0; nt < 8; nt++) {
            m0 = fmaxf(m0, fmaxf(s[nt][0], s[nt][1]));
            m1 = fmaxf(m1, fmaxf(s[nt][2], s[nt][3]));
        }
        m0 = fmaxf(m0, __shfl_xor_sync(0xffffffffu, m0, 1));
        m0 = fmaxf(m0, __shfl_xor_sync(0xffffffffu, m0, 2));
        m1 = fmaxf(m1, __shfl_xor_sync(0xffffffffu, m1, 1));
        m1 = fmaxf(m1, __shfl_xor_sync(0xffffffffu, m1, 2));
        const float mn0 = fmaxf(mi0, m0), mn1 = fmaxf(mi1, m1);
        const float rs0 = __expf(mi0 - mn0), rs1 = __expf(mi1 - mn1);
        mi0 = mn0; mi1 = mn1;
        li0 *= rs0; li1 *= rs1;
#pragma unroll
        for (int nt = 0; nt < 8; nt++) {
            o[nt][0] *= rs0; o[nt][1] *= rs0;
            o[nt][2] *= rs1; o[nt][3] *= rs1;
        }
        float ls0 = 0.f, ls1 = 0.f;
#pragma unroll
        for (int nt = 0; nt < 8; nt++) {
            s[nt][0] = __expf(s[nt][0] - mn0);
            s[nt][1] = __expf(s[nt][1] - mn0);
            s[nt][2] = __expf(s[nt][2] - mn1);
            s[nt][3] = __expf(s[nt][3] - mn1);
            ls0 += s[nt][0] + s[nt][1];
            ls1 += s[nt][2] + s[nt][3];
        }
        li0 += ls0; li1 += ls1;

        // O += P V (2-term: (Ph+Pl)*V)
#pragma unroll
        for (int kc = 0; kc < 4; kc++) {
            uint32_t pa[4], plo[4];
            pa[0] = packsplit(s[2*kc][0],   s[2*kc][1],   plo[0]);
            pa[1] = packsplit(s[2*kc][2],   s[2*kc][3],   plo[1]);
            pa[2] = packsplit(s[2*kc+1][0], s[2*kc+1][1], plo[2]);
            pa[3] = packsplit(s[2*kc+1][2], s[2*kc+1][3], plo[3]);
#pragma unroll
            for (int np = 0; np < 4; np++) {
                uint32_t vh4[4];
                ldsm4t(vh4, base + FVOFF + vboff + (uint32_t)kc * (16*FSTR) + np*32);
                mma16816(o[2*np],   pa,  vh4);
                mma16816(o[2*np],   plo, vh4);
                mma16816(o[2*np+1], pa,  vh4 + 2);
                mma16816(o[2*np+1], plo, vh4 + 2);
            }
        }

        __syncthreads();
        if (kt + 2 <= qt) loadkv(kt + 2, bufi);
    }

    // final row sums + write O single fp16 [B,S,D]
    li0 += __shfl_xor_sync(0xffffffffu, li0, 1);
    li0 += __shfl_xor_sync(0xffffffffu, li0, 2);
    li1 += __shfl_xor_sync(0xffffffffu, li1, 1);
    li1 += __shfl_xor_sync(0xffffffffu, li1, 2);
    const float inv0 = 1.f / li0, inv1 = 1.f / li1;
    const int b = bh >> 4, h = bh & (HH - 1);
    const int qr = q0 + wid*16 + (lane >> 2);
    const size_t rowA = ((size_t)(b*SS + qr)) * DD + h * DK;
    const size_t rowB = rowA + 8 * DD;
    __half2* OA2 = (__half2*)OA;
#pragma unroll
    for (int nt = 0; nt < 8; nt++) {
        const int dk = nt*8 + (lane & 3)*2;
        OA2[(rowA + dk) >> 1] = __floats2half2_rn(o[nt][0]*inv0, o[nt][1]*inv0);
        OA2[(rowB + dk) >> 1] = __floats2half2_rn(o[nt][2]*inv1, o[nt][3]*inv1);
    }
}

// ------------------------- residual add + layernorm + fp16 out --------------
__global__ __launch_bounds__(128)
void add_ln_kernel(float* __restrict__ x, const float* __restrict__ r,
                   const float* __restrict__ w, const float* __restrict__ bias,
                   __half* __restrict__ xa) {
    __shared__ float sh[4];
    const int row = blockIdx.x;
    const int tid = threadIdx.x;
    float4* xr = (float4*)(x + (size_t)row * DD);
    const float4* rr = (const float4*)(r + (size_t)row * DD);
    float4 v0 = xr[tid], v1 = xr[tid + 128];
    float4 a0 = rr[tid], a1 = rr[tid + 128];
    v0.x += a0.x; v0.y += a0.y; v0.z += a0.z; v0.w += a0.w;
    v1.x += a1.x; v1.y += a1.y; v1.z += a1.z; v1.w += a1.w;

    float s = v0.x+v0.y+v0.z+v0.w + v1.x+v1.y+v1.z+v1.w;
#pragma unroll
    for (int o = 16; o > 0; o >>= 1) s += __shfl_down_sync(0xffffffffu, s, o);
    if ((tid & 31) == 0) sh[tid >> 5] = s;
    __syncthreads();
    float mean = (sh[0]+sh[1]+sh[2]+sh[3]) * (1.f/DD);
    __syncthreads();

    float dx0 = v0.x-mean, dx1 = v0.y-mean, dx2 = v0.z-mean, dx3 = v0.w-mean;
    float dy0 = v1.x-mean, dy1 = v1.y-mean, dy2 = v1.z-mean, dy3 = v1.w-mean;
    float sq = dx0*dx0+dx1*dx1+dx2*dx2+dx3*dx3 + dy0*dy0+dy1*dy1+dy2*dy2+dy3*dy3;
#pragma unroll
    for (int o = 16; o > 0; o >>= 1) sq += __shfl_down_sync(0xffffffffu, sq, o);
    if ((tid & 31) == 0) sh[tid >> 5] = sq;
    __syncthreads();
    float var = (sh[0]+sh[1]+sh[2]+sh[3]) * (1.f/DD);
    float rs = rsqrtf(var + 1e-5f);

    float4 w0 = ((const float4*)w)[tid],     w1 = ((const float4*)w)[tid + 128];
    float4 b0 = ((const float4*)bias)[tid],  b1 = ((const float4*)bias)[tid + 128];
    float4 o0 = make_float4(dx0*rs*w0.x+b0.x, dx1*rs*w0.y+b0.y,
                            dx2*rs*w0.z+b0.z, dx3*rs*w0.w+b0.w);
    float4 o1 = make_float4(dy0*rs*w1.x+b1.x, dy1*rs*w1.y+b1.y,
                            dy2*rs*w1.z+b1.z, dy3*rs*w1.w+b1.w);
    xr[tid]       = o0;
    xr[tid + 128] = o1;

    __half2* H = (__half2*)(xa + (size_t)row * DD);
    H[tid*2]         = __floats2half2_rn(o0.x, o0.y);
    H[tid*2 + 1]     = __floats2half2_rn(o0.z, o0.w);
    H[(tid+128)*2]   = __floats2half2_rn(o1.x, o1.y);
    H[(tid+128)*2+1] = __floats2half2_rn(o1.z, o1.w);
}

// ------------------------- launch ------------------------------------------
extern "C" void kernel_launch(void* const* d_in, const int* in_sizes, int n_in,
                              void* d_out, int out_size) {
    (void)in_sizes; (void)n_in; (void)out_size;
    const int*   idx  = (const int*)  d_in[0];
    const float* emb  = (const float*)d_in[1];
    const float* Wq   = (const float*)d_in[2];
    const float* Wk   = (const float*)d_in[3];
    const float* Wv   = (const float*)d_in[4];
    const float* Wo   = (const float*)d_in[5];
    const float* ln1w = (const float*)d_in[6];
    const float* ln1b = (const float*)d_in[7];
    const float* W1   = (const float*)d_in[8];
    const float* W2   = (const float*)d_in[9];
    const float* ln2w = (const float*)d_in[10];
    const float* ln2b = (const float*)d_in[11];
    const float* Wout = (const float*)d_in[12];

    float *x, *t;
    __half *wh, *wl, *xa, *oa, *fa, *qa, *kh, *kl, *va;
    cudaGetSymbolAddress((void**)&x, g_x);
    cudaGetSymbolAddress((void**)&t, g_t);
    cudaGetSymbolAddress((void**)&wh, g_wh);
    cudaGetSymbolAddress((void**)&wl, g_wl);
    cudaGetSymbolAddress((void**)&xa, g_xa);
    cudaGetSymbolAddress((void**)&oa, g_oa);
    cudaGetSymbolAddress((void**)&fa, g_fa);
    cudaGetSymbolAddress((void**)&qa, g_qa);
    cudaGetSymbolAddress((void**)&kh, g_kh);
    cudaGetSymbolAddress((void**)&kl, g_kl);
    cudaGetSymbolAddress((void**)&va, g_va);

    cudaFuncSetAttribute(gemm_tc<0,0>, cudaFuncAttributeMaxDynamicSharedMemorySize, GSMEM);
    cudaFuncSetAttribute(gemm_tc<0,1>, cudaFuncAttributeMaxDynamicSharedMemorySize, GSMEM);
    cudaFuncSetAttribute(gemm_tc<1,2>, cudaFuncAttributeMaxDynamicSharedMemorySize, GSMEM);
    cudaFuncSetAttribute(flash_tc, cudaFuncAttributeMaxDynamicSharedMemorySize, FSMEM);

    // weight splits (once per launch)
    {
        const float* Ws[3] = {Wq, Wk, Wv};
        for (int l = 0; l < LL; l++)
            for (int j = 0; j < 3; j++) {
                size_t src = (size_t)l * DD * DD;
                size_t dst = WQKV + (size_t)l * 3*DD*DD + (size_t)j * DD * DD;
                wsplit_kernel<<<(DD*DD/4 + 255)/256, 256>>>(Ws[j] + src,
                                                            wh + dst, wl + dst, DD*DD/4);
            }
        int n4;
        n4 = (LL*DD*DD)/4;
        wsplit_kernel<<<(n4+255)/256, 256>>>(Wo, wh+WOO, wl+WOO, n4);
        n4 = (LL*DFF*DD)/4;
        wsplit_kernel<<<(n4+255)/256, 256>>>(W1, wh+W1O, wl+W1O, n4);
        wsplit_kernel<<<(n4+255)/256, 256>>>(W2, wh+W2O, wl+W2O, n4);
        n4 = (VV*DD)/4;
        wsplit_kernel<<<(n4+255)/256, 256>>>(Wout, wh+WUO, wl+WUO, n4);
    }

    embed_kernel<<<(BB*SS*(DD/2) + 255) / 256, 256>>>(idx, emb, x, xa);

    for (int l = 0; l < LL; l++) {
        const size_t wqkv = WQKV + (size_t)l * 3*DD*DD;
        const size_t ws   = (size_t)l * DD * DD;
        const size_t wf   = (size_t)l * DFF * DD;
        // fused QKV (N = 3072)
        gemm_tc<0,1><<<dim3(12, 32), 256, GSMEM>>>(xa, wh+wqkv, wl+wqkv,
                                                   nullptr, qa, kh, kl, va,
                                                   MM, 3*DD, DD);
        flash_tc<<<dim3(SS/64, BB*HH), 128, FSMEM>>>(qa, kh, kl, va, oa);
        gemm_tc<0,0><<<dim3(4, 32), 256, GSMEM>>>(oa, wh+WOO+ws, wl+WOO+ws,
                                                  t, nullptr, nullptr, nullptr, nullptr,
                                                  MM, DD, DD);
        add_ln_kernel<<<MM, 128>>>(x, t, ln1w + l*DD, ln1b + l*DD, xa);
        gemm_tc<1,2><<<dim3(16, 32), 256, GSMEM>>>(xa, wh+W1O+wf, wl+W1O+wf,
                                                   nullptr, fa, nullptr, nullptr, nullptr,
                                                   MM, DFF, DD);
        gemm_tc<0,0><<<dim3(4, 32), 256, GSMEM>>>(fa, wh+W2O+wf, wl+W2O+wf,
                                                  t, nullptr, nullptr, nullptr, nullptr,
                                                  MM, DD, DFF);
        add_ln_kernel<<<MM, 128>>>(x, t, ln2w + l*DD, ln2b + l*DD, xa);
    }
    gemm_tc<0,0><<<dim3(8, 32), 256, GSMEM>>>(xa, wh+WUO, wl+WUO,
                                              (float*)d_out, nullptr, nullptr, nullptr,
                                              nullptr, MM, VV, DD);
}

// round 11
// speedup vs baseline: 6.2708x; 1.4951x over previous
#include <cuda_runtime.h>
#include <cuda_fp16.h>
#include <math.h>
#include <stdint.h>

// Problem constants
#define BB   2
#define SS   2048
#define DD   1024
#define HH   16
#define LL   4
#define VV   2000
#define DK   64
#define DFF  4096
#define MM   (BB*SS)          // 4096 rows

// ------------------------- scratch (static device memory) -------------------
__device__ float g_x[MM*DD];      // activations [B*S, D] fp32 (residual path)
__device__ float g_t[MM*DD];      // temp (pre-LN residual branch)

// single-fp16 weights
#define WQKV 0u                    // [L][Wq;Wk;Wv] each 1024x1024
#define WOO  12582912u
#define W1O  16777216u
#define W2O  33554432u
#define WUO  50331648u
#define WTOT 52379648u
__device__ __half g_wh[WTOT];
// single-fp16 activations
__device__ __half g_xa[MM*DD];     // LN output
__device__ __half g_oa[MM*DD];     // attention out [B,S,D]
__device__ __half g_fa[MM*DFF];    // FFN hidden (post-relu)
__device__ __half g_qa[MM*DD];     // [B,H,S,DK]
__device__ __half g_kh[MM*DD], g_kl[MM*DD];
__device__ __half g_va[MM*DD];

// ------------------------- PTX helpers --------------------------------------
__device__ __forceinline__ uint32_t s2u(const void* p) {
    uint32_t a;
    asm("{ .reg .u64 t; cvta.to.shared.u64 t, %1; cvt.u32.u64 %0, t; }"
        : "=r"(a) : "l"(p));
    return a;
}
__device__ __forceinline__ void cpa16(uint32_t s, const void* g) {
    asm volatile("cp.async.cg.shared.global [%0], [%1], 16;" :: "r"(s), "l"(g));
}
__device__ __forceinline__ void ldsm4(uint32_t* r, uint32_t a) {
    asm volatile("ldmatrix.sync.aligned.m8n8.x4.shared.b16 {%0,%1,%2,%3}, [%4];"
                 : "=r"(r[0]), "=r"(r[1]), "=r"(r[2]), "=r"(r[3]) : "r"(a));
}
__device__ __forceinline__ void ldsm4t(uint32_t* r, uint32_t a) {
    asm volatile("ldmatrix.sync.aligned.m8n8.x4.trans.shared.b16 {%0,%1,%2,%3}, [%4];"
                 : "=r"(r[0]), "=r"(r[1]), "=r"(r[2]), "=r"(r[3]) : "r"(a));
}
__device__ __forceinline__ void mma16816(float* c, const uint32_t* a, const uint32_t* b) {
    asm volatile(
        "mma.sync.aligned.m16n8k16.row.col.f32.f16.f16.f32 "
        "{%0,%1,%2,%3}, {%4,%5,%6,%7}, {%8,%9}, {%0,%1,%2,%3};"
        : "+f"(c[0]), "+f"(c[1]), "+f"(c[2]), "+f"(c[3])
        : "r"(a[0]), "r"(a[1]), "r"(a[2]), "r"(a[3]), "r"(b[0]), "r"(b[1]));
}

// ------------------------- convert / split helpers ---------------------------
__device__ __forceinline__ void hsplit2(float a, float b, __half2* H, __half2* L,
                                        size_t i) {
    __half ha = __float2half_rn(a), hb = __float2half_rn(b);
    H[i] = __halves2half2(ha, hb);
    L[i] = __halves2half2(__float2half_rn(a - __half2float(ha)),
                          __float2half_rn(b - __half2float(hb)));
}
__device__ __forceinline__ uint32_t packsplit(float a, float b, uint32_t& lo) {
    __half ha = __float2half_rn(a), hb = __float2half_rn(b);
    __half2 h2 = __halves2half2(ha, hb);
    __half2 l2 = __halves2half2(__float2half_rn(a - __half2float(ha)),
                                __float2half_rn(b - __half2float(hb)));
    lo = *(uint32_t*)&l2;
    return *(uint32_t*)&h2;
}

__global__ void wconv_kernel(const float* __restrict__ s,
                             __half* __restrict__ h, int n4) {
    int i = blockIdx.x * blockDim.x + threadIdx.x;
    if (i >= n4) return;
    float4 v = ((const float4*)s)[i];
    ((__half2*)h)[(size_t)i*2]     = __floats2half2_rn(v.x, v.y);
    ((__half2*)h)[(size_t)i*2 + 1] = __floats2half2_rn(v.z, v.w);
}

// ------------------------- embedding + positional encoding ------------------
__global__ void embed_kernel(const int* __restrict__ idx,
                             const float* __restrict__ emb,
                             float* __restrict__ x, __half* __restrict__ xa) {
    int t = blockIdx.x * blockDim.x + threadIdx.x;
    if (t >= BB*SS*(DD/2)) return;
    int dp = t & 511;
    int bs = t >> 9;
    int s  = bs & (SS - 1);
    int d  = dp << 1;
    double freq = exp((double)d * (-9.210340371976184 / 1024.0));
    double ang  = (double)s * freq;
    double sv, cv;
    sincos(ang, &sv, &cv);
    int tok = idx[bs];
    float2 e = ((const float2*)emb)[(size_t)tok * 512 + dp];
    float vx = e.x + (float)sv, vy = e.y + (float)cv;
    ((float2*)x)[t] = make_float2(vx, vy);
    ((__half2*)xa)[t] = __floats2half2_rn(vx, vy);
}

// ------------------------- mma.sync fp16 1-term GEMM -------------------------
// C[M,N] = A[M,K] * B[N,K]^T, A and B single fp16, fp32 accum.
// CTA tile 128x256, K-tile 32, 256 thr, 8 warps (64x64 warp tiles).
// OMODE: 0 = fp32 row-major out
//        1 = fused QKV (N=3072): q/v single fp16, k hi/lo, remap [B,H,S,DK]
//        2 = fp16 single row-major out (with optional relu)
#define LDSB   80            // smem row stride in bytes (40 fp16)
#define ATILE  (128*LDSB)    // 10240
#define BTILE  (256*LDSB)    // 20480
#define STAGEB (ATILE + BTILE)       // 30720
#define NSTAGE 3
#define GSMEM  (NSTAGE*STAGEB)       // 92160

template<int ACT, int OMODE>
__global__ __launch_bounds__(256)
void gemm_tc(const __half* __restrict__ Aq, const __half* __restrict__ Bq,
             float* __restrict__ C,
             __half* __restrict__ P0, __half* __restrict__ P1,
             __half* __restrict__ P2, __half* __restrict__ P3,
             int M, int N, int K)
{
    extern __shared__ __align__(16) char smem[];
    const uint32_t sb = s2u(smem);
    const int tid = threadIdx.x;
    const int wid = tid >> 5, lane = tid & 31;
    const int wm = wid & 1, wn = wid >> 1;
    const int row0 = blockIdx.y * 128, col0 = blockIdx.x * 256;

    const int chunk = tid & 3;
    const int rr    = tid >> 2;
    const int rA0 = row0 + rr, rA1 = rA0 + 64;
    int rB0 = col0 + rr;       if (rB0 > N - 1) rB0 = N - 1;
    int rB1 = col0 + rr + 64;  if (rB1 > N - 1) rB1 = N - 1;
    int rB2 = col0 + rr + 128; if (rB2 > N - 1) rB2 = N - 1;
    int rB3 = col0 + rr + 192; if (rB3 > N - 1) rB3 = N - 1;
    const uint32_t sA0 = (uint32_t)rr * LDSB + (uint32_t)chunk * 16;

    auto issue = [&](int kt, int buf) {
        const int ko = kt * 32 + chunk * 8;
        const uint32_t base = sb + (uint32_t)buf * STAGEB;
        cpa16(base + sA0,            Aq + (size_t)rA0 * K + ko);
        cpa16(base + sA0 + 64u*LDSB, Aq + (size_t)rA1 * K + ko);
        const uint32_t bb = base + ATILE;
        cpa16(bb + sA0,              Bq + (size_t)rB0 * K + ko);
        cpa16(bb + sA0 +  64u*LDSB,  Bq + (size_t)rB1 * K + ko);
        cpa16(bb + sA0 + 128u*LDSB,  Bq + (size_t)rB2 * K + ko);
        cpa16(bb + sA0 + 192u*LDSB,  Bq + (size_t)rB3 * K + ko);
        asm volatile("cp.async.commit_group;" ::: "memory");
    };

    float acc[4][8][4];
#pragma unroll
    for (int i = 0; i < 4; i++)
#pragma unroll
        for (int j = 0; j < 8; j++)
#pragma unroll
            for (int q = 0; q < 4; q++) acc[i][j][q] = 0.f;

    const int KT = K >> 5;
    issue(0, 0);
    issue(1, 1);
    issue(2, 2);

    const uint32_t aoff = (uint32_t)(wm*64 + (lane & 15)) * LDSB + ((lane >> 4) << 4);
    const uint32_t boff = (uint32_t)(wn*64 + (lane & 7) + ((lane >> 4) << 3)) * LDSB
                        + (((lane >> 3) & 1) << 4);

    int buf = 0;
#pragma unroll 1
    for (int kt = 0; kt < KT; kt++) {
        if (kt + 2 < KT)      asm volatile("cp.async.wait_group 2;" ::: "memory");
        else if (kt + 1 < KT) asm volatile("cp.async.wait_group 1;" ::: "memory");
        else                  asm volatile("cp.async.wait_group 0;" ::: "memory");
        __syncthreads();
        const uint32_t base = sb + (uint32_t)buf * STAGEB;
#pragma unroll
        for (int ks = 0; ks < 2; ks++) {
            const uint32_t ka = base + (uint32_t)ks * 32 + aoff;
            const uint32_t kb = base + ATILE + (uint32_t)ks * 32 + boff;
            uint32_t ah[4][4];
#pragma unroll
            for (int mt = 0; mt < 4; mt++)
                ldsm4(ah[mt], ka + (uint32_t)mt * (16*LDSB));
#pragma unroll
            for (int p = 0; p < 4; p++) {
                uint32_t b4[4];
                ldsm4(b4, kb + (uint32_t)p * (16*LDSB));
#pragma unroll
                for (int mt = 0; mt < 4; mt++) {
                    mma16816(acc[mt][2*p],   ah[mt], b4);
                    mma16816(acc[mt][2*p+1], ah[mt], b4 + 2);
                }
            }
        }
        __syncthreads();
        if (kt + 3 < KT) issue(kt + 3, buf);
        buf = (buf == 2) ? 0 : buf + 1;
    }

    const int base_m = row0 + wm*64;
    const int base_n = col0 + wn*64;
#pragma unroll
    for (int mt = 0; mt < 4; mt++) {
#pragma unroll
        for (int nt = 0; nt < 8; nt++) {
            float* c = acc[mt][nt];
            if (ACT == 1) {
                c[0] = fmaxf(c[0], 0.f); c[1] = fmaxf(c[1], 0.f);
                c[2] = fmaxf(c[2], 0.f); c[3] = fmaxf(c[3], 0.f);
            }
            const int r0 = base_m + mt*16 + (lane >> 2);
            const int cc = base_n + nt*8 + (lane & 3)*2;
            if (OMODE == 0) {
                if (cc < N) {
                    *(float2*)(C + (size_t)r0 * N + cc)       = make_float2(c[0], c[1]);
                    *(float2*)(C + (size_t)(r0 + 8) * N + cc) = make_float2(c[2], c[3]);
                }
            } else if (OMODE == 1) {
                // fused QKV: n in [0,3072)
                const int sect = cc >> 10;
                const int nc = cc & 1023;
                const int h = nc >> 6, kk = nc & (DK - 1);
                const int b0i = r0 >> 11, s0r = r0 & (SS - 1);
                const size_t i0 = (((size_t)(b0i*HH + h)*SS + s0r)*DK + kk) >> 1;
                const int r1 = r0 + 8;
                const int b1i = r1 >> 11, s1r = r1 & (SS - 1);
                const size_t i1 = (((size_t)(b1i*HH + h)*SS + s1r)*DK + kk) >> 1;
                if (sect == 0) {
                    ((__half2*)P0)[i0] = __floats2half2_rn(c[0], c[1]);
                    ((__half2*)P0)[i1] = __floats2half2_rn(c[2], c[3]);
                } else if (sect == 1) {
                    hsplit2(c[0], c[1], (__half2*)P1, (__half2*)P2, i0);
                    hsplit2(c[2], c[3], (__half2*)P1, (__half2*)P2, i1);
                } else {
                    ((__half2*)P3)[i0] = __floats2half2_rn(c[0], c[1]);
                    ((__half2*)P3)[i1] = __floats2half2_rn(c[2], c[3]);
                }
            } else {
                if (cc < N) {
                    ((__half2*)P0)[((size_t)r0 * N + cc) >> 1]
                        = __floats2half2_rn(c[0], c[1]);
                    ((__half2*)P0)[((size_t)(r0 + 8) * N + cc) >> 1]
                        = __floats2half2_rn(c[2], c[3]);
                }
            }
        }
    }
}

// ------------------------- tensor-core flash attention ----------------------
// Q single fp16, K hi/lo fp16, V single fp16 in [B,H,S,DK]. Causal.
// CTA = 64 q-rows, 4 warps. 2-term QK^T (Q*(Kh+Kl)); 2-term PV ((Ph+Pl)*V).
// Output single fp16 [B,S,D].
#define FSTR   144                 // smem row stride bytes (64 fp16 + pad)
#define FKV0   9216                // after Q tile
#define FKOFF  0
#define FKLOFF 9216
#define FVOFF  18432
#define FSTAGE 27648
#define FSMEM  (FKV0 + 2*FSTAGE)   // 64512

__global__ __launch_bounds__(128)
void flash_tc(const __half* __restrict__ Qa,
              const __half* __restrict__ Kh, const __half* __restrict__ Kl,
              const __half* __restrict__ Va, __half* __restrict__ OA)
{
    extern __shared__ __align__(16) char smem[];
    const uint32_t sb = s2u(smem);
    const int bh  = blockIdx.y;
    const int qt  = gridDim.x - 1 - blockIdx.x;   // heavy blocks first
    const int tid = threadIdx.x, wid = tid >> 5, lane = tid & 31;
    const int q0  = qt * 64;

    // Q tile load
    {
        const size_t g = ((size_t)bh * SS + q0) * DK;
#pragma unroll
        for (int c = tid; c < 512; c += 128) {
            const int row = c >> 3, ch = c & 7;
            cpa16(sb + (uint32_t)row * FSTR + (uint32_t)ch * 16,
                  Qa + g + row * DK + ch * 8);
        }
        asm volatile("cp.async.commit_group;" ::: "memory");
    }

    auto loadkv = [&](int kt, int bufi) {
        const uint32_t base = sb + FKV0 + (uint32_t)bufi * FSTAGE;
        const size_t g = ((size_t)bh * SS + kt * 64) * DK;
#pragma unroll
        for (int c = tid; c < 512; c += 128) {
            const int row = c >> 3, ch = c & 7;
            const uint32_t so = (uint32_t)row * FSTR + (uint32_t)ch * 16;
            const size_t go = g + row * DK + ch * 8;
            cpa16(base + FKOFF  + so, Kh + go);
            cpa16(base + FKLOFF + so, Kl + go);
            cpa16(base + FVOFF  + so, Va + go);
        }
        asm volatile("cp.async.commit_group;" ::: "memory");
    };

    loadkv(0, 0);
    if (qt >= 1) loadkv(1, 1);

    if (qt >= 1) asm volatile("cp.async.wait_group 1;" ::: "memory");
    else         asm volatile("cp.async.wait_group 0;" ::: "memory");
    __syncthreads();

    // Q fragments
    uint32_t qf[4][4];
    {
        const uint32_t a0 = sb + (uint32_t)(wid*16 + (lane & 15)) * FSTR + ((lane >> 4) << 4);
#pragma unroll
        for (int kc = 0; kc < 4; kc++)
            ldsm4(qf[kc], a0 + kc*32);
    }

    float o[8][4];
#pragma unroll
    for (int i = 0; i < 8; i++)
#pragma unroll
        for (int j = 0; j < 4; j++) o[i][j] = 0.f;
    float mi0 = -1e30f, mi1 = -1e30f, li0 = 0.f, li1 = 0.f;

    const uint32_t kboff = (uint32_t)((lane & 7) + ((lane >> 4) << 3)) * FSTR
                         + (((lane >> 3) & 1) << 4);
    const uint32_t vboff = (uint32_t)((((lane >> 3) & 1) << 3) + (lane & 7)) * FSTR
                         + ((lane >> 4) << 4);

#pragma unroll 1
    for (int kt = 0; kt <= qt; kt++) {
        const int bufi = kt & 1;
        if (kt > 0) {
            if (kt < qt) asm volatile("cp.async.wait_group 1;" ::: "memory");
            else         asm volatile("cp.async.wait_group 0;" ::: "memory");
            __syncthreads();
        }
        const uint32_t base = sb + FKV0 + (uint32_t)bufi * FSTAGE;

        // S = Q K^T (2-term: Q*(Kh+Kl))
        float s[8][4];
#pragma unroll
        for (int i = 0; i < 8; i++)
#pragma unroll
            for (int j = 0; j < 4; j++) s[i][j] = 0.f;
#pragma unroll
        for (int kc = 0; kc < 4; kc++) {
#pragma unroll
            for (int np = 0; np < 4; np++) {
                uint32_t kh4[4], kl4[4];
                ldsm4(kh4, base + FKOFF  + kboff + kc*32 + (uint32_t)np * (16*FSTR));
                ldsm4(kl4, base + FKLOFF + kboff + kc*32 + (uint32_t)np * (16*FSTR));
                mma16816(s[2*np],   qf[kc], kh4);
                mma16816(s[2*np],   qf[kc], kl4);
                mma16816(s[2*np+1], qf[kc], kh4 + 2);
                mma16816(s[2*np+1], qf[kc], kl4 + 2);
            }
        }

        // scale + causal mask (diagonal tile only)
        if (kt == qt) {
            const int r = wid*16 + (lane >> 2);
            const int cb = (lane & 3) * 2;
#pragma unroll
            for (int nt = 0; nt < 8; nt++) {
                const int k0 = nt*8 + cb;
                s[nt][0] = (k0     <= r    ) ? s[nt][0]*0.125f : -1e30f;
                s[nt][1] = (k0 + 1 <= r    ) ? s[nt][1]*0.125f : -1e30f;
                s[nt][2] = (k0     <= r + 8) ? s[nt][2]*0.125f : -1e30f;
                s[nt][3] = (k0 + 1 <= r + 8) ? s[nt][3]*0.125f : -1e30f;
            }
        } else {
#pragma unroll
            for (int nt = 0; nt < 8; nt++) {
                s[nt][0] *= 0.125f; s[nt][1] *= 0.125f;
                s[nt][2] *= 0.125f; s[nt][3] *= 0.125f;
            }
        }

        // online softmax
        float m0 = -1e30f, m1 = -1e30f;
#pragma unroll
        for (int nt = 0; nt < 8; nt++) {
            m0 = fmaxf(m0, fmaxf(s[nt][0], s[nt][1]));
            m1 = fmaxf(m1, fmaxf(s[nt][2], s[nt][3]));
        }
        m0 = fmaxf(m0, __shfl_xor_sync(0xffffffffu, m0, 1));
        m0 = fmaxf(m0, __shfl_xor_sync(0xffffffffu, m0, 2));
        m1 = fmaxf(m1, __shfl_xor_sync(0xffffffffu, m1, 1));
        m1 = fmaxf(m1, __shfl_xor_sync(0xffffffffu, m1, 2));
        const float mn0 = fmaxf(mi0, m0), mn1 = fmaxf(mi1, m1);
        const float rs0 = __expf(mi0 - mn0), rs1 = __expf(mi1 - mn1);
        mi0 = mn0; mi1 = mn1;
        li0 *= rs0; li1 *= rs1;
#pragma unroll
        for (int nt = 0; nt < 8; nt++) {
            o[nt][0] *= rs0; o[nt][1] *= rs0;
            o[nt][2] *= rs1; o[nt][3] *= rs1;
        }
        float ls0 = 0.f, ls1 = 0.f;
#pragma unroll
        for (int nt = 0; nt < 8; nt++) {
            s[nt][0] = __expf(s[nt][0] - mn0);
            s[nt][1] = __expf(s[nt][1] - mn0);
            s[nt][2] = __expf(s[nt][2] - mn1);
            s[nt][3] = __expf(s[nt][3] - mn1);
            ls0 += s[nt][0] + s[nt][1];
            ls1 += s[nt][2] + s[nt][3];
        }
        li0 += ls0; li1 += ls1;

        // O += P V (2-term: (Ph+Pl)*V)
#pragma unroll
        for (int kc = 0; kc < 4; kc++) {
            uint32_t pa[4], plo[4];
            pa[0] = packsplit(s[2*kc][0],   s[2*kc][1],   plo[0]);
            pa[1] = packsplit(s[2*kc][2],   s[2*kc][3],   plo[1]);
            pa[2] = packsplit(s[2*kc+1][0], s[2*kc+1][1], plo[2]);
            pa[3] = packsplit(s[2*kc+1][2], s[2*kc+1][3], plo[3]);
#pragma unroll
            for (int np = 0; np < 4; np++) {
                uint32_t vh4[4];
                ldsm4t(vh4, base + FVOFF + vboff + (uint32_t)kc * (16*FSTR) + np*32);
                mma16816(o[2*np],   pa,  vh4);
                mma16816(o[2*np],   plo, vh4);
                mma16816(o[2*np+1], pa,  vh4 + 2);
                mma16816(o[2*np+1], plo, vh4 + 2);
            }
        }

        __syncthreads();
        if (kt + 2 <= qt) loadkv(kt + 2, bufi);
    }

    // final row sums + write O single fp16 [B,S,D]
    li0 += __shfl_xor_sync(0xffffffffu, li0, 1);
    li0 += __shfl_xor_sync(0xffffffffu, li0, 2);
    li1 += __shfl_xor_sync(0xffffffffu, li1, 1);
    li1 += __shfl_xor_sync(0xffffffffu, li1, 2);
    const float inv0 = 1.f / li0, inv1 = 1.f / li1;
    const int b = bh >> 4, h = bh & (HH - 1);
    const int qr = q0 + wid*16 + (lane >> 2);
    const size_t rowA = ((size_t)(b*SS + qr)) * DD + h * DK;
    const size_t rowB = rowA + 8 * DD;
    __half2* OA2 = (__half2*)OA;
#pragma unroll
    for (int nt = 0; nt < 8; nt++) {
        const int dk = nt*8 + (lane & 3)*2;
        OA2[(rowA + dk) >> 1] = __floats2half2_rn(o[nt][0]*inv0, o[nt][1]*inv0);
        OA2[(rowB + dk) >> 1] = __floats2half2_rn(o[nt][2]*inv1, o[nt][3]*inv1);
    }
}

// ------------------------- residual add + layernorm + fp16 out --------------
__global__ __launch_bounds__(128)
void add_ln_kernel(float* __restrict__ x, const float* __restrict__ r,
                   const float* __restrict__ w, const float* __restrict__ bias,
                   __half* __restrict__ xa) {
    __shared__ float sh[4];
    const int row = blockIdx.x;
    const int tid = threadIdx.x;
    float4* xr = (float4*)(x + (size_t)row * DD);
    const float4* rr = (const float4*)(r + (size_t)row * DD);
    float4 v0 = xr[tid], v1 = xr[tid + 128];
    float4 a0 = rr[tid], a1 = rr[tid + 128];
    v0.x += a0.x; v0.y += a0.y; v0.z += a0.z; v0.w += a0.w;
    v1.x += a1.x; v1.y += a1.y; v1.z += a1.z; v1.w += a1.w;

    float s = v0.x+v0.y+v0.z+v0.w + v1.x+v1.y+v1.z+v1.w;
#pragma unroll
    for (int o = 16; o > 0; o >>= 1) s += __shfl_down_sync(0xffffffffu, s, o);
    if ((tid & 31) == 0) sh[tid >> 5] = s;
    __syncthreads();
    float mean = (sh[0]+sh[1]+sh[2]+sh[3]) * (1.f/DD);
    __syncthreads();

    float dx0 = v0.x-mean, dx1 = v0.y-mean, dx2 = v0.z-mean, dx3 = v0.w-mean;
    float dy0 = v1.x-mean, dy1 = v1.y-mean, dy2 = v1.z-mean, dy3 = v1.w-mean;
    float sq = dx0*dx0+dx1*dx1+dx2*dx2+dx3*dx3 + dy0*dy0+dy1*dy1+dy2*dy2+dy3*dy3;
#pragma unroll
    for (int o = 16; o > 0; o >>= 1) sq += __shfl_down_sync(0xffffffffu, sq, o);
    if ((tid & 31) == 0) sh[tid >> 5] = sq;
    __syncthreads();
    float var = (sh[0]+sh[1]+sh[2]+sh[3]) * (1.f/DD);
    float rs = rsqrtf(var + 1e-5f);

    float4 w0 = ((const float4*)w)[tid],     w1 = ((const float4*)w)[tid + 128];
    float4 b0 = ((const float4*)bias)[tid],  b1 = ((const float4*)bias)[tid + 128];
    float4 o0 = make_float4(dx0*rs*w0.x+b0.x, dx1*rs*w0.y+b0.y,
                            dx2*rs*w0.z+b0.z, dx3*rs*w0.w+b0.w);
    float4 o1 = make_float4(dy0*rs*w1.x+b1.x, dy1*rs*w1.y+b1.y,
                            dy2*rs*w1.z+b1.z, dy3*rs*w1.w+b1.w);
    xr[tid]       = o0;
    xr[tid + 128] = o1;

    __half2* H = (__half2*)(xa + (size_t)row * DD);
    H[tid*2]         = __floats2half2_rn(o0.x, o0.y);
    H[tid*2 + 1]     = __floats2half2_rn(o0.z, o0.w);
    H[(tid+128)*2]   = __floats2half2_rn(o1.x, o1.y);
    H[(tid+128)*2+1] = __floats2half2_rn(o1.z, o1.w);
}

// ------------------------- launch ------------------------------------------
extern "C" void kernel_launch(void* const* d_in, const int* in_sizes, int n_in,
                              void* d_out, int out_size) {
    (void)in_sizes; (void)n_in; (void)out_size;
    const int*   idx  = (const int*)  d_in[0];
    const float* emb  = (const float*)d_in[1];
    const float* Wq   = (const float*)d_in[2];
    const float* Wk   = (const float*)d_in[3];
    const float* Wv   = (const float*)d_in[4];
    const float* Wo   = (const float*)d_in[5];
    const float* ln1w = (const float*)d_in[6];
    const float* ln1b = (const float*)d_in[7];
    const float* W1   = (const float*)d_in[8];
    const float* W2   = (const float*)d_in[9];
    const float* ln2w = (const float*)d_in[10];
    const float* ln2b = (const float*)d_in[11];
    const float* Wout = (const float*)d_in[12];

    float *x, *t;
    __half *wh, *xa, *oa, *fa, *qa, *kh, *kl, *va;
    cudaGetSymbolAddress((void**)&x, g_x);
    cudaGetSymbolAddress((void**)&t, g_t);
    cudaGetSymbolAddress((void**)&wh, g_wh);
    cudaGetSymbolAddress((void**)&xa, g_xa);
    cudaGetSymbolAddress((void**)&oa, g_oa);
    cudaGetSymbolAddress((void**)&fa, g_fa);
    cudaGetSymbolAddress((void**)&qa, g_qa);
    cudaGetSymbolAddress((void**)&kh, g_kh);
    cudaGetSymbolAddress((void**)&kl, g_kl);
    cudaGetSymbolAddress((void**)&va, g_va);

    cudaFuncSetAttribute(gemm_tc<0,0>, cudaFuncAttributeMaxDynamicSharedMemorySize, GSMEM);
    cudaFuncSetAttribute(gemm_tc<0,1>, cudaFuncAttributeMaxDynamicSharedMemorySize, GSMEM);
    cudaFuncSetAttribute(gemm_tc<1,2>, cudaFuncAttributeMaxDynamicSharedMemorySize, GSMEM);
    cudaFuncSetAttribute(flash_tc, cudaFuncAttributeMaxDynamicSharedMemorySize, FSMEM);

    // weight conversion (once per launch)
    {
        const float* Ws[3] = {Wq, Wk, Wv};
        for (int l = 0; l < LL; l++)
            for (int j = 0; j < 3; j++) {
                size_t src = (size_t)l * DD * DD;
                size_t dst = WQKV + (size_t)l * 3*DD*DD + (size_t)j * DD * DD;
                wconv_kernel<<<(DD*DD/4 + 255)/256, 256>>>(Ws[j] + src, wh + dst, DD*DD/4);
            }
        int n4;
        n4 = (LL*DD*DD)/4;
        wconv_kernel<<<(n4+255)/256, 256>>>(Wo, wh+WOO, n4);
        n4 = (LL*DFF*DD)/4;
        wconv_kernel<<<(n4+255)/256, 256>>>(W1, wh+W1O, n4);
        wconv_kernel<<<(n4+255)/256, 256>>>(W2, wh+W2O, n4);
        n4 = (VV*DD)/4;
        wconv_kernel<<<(n4+255)/256, 256>>>(Wout, wh+WUO, n4);
    }

    embed_kernel<<<(BB*SS*(DD/2) + 255) / 256, 256>>>(idx, emb, x, xa);

    for (int l = 0; l < LL; l++) {
        const size_t wqkv = WQKV + (size_t)l * 3*DD*DD;
        const size_t ws   = (size_t)l * DD * DD;
        const size_t wf   = (size_t)l * DFF * DD;
        // fused QKV (N = 3072)
        gemm_tc<0,1><<<dim3(12, 32), 256, GSMEM>>>(xa, wh+wqkv,
                                                   nullptr, qa, kh, kl, va,
                                                   MM, 3*DD, DD);
        flash_tc<<<dim3(SS/64, BB*HH), 128, FSMEM>>>(qa, kh, kl, va, oa);
        gemm_tc<0,0><<<dim3(4, 32), 256, GSMEM>>>(oa, wh+WOO+ws,
                                                  t, nullptr, nullptr, nullptr, nullptr,
                                                  MM, DD, DD);
        add_ln_kernel<<<MM, 128>>>(x, t, ln1w + l*DD, ln1b + l*DD, xa);
        gemm_tc<1,2><<<dim3(16, 32), 256, GSMEM>>>(xa, wh+W1O+wf,
                                                   nullptr, fa, nullptr, nullptr, nullptr,
                                                   MM, DFF, DD);
        gemm_tc<0,0><<<dim3(4, 32), 256, GSMEM>>>(fa, wh+W2O+wf,
                                                  t, nullptr, nullptr, nullptr, nullptr,
                                                  MM, DD, DFF);
        add_ln_kernel<<<MM, 128>>>(x, t, ln2w + l*DD, ln2b + l*DD, xa);
    }
    gemm_tc<0,0><<<dim3(8, 32), 256, GSMEM>>>(xa, wh+WUO,
                                              (float*)d_out, nullptr, nullptr, nullptr,
                                              nullptr, MM, VV, DD);
}

// round 13
// speedup vs baseline: 6.4841x; 1.0340x over previous
#include <cuda_runtime.h>
#include <cuda_fp16.h>
#include <math.h>
#include <stdint.h>

// Problem constants
#define BB   2
#define SS   2048
#define DD   1024
#define HH   16
#define LL   4
#define VV   2000
#define DK   64
#define DFF  4096
#define MM   (BB*SS)          // 4096 rows

// ------------------------- scratch (static device memory) -------------------
__device__ float g_x[MM*DD];      // activations [B*S, D] fp32 (residual path)
__device__ float g_t[MM*DD];      // temp (pre-LN residual branch)

// single-fp16 weights
#define WQKV 0u                    // [L][Wq;Wk;Wv] each 1024x1024
#define WOO  12582912u
#define W1O  16777216u
#define W2O  33554432u
#define WUO  50331648u
#define WTOT 52379648u
__device__ __half g_wh[WTOT];
// single-fp16 activations
__device__ __half g_xa[MM*DD];     // LN output
__device__ __half g_oa[MM*DD];     // attention out [B,S,D]
__device__ __half g_fa[MM*DFF];    // FFN hidden (post-relu)
__device__ __half g_qa[MM*DD];     // [B,H,S,DK] (pre-scaled by 1/8)
__device__ __half g_kh[MM*DD], g_kl[MM*DD];
__device__ __half g_va[MM*DD];

// ------------------------- PTX helpers --------------------------------------
__device__ __forceinline__ uint32_t s2u(const void* p) {
    uint32_t a;
    asm("{ .reg .u64 t; cvta.to.shared.u64 t, %1; cvt.u32.u64 %0, t; }"
        : "=r"(a) : "l"(p));
    return a;
}
__device__ __forceinline__ void cpa16(uint32_t s, const void* g) {
    asm volatile("cp.async.cg.shared.global [%0], [%1], 16;" :: "r"(s), "l"(g));
}
__device__ __forceinline__ void ldsm4(uint32_t* r, uint32_t a) {
    asm volatile("ldmatrix.sync.aligned.m8n8.x4.shared.b16 {%0,%1,%2,%3}, [%4];"
                 : "=r"(r[0]), "=r"(r[1]), "=r"(r[2]), "=r"(r[3]) : "r"(a));
}
__device__ __forceinline__ void ldsm4t(uint32_t* r, uint32_t a) {
    asm volatile("ldmatrix.sync.aligned.m8n8.x4.trans.shared.b16 {%0,%1,%2,%3}, [%4];"
                 : "=r"(r[0]), "=r"(r[1]), "=r"(r[2]), "=r"(r[3]) : "r"(a));
}
__device__ __forceinline__ void mma16816(float* c, const uint32_t* a, const uint32_t* b) {
    asm volatile(
        "mma.sync.aligned.m16n8k16.row.col.f32.f16.f16.f32 "
        "{%0,%1,%2,%3}, {%4,%5,%6,%7}, {%8,%9}, {%0,%1,%2,%3};"
        : "+f"(c[0]), "+f"(c[1]), "+f"(c[2]), "+f"(c[3])
        : "r"(a[0]), "r"(a[1]), "r"(a[2]), "r"(a[3]), "r"(b[0]), "r"(b[1]));
}

// ------------------------- convert / split helpers ---------------------------
__device__ __forceinline__ void hsplit2(float a, float b, __half2* H, __half2* L,
                                        size_t i) {
    __half ha = __float2half_rn(a), hb = __float2half_rn(b);
    H[i] = __halves2half2(ha, hb);
    L[i] = __halves2half2(__float2half_rn(a - __half2float(ha)),
                          __float2half_rn(b - __half2float(hb)));
}
__device__ __forceinline__ uint32_t pack2(float a, float b) {
    __half2 h2 = __floats2half2_rn(a, b);
    return *(uint32_t*)&h2;
}

// single-pass weight conversion for ALL weight tensors
__global__ void wconv_all(const float* __restrict__ Wq, const float* __restrict__ Wk,
                          const float* __restrict__ Wv, const float* __restrict__ Wo,
                          const float* __restrict__ W1, const float* __restrict__ W2,
                          const float* __restrict__ Wout, __half* __restrict__ wh) {
    size_t i = ((size_t)blockIdx.x * blockDim.x + threadIdx.x) * 8;  // half index
    if (i >= WTOT) return;
    const float* src;
    if (i < WOO) {
        size_t l   = i / (3u*DD*DD);
        size_t rem = i - l * (3u*DD*DD);
        size_t j   = rem / ((size_t)DD*DD);
        size_t off = rem - j * ((size_t)DD*DD);
        const float* W = (j == 0) ? Wq : (j == 1) ? Wk : Wv;
        src = W + l * (size_t)DD*DD + off;
    } else if (i < W1O) src = Wo   + (i - WOO);
    else if (i < W2O)   src = W1   + (i - W1O);
    else if (i < WUO)   src = W2   + (i - W2O);
    else                src = Wout + (i - WUO);
    float4 v0 = ((const float4*)src)[0];
    float4 v1 = ((const float4*)src)[1];
    uint4 out;
    out.x = pack2(v0.x, v0.y); out.y = pack2(v0.z, v0.w);
    out.z = pack2(v1.x, v1.y); out.w = pack2(v1.z, v1.w);
    *(uint4*)(wh + i) = out;
}

// ------------------------- embedding + positional encoding ------------------
__global__ void embed_kernel(const int* __restrict__ idx,
                             const float* __restrict__ emb,
                             float* __restrict__ x, __half* __restrict__ xa) {
    int t = blockIdx.x * blockDim.x + threadIdx.x;
    if (t >= BB*SS*(DD/2)) return;
    int dp = t & 511;
    int bs = t >> 9;
    int s  = bs & (SS - 1);
    int d  = dp << 1;
    double freq = exp((double)d * (-9.210340371976184 / 1024.0));
    double ang  = (double)s * freq;
    double sv, cv;
    sincos(ang, &sv, &cv);
    int tok = idx[bs];
    float2 e = ((const float2*)emb)[(size_t)tok * 512 + dp];
    float vx = e.x + (float)sv, vy = e.y + (float)cv;
    ((float2*)x)[t] = make_float2(vx, vy);
    ((__half2*)xa)[t] = __floats2half2_rn(vx, vy);
}

// ------------------------- mma.sync fp16 1-term GEMM -------------------------
// C[M,N] = A[M,K] * B[N,K]^T, A and B single fp16, fp32 accum.
// CTA tile 128x256, K-tile 32, 256 thr, 8 warps (64x64 warp tiles).
// OMODE: 0 = fp32 row-major out
//        1 = fused QKV (N=3072): q(*0.125)/v single fp16, k hi/lo, remap [B,H,S,DK]
//        2 = fp16 single row-major out (with optional relu)
#define LDSB   80            // smem row stride in bytes (40 fp16)
#define ATILE  (128*LDSB)    // 10240
#define BTILE  (256*LDSB)    // 20480
#define STAGEB (ATILE + BTILE)       // 30720
#define NSTAGE 3
#define GSMEM  (NSTAGE*STAGEB)       // 92160

template<int ACT, int OMODE>
__global__ __launch_bounds__(256)
void gemm_tc(const __half* __restrict__ Aq, const __half* __restrict__ Bq,
             float* __restrict__ C,
             __half* __restrict__ P0, __half* __restrict__ P1,
             __half* __restrict__ P2, __half* __restrict__ P3,
             int M, int N, int K)
{
    extern __shared__ __align__(16) char smem[];
    const uint32_t sb = s2u(smem);
    const int tid = threadIdx.x;
    const int wid = tid >> 5, lane = tid & 31;
    const int wm = wid & 1, wn = wid >> 1;
    const int row0 = blockIdx.y * 128, col0 = blockIdx.x * 256;

    const int chunk = tid & 3;
    const int rr    = tid >> 2;
    const int rA0 = row0 + rr, rA1 = rA0 + 64;
    int rB0 = col0 + rr;       if (rB0 > N - 1) rB0 = N - 1;
    int rB1 = col0 + rr + 64;  if (rB1 > N - 1) rB1 = N - 1;
    int rB2 = col0 + rr + 128; if (rB2 > N - 1) rB2 = N - 1;
    int rB3 = col0 + rr + 192; if (rB3 > N - 1) rB3 = N - 1;
    const uint32_t sA0 = (uint32_t)rr * LDSB + (uint32_t)chunk * 16;

    auto issue = [&](int kt, int buf) {
        const int ko = kt * 32 + chunk * 8;
        const uint32_t base = sb + (uint32_t)buf * STAGEB;
        cpa16(base + sA0,            Aq + (size_t)rA0 * K + ko);
        cpa16(base + sA0 + 64u*LDSB, Aq + (size_t)rA1 * K + ko);
        const uint32_t bb = base + ATILE;
        cpa16(bb + sA0,              Bq + (size_t)rB0 * K + ko);
        cpa16(bb + sA0 +  64u*LDSB,  Bq + (size_t)rB1 * K + ko);
        cpa16(bb + sA0 + 128u*LDSB,  Bq + (size_t)rB2 * K + ko);
        cpa16(bb + sA0 + 192u*LDSB,  Bq + (size_t)rB3 * K + ko);
        asm volatile("cp.async.commit_group;" ::: "memory");
    };

    float acc[4][8][4];
#pragma unroll
    for (int i = 0; i < 4; i++)
#pragma unroll
        for (int j = 0; j < 8; j++)
#pragma unroll
            for (int q = 0; q < 4; q++) acc[i][j][q] = 0.f;

    const int KT = K >> 5;
    issue(0, 0);
    issue(1, 1);
    issue(2, 2);

    const uint32_t aoff = (uint32_t)(wm*64 + (lane & 15)) * LDSB + ((lane >> 4) << 4);
    const uint32_t boff = (uint32_t)(wn*64 + (lane & 7) + ((lane >> 4) << 3)) * LDSB
                        + (((lane >> 3) & 1) << 4);

    int buf = 0;
#pragma unroll 1
    for (int kt = 0; kt < KT; kt++) {
        if (kt + 2 < KT)      asm volatile("cp.async.wait_group 2;" ::: "memory");
        else if (kt + 1 < KT) asm volatile("cp.async.wait_group 1;" ::: "memory");
        else                  asm volatile("cp.async.wait_group 0;" ::: "memory");
        __syncthreads();
        const uint32_t base = sb + (uint32_t)buf * STAGEB;
#pragma unroll
        for (int ks = 0; ks < 2; ks++) {
            const uint32_t ka = base + (uint32_t)ks * 32 + aoff;
            const uint32_t kb = base + ATILE + (uint32_t)ks * 32 + boff;
            uint32_t ah[4][4];
#pragma unroll
            for (int mt = 0; mt < 4; mt++)
                ldsm4(ah[mt], ka + (uint32_t)mt * (16*LDSB));
#pragma unroll
            for (int p = 0; p < 4; p++) {
                uint32_t b4[4];
                ldsm4(b4, kb + (uint32_t)p * (16*LDSB));
#pragma unroll
                for (int mt = 0; mt < 4; mt++) {
                    mma16816(acc[mt][2*p],   ah[mt], b4);
                    mma16816(acc[mt][2*p+1], ah[mt], b4 + 2);
                }
            }
        }
        __syncthreads();
        if (kt + 3 < KT) issue(kt + 3, buf);
        buf = (buf == 2) ? 0 : buf + 1;
    }

    const int base_m = row0 + wm*64;
    const int base_n = col0 + wn*64;
#pragma unroll
    for (int mt = 0; mt < 4; mt++) {
#pragma unroll
        for (int nt = 0; nt < 8; nt++) {
            float* c = acc[mt][nt];
            if (ACT == 1) {
                c[0] = fmaxf(c[0], 0.f); c[1] = fmaxf(c[1], 0.f);
                c[2] = fmaxf(c[2], 0.f); c[3] = fmaxf(c[3], 0.f);
            }
            const int r0 = base_m + mt*16 + (lane >> 2);
            const int cc = base_n + nt*8 + (lane & 3)*2;
            if (OMODE == 0) {
                if (cc < N) {
                    *(float2*)(C + (size_t)r0 * N + cc)       = make_float2(c[0], c[1]);
                    *(float2*)(C + (size_t)(r0 + 8) * N + cc) = make_float2(c[2], c[3]);
                }
            } else if (OMODE == 1) {
                // fused QKV: n in [0,3072)
                const int sect = cc >> 10;
                const int nc = cc & 1023;
                const int h = nc >> 6, kk = nc & (DK - 1);
                const int b0i = r0 >> 11, s0r = r0 & (SS - 1);
                const size_t i0 = (((size_t)(b0i*HH + h)*SS + s0r)*DK + kk) >> 1;
                const int r1 = r0 + 8;
                const int b1i = r1 >> 11, s1r = r1 & (SS - 1);
                const size_t i1 = (((size_t)(b1i*HH + h)*SS + s1r)*DK + kk) >> 1;
                if (sect == 0) {
                    // Q pre-scaled by 1/sqrt(DK) = 0.125
                    ((__half2*)P0)[i0] = __floats2half2_rn(c[0]*0.125f, c[1]*0.125f);
                    ((__half2*)P0)[i1] = __floats2half2_rn(c[2]*0.125f, c[3]*0.125f);
                } else if (sect == 1) {
                    hsplit2(c[0], c[1], (__half2*)P1, (__half2*)P2, i0);
                    hsplit2(c[2], c[3], (__half2*)P1, (__half2*)P2, i1);
                } else {
                    ((__half2*)P3)[i0] = __floats2half2_rn(c[0], c[1]);
                    ((__half2*)P3)[i1] = __floats2half2_rn(c[2], c[3]);
                }
            } else {
                if (cc < N) {
                    ((__half2*)P0)[((size_t)r0 * N + cc) >> 1]
                        = __floats2half2_rn(c[0], c[1]);
                    ((__half2*)P0)[((size_t)(r0 + 8) * N + cc) >> 1]
                        = __floats2half2_rn(c[2], c[3]);
                }
            }
        }
    }
}

// ------------------------- tensor-core flash attention ----------------------
// Q single fp16 (pre-scaled 1/8), K hi/lo fp16, V single fp16 in [B,H,S,DK].
// Causal. CTA = 128 q-rows, 8 warps (16 q-rows each). k-tile 64.
// 2-term QK^T (Q*(Kh+Kl)); 1-term PV. Output single fp16 [B,S,D].
#define FSTR   144                 // smem row stride bytes (64 fp16 + pad)
#define FQSZ   (128*FSTR)          // 18432
#define SKH    0
#define SKL    9216
#define SV     18432
#define FSTAGE 27648
#define FSMEM  (FQSZ + 2*FSTAGE)   // 73728

__global__ __launch_bounds__(256, 2)
void flash_tc(const __half* __restrict__ Qa,
              const __half* __restrict__ Kh, const __half* __restrict__ Kl,
              const __half* __restrict__ Va, __half* __restrict__ OA)
{
    extern __shared__ __align__(16) char smem[];
    const uint32_t sb = s2u(smem);
    const int bh  = blockIdx.y;
    const int qt  = gridDim.x - 1 - blockIdx.x;   // heavy blocks first
    const int tid = threadIdx.x, wid = tid >> 5, lane = tid & 31;
    const int q0  = qt * 128;
    const int ntiles = 2*qt + 2;

    // Q tile load: 128 rows x 8 chunks
    {
        const size_t g = ((size_t)bh * SS + q0) * DK;
#pragma unroll
        for (int c = tid; c < 1024; c += 256) {
            const int row = c >> 3, ch = c & 7;
            cpa16(sb + (uint32_t)row * FSTR + (uint32_t)ch * 16,
                  Qa + g + row * DK + ch * 8);
        }
        asm volatile("cp.async.commit_group;" ::: "memory");
    }

    auto loadkv = [&](int kt, int bufi) {
        const uint32_t base = sb + FQSZ + (uint32_t)bufi * FSTAGE;
        const size_t g = ((size_t)bh * SS + kt * 64) * DK;
#pragma unroll
        for (int c = tid; c < 512; c += 256) {
            const int row = c >> 3, ch = c & 7;
            const uint32_t so = (uint32_t)row * FSTR + (uint32_t)ch * 16;
            const size_t go = g + row * DK + ch * 8;
            cpa16(base + SKH + so, Kh + go);
            cpa16(base + SKL + so, Kl + go);
            cpa16(base + SV  + so, Va + go);
        }
        asm volatile("cp.async.commit_group;" ::: "memory");
    };

    loadkv(0, 0);
    loadkv(1, 1);

    asm volatile("cp.async.wait_group 1;" ::: "memory");
    __syncthreads();

    // Q fragments (16 rows per warp)
    uint32_t qf[4][4];
    {
        const uint32_t a0 = sb + (uint32_t)(wid*16 + (lane & 15)) * FSTR + ((lane >> 4) << 4);
#pragma unroll
        for (int kc = 0; kc < 4; kc++)
            ldsm4(qf[kc], a0 + kc*32);
    }

    float o[8][4];
#pragma unroll
    for (int i = 0; i < 8; i++)
#pragma unroll
        for (int j = 0; j < 4; j++) o[i][j] = 0.f;
    float mi0 = -1e30f, mi1 = -1e30f, li0 = 0.f, li1 = 0.f;

    const uint32_t kboff = (uint32_t)((lane & 7) + ((lane >> 4) << 3)) * FSTR
                         + (((lane >> 3) & 1) << 4);
    const uint32_t vboff = (uint32_t)((((lane >> 3) & 1) << 3) + (lane & 7)) * FSTR
                         + ((lane >> 4) << 4);

#pragma unroll 1
    for (int kt = 0; kt < ntiles; kt++) {
        const int bufi = kt & 1;
        if (kt > 0) {
            if (kt < ntiles - 1) asm volatile("cp.async.wait_group 1;" ::: "memory");
            else                 asm volatile("cp.async.wait_group 0;" ::: "memory");
            __syncthreads();
        }
        const uint32_t base = sb + FQSZ + (uint32_t)bufi * FSTAGE;

        // last diagonal tile: warps 0-3 (rows 0-63) fully masked -> skip body
        const bool skip = (kt == ntiles - 1) && (wid < 4);
        if (!skip) {
            // S = Q K^T (2-term: Q*(Kh+Kl)); Q pre-scaled
            float s[8][4];
#pragma unroll
            for (int i = 0; i < 8; i++)
#pragma unroll
                for (int j = 0; j < 4; j++) s[i][j] = 0.f;
#pragma unroll
            for (int kc = 0; kc < 4; kc++) {
#pragma unroll
                for (int np = 0; np < 4; np++) {
                    uint32_t kh4[4], kl4[4];
                    ldsm4(kh4, base + SKH + kboff + kc*32 + (uint32_t)np * (16*FSTR));
                    ldsm4(kl4, base + SKL + kboff + kc*32 + (uint32_t)np * (16*FSTR));
                    mma16816(s[2*np],   qf[kc], kh4);
                    mma16816(s[2*np],   qf[kc], kl4);
                    mma16816(s[2*np+1], qf[kc], kh4 + 2);
                    mma16816(s[2*np+1], qf[kc], kl4 + 2);
                }
            }

            // causal mask (last two k-tiles only)
            if (kt >= ntiles - 2) {
                const int rk = wid*16 + (lane >> 2) - (kt*64 - q0);
                const int cb = (lane & 3) * 2;
#pragma unroll
                for (int nt = 0; nt < 8; nt++) {
                    const int k0 = nt*8 + cb;
                    if (k0     > rk    ) s[nt][0] = -1e30f;
                    if (k0 + 1 > rk    ) s[nt][1] = -1e30f;
                    if (k0     > rk + 8) s[nt][2] = -1e30f;
                    if (k0 + 1 > rk + 8) s[nt][3] = -1e30f;
                }
            }

            // online softmax
            float m0 = -1e30f, m1 = -1e30f;
#pragma unroll
            for (int nt = 0; nt < 8; nt++) {
                m0 = fmaxf(m0, fmaxf(s[nt][0], s[nt][1]));
                m1 = fmaxf(m1, fmaxf(s[nt][2], s[nt][3]));
            }
            m0 = fmaxf(m0, __shfl_xor_sync(0xffffffffu, m0, 1));
            m0 = fmaxf(m0, __shfl_xor_sync(0xffffffffu, m0, 2));
            m1 = fmaxf(m1, __shfl_xor_sync(0xffffffffu, m1, 1));
            m1 = fmaxf(m1, __shfl_xor_sync(0xffffffffu, m1, 2));
            const float mn0 = fmaxf(mi0, m0), mn1 = fmaxf(mi1, m1);
            const float rs0 = __expf(mi0 - mn0), rs1 = __expf(mi1 - mn1);
            mi0 = mn0; mi1 = mn1;
            li0 *= rs0; li1 *= rs1;
#pragma unroll
            for (int nt = 0; nt < 8; nt++) {
                o[nt][0] *= rs0; o[nt][1] *= rs0;
                o[nt][2] *= rs1; o[nt][3] *= rs1;
            }
            float ls0 = 0.f, ls1 = 0.f;
#pragma unroll
            for (int nt = 0; nt < 8; nt++) {
                s[nt][0] = __expf(s[nt][0] - mn0);
                s[nt][1] = __expf(s[nt][1] - mn0);
                s[nt][2] = __expf(s[nt][2] - mn1);
                s[nt][3] = __expf(s[nt][3] - mn1);
                ls0 += s[nt][0] + s[nt][1];
                ls1 += s[nt][2] + s[nt][3];
            }
            li0 += ls0; li1 += ls1;

            // O += P V (1-term, P single fp16)
#pragma unroll
            for (int kc = 0; kc < 4; kc++) {
                uint32_t pa[4];
                pa[0] = pack2(s[2*kc][0],   s[2*kc][1]);
                pa[1] = pack2(s[2*kc][2],   s[2*kc][3]);
                pa[2] = pack2(s[2*kc+1][0], s[2*kc+1][1]);
                pa[3] = pack2(s[2*kc+1][2], s[2*kc+1][3]);
#pragma unroll
                for (int np = 0; np < 4; np++) {
                    uint32_t vh4[4];
                    ldsm4t(vh4, base + SV + vboff + (uint32_t)kc * (16*FSTR) + np*32);
                    mma16816(o[2*np],   pa, vh4);
                    mma16816(o[2*np+1], pa, vh4 + 2);
                }
            }
        }

        __syncthreads();
        if (kt + 2 < ntiles) loadkv(kt + 2, bufi);
    }

    // final row sums + write O single fp16 [B,S,D]
    li0 += __shfl_xor_sync(0xffffffffu, li0, 1);
    li0 += __shfl_xor_sync(0xffffffffu, li0, 2);
    li1 += __shfl_xor_sync(0xffffffffu, li1, 1);
    li1 += __shfl_xor_sync(0xffffffffu, li1, 2);
    const float inv0 = 1.f / li0, inv1 = 1.f / li1;
    const int b = bh >> 4, h = bh & (HH - 1);
    const int qr = q0 + wid*16 + (lane >> 2);
    const size_t rowA = ((size_t)(b*SS + qr)) * DD + h * DK;
    const size_t rowB = rowA + 8 * DD;
    __half2* OA2 = (__half2*)OA;
#pragma unroll
    for (int nt = 0; nt < 8; nt++) {
        const int dk = nt*8 + (lane & 3)*2;
        OA2[(rowA + dk) >> 1] = __floats2half2_rn(o[nt][0]*inv0, o[nt][1]*inv0);
        OA2[(rowB + dk) >> 1] = __floats2half2_rn(o[nt][2]*inv1, o[nt][3]*inv1);
    }
}

// ------------------------- residual add + layernorm + fp16 out --------------
__global__ __launch_bounds__(128)
void add_ln_kernel(float* __restrict__ x, const float* __restrict__ r,
                   const float* __restrict__ w, const float* __restrict__ bias,
                   __half* __restrict__ xa) {
    __shared__ float sh[4];
    const int row = blockIdx.x;
    const int tid = threadIdx.x;
    float4* xr = (float4*)(x + (size_t)row * DD);
    const float4* rr = (const float4*)(r + (size_t)row * DD);
    float4 v0 = xr[tid], v1 = xr[tid + 128];
    float4 a0 = rr[tid], a1 = rr[tid + 128];
    v0.x += a0.x; v0.y += a0.y; v0.z += a0.z; v0.w += a0.w;
    v1.x += a1.x; v1.y += a1.y; v1.z += a1.z; v1.w += a1.w;

    float s = v0.x+v0.y+v0.z+v0.w + v1.x+v1.y+v1.z+v1.w;
#pragma unroll
    for (int o = 16; o > 0; o >>= 1) s += __shfl_down_sync(0xffffffffu, s, o);
    if ((tid & 31) == 0) sh[tid >> 5] = s;
    __syncthreads();
    float mean = (sh[0]+sh[1]+sh[2]+sh[3]) * (1.f/DD);
    __syncthreads();

    float dx0 = v0.x-mean, dx1 = v0.y-mean, dx2 = v0.z-mean, dx3 = v0.w-mean;
    float dy0 = v1.x-mean, dy1 = v1.y-mean, dy2 = v1.z-mean, dy3 = v1.w-mean;
    float sq = dx0*dx0+dx1*dx1+dx2*dx2+dx3*dx3 + dy0*dy0+dy1*dy1+dy2*dy2+dy3*dy3;
#pragma unroll
    for (int o = 16; o > 0; o >>= 1) sq += __shfl_down_sync(0xffffffffu, sq, o);
    if ((tid & 31) == 0) sh[tid >> 5] = sq;
    __syncthreads();
    float var = (sh[0]+sh[1]+sh[2]+sh[3]) * (1.f/DD);
    float rs = rsqrtf(var + 1e-5f);

    float4 w0 = ((const float4*)w)[tid],     w1 = ((const float4*)w)[tid + 128];
    float4 b0 = ((const float4*)bias)[tid],  b1 = ((const float4*)bias)[tid + 128];
    float4 o0 = make_float4(dx0*rs*w0.x+b0.x, dx1*rs*w0.y+b0.y,
                            dx2*rs*w0.z+b0.z, dx3*rs*w0.w+b0.w);
    float4 o1 = make_float4(dy0*rs*w1.x+b1.x, dy1*rs*w1.y+b1.y,
                            dy2*rs*w1.z+b1.z, dy3*rs*w1.w+b1.w);
    xr[tid]       = o0;
    xr[tid + 128] = o1;

    __half2* H = (__half2*)(xa + (size_t)row * DD);
    H[tid*2]         = __floats2half2_rn(o0.x, o0.y);
    H[tid*2 + 1]     = __floats2half2_rn(o0.z, o0.w);
    H[(tid+128)*2]   = __floats2half2_rn(o1.x, o1.y);
    H[(tid+128)*2+1] = __floats2half2_rn(o1.z, o1.w);
}

// ------------------------- launch ------------------------------------------
extern "C" void kernel_launch(void* const* d_in, const int* in_sizes, int n_in,
                              void* d_out, int out_size) {
    (void)in_sizes; (void)n_in; (void)out_size;
    const int*   idx  = (const int*)  d_in[0];
    const float* emb  = (const float*)d_in[1];
    const float* Wq   = (const float*)d_in[2];
    const float* Wk   = (const float*)d_in[3];
    const float* Wv   = (const float*)d_in[4];
    const float* Wo   = (const float*)d_in[5];
    const float* ln1w = (const float*)d_in[6];
    const float* ln1b = (const float*)d_in[7];
    const float* W1   = (const float*)d_in[8];
    const float* W2   = (const float*)d_in[9];
    const float* ln2w = (const float*)d_in[10];
    const float* ln2b = (const float*)d_in[11];
    const float* Wout = (const float*)d_in[12];

    float *x, *t;
    __half *wh, *xa, *oa, *fa, *qa, *kh, *kl, *va;
    cudaGetSymbolAddress((void**)&x, g_x);
    cudaGetSymbolAddress((void**)&t, g_t);
    cudaGetSymbolAddress((void**)&wh, g_wh);
    cudaGetSymbolAddress((void**)&xa, g_xa);
    cudaGetSymbolAddress((void**)&oa, g_oa);
    cudaGetSymbolAddress((void**)&fa, g_fa);
    cudaGetSymbolAddress((void**)&qa, g_qa);
    cudaGetSymbolAddress((void**)&kh, g_kh);
    cudaGetSymbolAddress((void**)&kl, g_kl);
    cudaGetSymbolAddress((void**)&va, g_va);

    cudaFuncSetAttribute(gemm_tc<0,0>, cudaFuncAttributeMaxDynamicSharedMemorySize, GSMEM);
    cudaFuncSetAttribute(gemm_tc<0,1>, cudaFuncAttributeMaxDynamicSharedMemorySize, GSMEM);
    cudaFuncSetAttribute(gemm_tc<1,2>, cudaFuncAttributeMaxDynamicSharedMemorySize, GSMEM);
    cudaFuncSetAttribute(flash_tc, cudaFuncAttributeMaxDynamicSharedMemorySize, FSMEM);

    // weight conversion: single pass over all tensors
    {
        const int nthreads = (int)(WTOT / 8);
        wconv_all<<<(nthreads + 255)/256, 256>>>(Wq, Wk, Wv, Wo, W1, W2, Wout, wh);
    }

    embed_kernel<<<(BB*SS*(DD/2) + 255) / 256, 256>>>(idx, emb, x, xa);

    for (int l = 0; l < LL; l++) {
        const size_t wqkv = WQKV + (size_t)l * 3*DD*DD;
        const size_t ws   = (size_t)l * DD * DD;
        const size_t wf   = (size_t)l * DFF * DD;
        // fused QKV (N = 3072)
        gemm_tc<0,1><<<dim3(12, 32), 256, GSMEM>>>(xa, wh+wqkv,
                                                   nullptr, qa, kh, kl, va,
                                                   MM, 3*DD, DD);
        flash_tc<<<dim3(SS/128, BB*HH), 256, FSMEM>>>(qa, kh, kl, va, oa);
        gemm_tc<0,0><<<dim3(4, 32), 256, GSMEM>>>(oa, wh+WOO+ws,
                                                  t, nullptr, nullptr, nullptr, nullptr,
                                                  MM, DD, DD);
        add_ln_kernel<<<MM, 128>>>(x, t, ln1w + l*DD, ln1b + l*DD, xa);
        gemm_tc<1,2><<<dim3(16, 32), 256, GSMEM>>>(xa, wh+W1O+wf,
                                                   nullptr, fa, nullptr, nullptr, nullptr,
                                                   MM, DFF, DD);
        gemm_tc<0,0><<<dim3(4, 32), 256, GSMEM>>>(fa, wh+W2O+wf,
                                                  t, nullptr, nullptr, nullptr, nullptr,
                                                  MM, DD, DFF);
        add_ln_kernel<<<MM, 128>>>(x, t, ln2w + l*DD, ln2b + l*DD, xa);
    }
    gemm_tc<0,0><<<dim3(8, 32), 256, GSMEM>>>(xa, wh+WUO,
                                              (float*)d_out, nullptr, nullptr, nullptr,
                                              nullptr, MM, VV, DD);
}

// round 14
// speedup vs baseline: 6.8071x; 1.0498x over previous
#include <cuda_runtime.h>
#include <cuda_fp16.h>
#include <math.h>
#include <stdint.h>

// Problem constants
#define BB   2
#define SS   2048
#define DD   1024
#define HH   16
#define LL   4
#define VV   2000
#define DK   64
#define DFF  4096
#define MM   (BB*SS)          // 4096 rows

// ------------------------- scratch (static device memory) -------------------
__device__ float g_x[MM*DD];      // activations [B*S, D] fp32 (residual path)
__device__ float g_t[MM*DD];      // temp (pre-LN residual branch)

// single-fp16 weights
#define WQKV 0u                    // [L][Wq;Wk;Wv] each 1024x1024
#define WOO  12582912u
#define W1O  16777216u
#define W2O  33554432u
#define WUO  50331648u
#define WTOT 52379648u
__device__ __half g_wh[WTOT];
// single-fp16 activations
__device__ __half g_xa[MM*DD];     // LN output
__device__ __half g_oa[MM*DD];     // attention out [B,S,D]
__device__ __half g_fa[MM*DFF];    // FFN hidden (post-relu)
__device__ __half g_qa[MM*DD];     // [B,H,S,DK] (pre-scaled by 1/8)
__device__ __half g_ka[MM*DD];
__device__ __half g_va[MM*DD];

// ------------------------- PTX helpers --------------------------------------
__device__ __forceinline__ uint32_t s2u(const void* p) {
    uint32_t a;
    asm("{ .reg .u64 t; cvta.to.shared.u64 t, %1; cvt.u32.u64 %0, t; }"
        : "=r"(a) : "l"(p));
    return a;
}
__device__ __forceinline__ void cpa16(uint32_t s, const void* g) {
    asm volatile("cp.async.cg.shared.global [%0], [%1], 16;" :: "r"(s), "l"(g));
}
__device__ __forceinline__ void ldsm4(uint32_t* r, uint32_t a) {
    asm volatile("ldmatrix.sync.aligned.m8n8.x4.shared.b16 {%0,%1,%2,%3}, [%4];"
                 : "=r"(r[0]), "=r"(r[1]), "=r"(r[2]), "=r"(r[3]) : "r"(a));
}
__device__ __forceinline__ void ldsm4t(uint32_t* r, uint32_t a) {
    asm volatile("ldmatrix.sync.aligned.m8n8.x4.trans.shared.b16 {%0,%1,%2,%3}, [%4];"
                 : "=r"(r[0]), "=r"(r[1]), "=r"(r[2]), "=r"(r[3]) : "r"(a));
}
__device__ __forceinline__ void mma16816(float* c, const uint32_t* a, const uint32_t* b) {
    asm volatile(
        "mma.sync.aligned.m16n8k16.row.col.f32.f16.f16.f32 "
        "{%0,%1,%2,%3}, {%4,%5,%6,%7}, {%8,%9}, {%0,%1,%2,%3};"
        : "+f"(c[0]), "+f"(c[1]), "+f"(c[2]), "+f"(c[3])
        : "r"(a[0]), "r"(a[1]), "r"(a[2]), "r"(a[3]), "r"(b[0]), "r"(b[1]));
}

// ------------------------- convert helpers -----------------------------------
__device__ __forceinline__ uint32_t pack2(float a, float b) {
    __half2 h2 = __floats2half2_rn(a, b);
    return *(uint32_t*)&h2;
}

// single-pass weight conversion for ALL weight tensors
__global__ void wconv_all(const float* __restrict__ Wq, const float* __restrict__ Wk,
                          const float* __restrict__ Wv, const float* __restrict__ Wo,
                          const float* __restrict__ W1, const float* __restrict__ W2,
                          const float* __restrict__ Wout, __half* __restrict__ wh) {
    size_t i = ((size_t)blockIdx.x * blockDim.x + threadIdx.x) * 8;  // half index
    if (i >= WTOT) return;
    const float* src;
    if (i < WOO) {
        size_t l   = i / (3u*DD*DD);
        size_t rem = i - l * (3u*DD*DD);
        size_t j   = rem / ((size_t)DD*DD);
        size_t off = rem - j * ((size_t)DD*DD);
        const float* W = (j == 0) ? Wq : (j == 1) ? Wk : Wv;
        src = W + l * (size_t)DD*DD + off;
    } else if (i < W1O) src = Wo   + (i - WOO);
    else if (i < W2O)   src = W1   + (i - W1O);
    else if (i < WUO)   src = W2   + (i - W2O);
    else                src = Wout + (i - WUO);
    float4 v0 = ((const float4*)src)[0];
    float4 v1 = ((const float4*)src)[1];
    uint4 out;
    out.x = pack2(v0.x, v0.y); out.y = pack2(v0.z, v0.w);
    out.z = pack2(v1.x, v1.y); out.w = pack2(v1.z, v1.w);
    *(uint4*)(wh + i) = out;
}

// ------------------------- embedding + positional encoding ------------------
__global__ void embed_kernel(const int* __restrict__ idx,
                             const float* __restrict__ emb,
                             float* __restrict__ x, __half* __restrict__ xa) {
    int t = blockIdx.x * blockDim.x + threadIdx.x;
    if (t >= BB*SS*(DD/2)) return;
    int dp = t & 511;
    int bs = t >> 9;
    int s  = bs & (SS - 1);
    int d  = dp << 1;
    double freq = exp((double)d * (-9.210340371976184 / 1024.0));
    double ang  = (double)s * freq;
    double sv, cv;
    sincos(ang, &sv, &cv);
    int tok = idx[bs];
    float2 e = ((const float2*)emb)[(size_t)tok * 512 + dp];
    float vx = e.x + (float)sv, vy = e.y + (float)cv;
    ((float2*)x)[t] = make_float2(vx, vy);
    ((__half2*)xa)[t] = __floats2half2_rn(vx, vy);
}

// ------------------------- mma.sync fp16 1-term GEMM -------------------------
// C[M,N] = A[M,K] * B[N,K]^T, A and B single fp16, fp32 accum.
// CTA tile 128x256, K-tile 32, 256 thr, 8 warps (64x64 warp tiles).
// OMODE: 0 = fp32 row-major out
//        1 = fused QKV (N=3072): q(*0.125)/k/v single fp16, remap [B,H,S,DK]
//        2 = fp16 single row-major out (with optional relu)
#define LDSB   80            // smem row stride in bytes (40 fp16)
#define ATILE  (128*LDSB)    // 10240
#define BTILE  (256*LDSB)    // 20480
#define STAGEB (ATILE + BTILE)       // 30720
#define NSTAGE 3
#define GSMEM  (NSTAGE*STAGEB)       // 92160

template<int ACT, int OMODE>
__global__ __launch_bounds__(256)
void gemm_tc(const __half* __restrict__ Aq, const __half* __restrict__ Bq,
             float* __restrict__ C,
             __half* __restrict__ P0, __half* __restrict__ P1,
             __half* __restrict__ P2,
             int M, int N, int K)
{
    extern __shared__ __align__(16) char smem[];
    const uint32_t sb = s2u(smem);
    const int tid = threadIdx.x;
    const int wid = tid >> 5, lane = tid & 31;
    const int wm = wid & 1, wn = wid >> 1;
    const int row0 = blockIdx.y * 128, col0 = blockIdx.x * 256;

    const int chunk = tid & 3;
    const int rr    = tid >> 2;
    const int rA0 = row0 + rr, rA1 = rA0 + 64;
    int rB0 = col0 + rr;       if (rB0 > N - 1) rB0 = N - 1;
    int rB1 = col0 + rr + 64;  if (rB1 > N - 1) rB1 = N - 1;
    int rB2 = col0 + rr + 128; if (rB2 > N - 1) rB2 = N - 1;
    int rB3 = col0 + rr + 192; if (rB3 > N - 1) rB3 = N - 1;
    const uint32_t sA0 = (uint32_t)rr * LDSB + (uint32_t)chunk * 16;

    auto issue = [&](int kt, int buf) {
        const int ko = kt * 32 + chunk * 8;
        const uint32_t base = sb + (uint32_t)buf * STAGEB;
        cpa16(base + sA0,            Aq + (size_t)rA0 * K + ko);
        cpa16(base + sA0 + 64u*LDSB, Aq + (size_t)rA1 * K + ko);
        const uint32_t bb = base + ATILE;
        cpa16(bb + sA0,              Bq + (size_t)rB0 * K + ko);
        cpa16(bb + sA0 +  64u*LDSB,  Bq + (size_t)rB1 * K + ko);
        cpa16(bb + sA0 + 128u*LDSB,  Bq + (size_t)rB2 * K + ko);
        cpa16(bb + sA0 + 192u*LDSB,  Bq + (size_t)rB3 * K + ko);
        asm volatile("cp.async.commit_group;" ::: "memory");
    };

    float acc[4][8][4];
#pragma unroll
    for (int i = 0; i < 4; i++)
#pragma unroll
        for (int j = 0; j < 8; j++)
#pragma unroll
            for (int q = 0; q < 4; q++) acc[i][j][q] = 0.f;

    const int KT = K >> 5;
    issue(0, 0);
    issue(1, 1);
    issue(2, 2);

    const uint32_t aoff = (uint32_t)(wm*64 + (lane & 15)) * LDSB + ((lane >> 4) << 4);
    const uint32_t boff = (uint32_t)(wn*64 + (lane & 7) + ((lane >> 4) << 3)) * LDSB
                        + (((lane >> 3) & 1) << 4);

    int buf = 0;
#pragma unroll 1
    for (int kt = 0; kt < KT; kt++) {
        if (kt + 2 < KT)      asm volatile("cp.async.wait_group 2;" ::: "memory");
        else if (kt + 1 < KT) asm volatile("cp.async.wait_group 1;" ::: "memory");
        else                  asm volatile("cp.async.wait_group 0;" ::: "memory");
        __syncthreads();
        const uint32_t base = sb + (uint32_t)buf * STAGEB;
#pragma unroll
        for (int ks = 0; ks < 2; ks++) {
            const uint32_t ka = base + (uint32_t)ks * 32 + aoff;
            const uint32_t kb = base + ATILE + (uint32_t)ks * 32 + boff;
            uint32_t ah[4][4];
#pragma unroll
            for (int mt = 0; mt < 4; mt++)
                ldsm4(ah[mt], ka + (uint32_t)mt * (16*LDSB));
#pragma unroll
            for (int p = 0; p < 4; p++) {
                uint32_t b4[4];
                ldsm4(b4, kb + (uint32_t)p * (16*LDSB));
#pragma unroll
                for (int mt = 0; mt < 4; mt++) {
                    mma16816(acc[mt][2*p],   ah[mt], b4);
                    mma16816(acc[mt][2*p+1], ah[mt], b4 + 2);
                }
            }
        }
        __syncthreads();
        if (kt + 3 < KT) issue(kt + 3, buf);
        buf = (buf == 2) ? 0 : buf + 1;
    }

    const int base_m = row0 + wm*64;
    const int base_n = col0 + wn*64;
#pragma unroll
    for (int mt = 0; mt < 4; mt++) {
#pragma unroll
        for (int nt = 0; nt < 8; nt++) {
            float* c = acc[mt][nt];
            if (ACT == 1) {
                c[0] = fmaxf(c[0], 0.f); c[1] = fmaxf(c[1], 0.f);
                c[2] = fmaxf(c[2], 0.f); c[3] = fmaxf(c[3], 0.f);
            }
            const int r0 = base_m + mt*16 + (lane >> 2);
            const int cc = base_n + nt*8 + (lane & 3)*2;
            if (OMODE == 0) {
                if (cc < N) {
                    *(float2*)(C + (size_t)r0 * N + cc)       = make_float2(c[0], c[1]);
                    *(float2*)(C + (size_t)(r0 + 8) * N + cc) = make_float2(c[2], c[3]);
                }
            } else if (OMODE == 1) {
                // fused QKV: n in [0,3072)
                const int sect = cc >> 10;
                const int nc = cc & 1023;
                const int h = nc >> 6, kk = nc & (DK - 1);
                const int b0i = r0 >> 11, s0r = r0 & (SS - 1);
                const size_t i0 = (((size_t)(b0i*HH + h)*SS + s0r)*DK + kk) >> 1;
                const int r1 = r0 + 8;
                const int b1i = r1 >> 11, s1r = r1 & (SS - 1);
                const size_t i1 = (((size_t)(b1i*HH + h)*SS + s1r)*DK + kk) >> 1;
                __half2* dst = (__half2*)((sect == 0) ? P0 : (sect == 1) ? P1 : P2);
                const float sc = (sect == 0) ? 0.125f : 1.f;  // Q pre-scaled 1/sqrt(DK)
                dst[i0] = __floats2half2_rn(c[0]*sc, c[1]*sc);
                dst[i1] = __floats2half2_rn(c[2]*sc, c[3]*sc);
            } else {
                if (cc < N) {
                    ((__half2*)P0)[((size_t)r0 * N + cc) >> 1]
                        = __floats2half2_rn(c[0], c[1]);
                    ((__half2*)P0)[((size_t)(r0 + 8) * N + cc) >> 1]
                        = __floats2half2_rn(c[2], c[3]);
                }
            }
        }
    }
}

// ------------------------- tensor-core flash attention ----------------------
// Q single fp16 (pre-scaled 1/8), K single fp16, V single fp16 in [B,H,S,DK].
// Causal. CTA = 128 q-rows, 8 warps (16 q-rows each). k-tile 64.
// 1-term QK^T; 1-term PV. Output single fp16 [B,S,D].
#define FSTR   144                 // smem row stride bytes (64 fp16 + pad)
#define FQSZ   (128*FSTR)          // 18432
#define SKH    0
#define SV     9216
#define FSTAGE 18432
#define FSMEM  (FQSZ + 2*FSTAGE)   // 55296

__global__ __launch_bounds__(256, 2)
void flash_tc(const __half* __restrict__ Qa, const __half* __restrict__ Ka,
              const __half* __restrict__ Va, __half* __restrict__ OA)
{
    extern __shared__ __align__(16) char smem[];
    const uint32_t sb = s2u(smem);
    const int bh  = blockIdx.y;
    const int qt  = gridDim.x - 1 - blockIdx.x;   // heavy blocks first
    const int tid = threadIdx.x, wid = tid >> 5, lane = tid & 31;
    const int q0  = qt * 128;
    const int ntiles = 2*qt + 2;

    // Q tile load: 128 rows x 8 chunks
    {
        const size_t g = ((size_t)bh * SS + q0) * DK;
#pragma unroll
        for (int c = tid; c < 1024; c += 256) {
            const int row = c >> 3, ch = c & 7;
            cpa16(sb + (uint32_t)row * FSTR + (uint32_t)ch * 16,
                  Qa + g + row * DK + ch * 8);
        }
        asm volatile("cp.async.commit_group;" ::: "memory");
    }

    auto loadkv = [&](int kt, int bufi) {
        const uint32_t base = sb + FQSZ + (uint32_t)bufi * FSTAGE;
        const size_t g = ((size_t)bh * SS + kt * 64) * DK;
#pragma unroll
        for (int c = tid; c < 512; c += 256) {
            const int row = c >> 3, ch = c & 7;
            const uint32_t so = (uint32_t)row * FSTR + (uint32_t)ch * 16;
            const size_t go = g + row * DK + ch * 8;
            cpa16(base + SKH + so, Ka + go);
            cpa16(base + SV  + so, Va + go);
        }
        asm volatile("cp.async.commit_group;" ::: "memory");
    };

    loadkv(0, 0);
    loadkv(1, 1);

    asm volatile("cp.async.wait_group 1;" ::: "memory");
    __syncthreads();

    // Q fragments (16 rows per warp)
    uint32_t qf[4][4];
    {
        const uint32_t a0 = sb + (uint32_t)(wid*16 + (lane & 15)) * FSTR + ((lane >> 4) << 4);
#pragma unroll
        for (int kc = 0; kc < 4; kc++)
            ldsm4(qf[kc], a0 + kc*32);
    }

    float o[8][4];
#pragma unroll
    for (int i = 0; i < 8; i++)
#pragma unroll
        for (int j = 0; j < 4; j++) o[i][j] = 0.f;
    float mi0 = -1e30f, mi1 = -1e30f, li0 = 0.f, li1 = 0.f;

    const uint32_t kboff = (uint32_t)((lane & 7) + ((lane >> 4) << 3)) * FSTR
                         + (((lane >> 3) & 1) << 4);
    const uint32_t vboff = (uint32_t)((((lane >> 3) & 1) << 3) + (lane & 7)) * FSTR
                         + ((lane >> 4) << 4);

#pragma unroll 1
    for (int kt = 0; kt < ntiles; kt++) {
        const int bufi = kt & 1;
        if (kt > 0) {
            if (kt < ntiles - 1) asm volatile("cp.async.wait_group 1;" ::: "memory");
            else                 asm volatile("cp.async.wait_group 0;" ::: "memory");
            __syncthreads();
        }
        const uint32_t base = sb + FQSZ + (uint32_t)bufi * FSTAGE;

        // last diagonal tile: warps 0-3 (rows 0-63) fully masked -> skip body
        const bool skip = (kt == ntiles - 1) && (wid < 4);
        if (!skip) {
            // S = Q K^T (1-term); Q pre-scaled
            float s[8][4];
#pragma unroll
            for (int i = 0; i < 8; i++)
#pragma unroll
                for (int j = 0; j < 4; j++) s[i][j] = 0.f;
#pragma unroll
            for (int kc = 0; kc < 4; kc++) {
#pragma unroll
                for (int np = 0; np < 4; np++) {
                    uint32_t kh4[4];
                    ldsm4(kh4, base + SKH + kboff + kc*32 + (uint32_t)np * (16*FSTR));
                    mma16816(s[2*np],   qf[kc], kh4);
                    mma16816(s[2*np+1], qf[kc], kh4 + 2);
                }
            }

            // causal mask (last two k-tiles only)
            if (kt >= ntiles - 2) {
                const int rk = wid*16 + (lane >> 2) - (kt*64 - q0);
                const int cb = (lane & 3) * 2;
#pragma unroll
                for (int nt = 0; nt < 8; nt++) {
                    const int k0 = nt*8 + cb;
                    if (k0     > rk    ) s[nt][0] = -1e30f;
                    if (k0 + 1 > rk    ) s[nt][1] = -1e30f;
                    if (k0     > rk + 8) s[nt][2] = -1e30f;
                    if (k0 + 1 > rk + 8) s[nt][3] = -1e30f;
                }
            }

            // online softmax
            float m0 = -1e30f, m1 = -1e30f;
#pragma unroll
            for (int nt = 0; nt < 8; nt++) {
                m0 = fmaxf(m0, fmaxf(s[nt][0], s[nt][1]));
                m1 = fmaxf(m1, fmaxf(s[nt][2], s[nt][3]));
            }
            m0 = fmaxf(m0, __shfl_xor_sync(0xffffffffu, m0, 1));
            m0 = fmaxf(m0, __shfl_xor_sync(0xffffffffu, m0, 2));
            m1 = fmaxf(m1, __shfl_xor_sync(0xffffffffu, m1, 1));
            m1 = fmaxf(m1, __shfl_xor_sync(0xffffffffu, m1, 2));
            const float mn0 = fmaxf(mi0, m0), mn1 = fmaxf(mi1, m1);
            const float rs0 = __expf(mi0 - mn0), rs1 = __expf(mi1 - mn1);
            mi0 = mn0; mi1 = mn1;
            li0 *= rs0; li1 *= rs1;
#pragma unroll
            for (int nt = 0; nt < 8; nt++) {
                o[nt][0] *= rs0; o[nt][1] *= rs0;
                o[nt][2] *= rs1; o[nt][3] *= rs1;
            }
            float ls0 = 0.f, ls1 = 0.f;
#pragma unroll
            for (int nt = 0; nt < 8; nt++) {
                s[nt][0] = __expf(s[nt][0] - mn0);
                s[nt][1] = __expf(s[nt][1] - mn0);
                s[nt][2] = __expf(s[nt][2] - mn1);
                s[nt][3] = __expf(s[nt][3] - mn1);
                ls0 += s[nt][0] + s[nt][1];
                ls1 += s[nt][2] + s[nt][3];
            }
            li0 += ls0; li1 += ls1;

            // O += P V (1-term, P single fp16)
#pragma unroll
            for (int kc = 0; kc < 4; kc++) {
                uint32_t pa[4];
                pa[0] = pack2(s[2*kc][0],   s[2*kc][1]);
                pa[1] = pack2(s[2*kc][2],   s[2*kc][3]);
                pa[2] = pack2(s[2*kc+1][0], s[2*kc+1][1]);
                pa[3] = pack2(s[2*kc+1][2], s[2*kc+1][3]);
#pragma unroll
                for (int np = 0; np < 4; np++) {
                    uint32_t vh4[4];
                    ldsm4t(vh4, base + SV + vboff + (uint32_t)kc * (16*FSTR) + np*32);
                    mma16816(o[2*np],   pa, vh4);
                    mma16816(o[2*np+1], pa, vh4 + 2);
                }
            }
        }

        __syncthreads();
        if (kt + 2 < ntiles) loadkv(kt + 2, bufi);
    }

    // final row sums + write O single fp16 [B,S,D]
    li0 += __shfl_xor_sync(0xffffffffu, li0, 1);
    li0 += __shfl_xor_sync(0xffffffffu, li0, 2);
    li1 += __shfl_xor_sync(0xffffffffu, li1, 1);
    li1 += __shfl_xor_sync(0xffffffffu, li1, 2);
    const float inv0 = 1.f / li0, inv1 = 1.f / li1;
    const int b = bh >> 4, h = bh & (HH - 1);
    const int qr = q0 + wid*16 + (lane >> 2);
    const size_t rowA = ((size_t)(b*SS + qr)) * DD + h * DK;
    const size_t rowB = rowA + 8 * DD;
    __half2* OA2 = (__half2*)OA;
#pragma unroll
    for (int nt = 0; nt < 8; nt++) {
        const int dk = nt*8 + (lane & 3)*2;
        OA2[(rowA + dk) >> 1] = __floats2half2_rn(o[nt][0]*inv0, o[nt][1]*inv0);
        OA2[(rowB + dk) >> 1] = __floats2half2_rn(o[nt][2]*inv1, o[nt][3]*inv1);
    }
}

// ------------------------- residual add + layernorm + fp16 out --------------
__global__ __launch_bounds__(128)
void add_ln_kernel(float* __restrict__ x, const float* __restrict__ r,
                   const float* __restrict__ w, const float* __restrict__ bias,
                   __half* __restrict__ xa) {
    __shared__ float sh[4];
    const int row = blockIdx.x;
    const int tid = threadIdx.x;
    float4* xr = (float4*)(x + (size_t)row * DD);
    const float4* rr = (const float4*)(r + (size_t)row * DD);
    float4 v0 = xr[tid], v1 = xr[tid + 128];
    float4 a0 = rr[tid], a1 = rr[tid + 128];
    v0.x += a0.x; v0.y += a0.y; v0.z += a0.z; v0.w += a0.w;
    v1.x += a1.x; v1.y += a1.y; v1.z += a1.z; v1.w += a1.w;

    float s = v0.x+v0.y+v0.z+v0.w + v1.x+v1.y+v1.z+v1.w;
#pragma unroll
    for (int o = 16; o > 0; o >>= 1) s += __shfl_down_sync(0xffffffffu, s, o);
    if ((tid & 31) == 0) sh[tid >> 5] = s;
    __syncthreads();
    float mean = (sh[0]+sh[1]+sh[2]+sh[3]) * (1.f/DD);
    __syncthreads();

    float dx0 = v0.x-mean, dx1 = v0.y-mean, dx2 = v0.z-mean, dx3 = v0.w-mean;
    float dy0 = v1.x-mean, dy1 = v1.y-mean, dy2 = v1.z-mean, dy3 = v1.w-mean;
    float sq = dx0*dx0+dx1*dx1+dx2*dx2+dx3*dx3 + dy0*dy0+dy1*dy1+dy2*dy2+dy3*dy3;
#pragma unroll
    for (int o = 16; o > 0; o >>= 1) sq += __shfl_down_sync(0xffffffffu, sq, o);
    if ((tid & 31) == 0) sh[tid >> 5] = sq;
    __syncthreads();
    float var = (sh[0]+sh[1]+sh[2]+sh[3]) * (1.f/DD);
    float rs = rsqrtf(var + 1e-5f);

    float4 w0 = ((const float4*)w)[tid],     w1 = ((const float4*)w)[tid + 128];
    float4 b0 = ((const float4*)bias)[tid],  b1 = ((const float4*)bias)[tid + 128];
    float4 o0 = make_float4(dx0*rs*w0.x+b0.x, dx1*rs*w0.y+b0.y,
                            dx2*rs*w0.z+b0.z, dx3*rs*w0.w+b0.w);
    float4 o1 = make_float4(dy0*rs*w1.x+b1.x, dy1*rs*w1.y+b1.y,
                            dy2*rs*w1.z+b1.z, dy3*rs*w1.w+b1.w);
    xr[tid]       = o0;
    xr[tid + 128] = o1;

    __half2* H = (__half2*)(xa + (size_t)row * DD);
    H[tid*2]         = __floats2half2_rn(o0.x, o0.y);
    H[tid*2 + 1]     = __floats2half2_rn(o0.z, o0.w);
    H[(tid+128)*2]   = __floats2half2_rn(o1.x, o1.y);
    H[(tid+128)*2+1] = __floats2half2_rn(o1.z, o1.w);
}

// ------------------------- launch ------------------------------------------
extern "C" void kernel_launch(void* const* d_in, const int* in_sizes, int n_in,
                              void* d_out, int out_size) {
    (void)in_sizes; (void)n_in; (void)out_size;
    const int*   idx  = (const int*)  d_in[0];
    const float* emb  = (const float*)d_in[1];
    const float* Wq   = (const float*)d_in[2];
    const float* Wk   = (const float*)d_in[3];
    const float* Wv   = (const float*)d_in[4];
    const float* Wo   = (const float*)d_in[5];
    const float* ln1w = (const float*)d_in[6];
    const float* ln1b = (const float*)d_in[7];
    const float* W1   = (const float*)d_in[8];
    const float* W2   = (const float*)d_in[9];
    const float* ln2w = (const float*)d_in[10];
    const float* ln2b = (const float*)d_in[11];
    const float* Wout = (const float*)d_in[12];

    float *x, *t;
    __half *wh, *xa, *oa, *fa, *qa, *ka, *va;
    cudaGetSymbolAddress((void**)&x, g_x);
    cudaGetSymbolAddress((void**)&t, g_t);
    cudaGetSymbolAddress((void**)&wh, g_wh);
    cudaGetSymbolAddress((void**)&xa, g_xa);
    cudaGetSymbolAddress((void**)&oa, g_oa);
    cudaGetSymbolAddress((void**)&fa, g_fa);
    cudaGetSymbolAddress((void**)&qa, g_qa);
    cudaGetSymbolAddress((void**)&ka, g_ka);
    cudaGetSymbolAddress((void**)&va, g_va);

    cudaFuncSetAttribute(gemm_tc<0,0>, cudaFuncAttributeMaxDynamicSharedMemorySize, GSMEM);
    cudaFuncSetAttribute(gemm_tc<0,1>, cudaFuncAttributeMaxDynamicSharedMemorySize, GSMEM);
    cudaFuncSetAttribute(gemm_tc<1,2>, cudaFuncAttributeMaxDynamicSharedMemorySize, GSMEM);
    cudaFuncSetAttribute(flash_tc, cudaFuncAttributeMaxDynamicSharedMemorySize, FSMEM);

    // weight conversion: single pass over all tensors
    {
        const int nthreads = (int)(WTOT / 8);
        wconv_all<<<(nthreads + 255)/256, 256>>>(Wq, Wk, Wv, Wo, W1, W2, Wout, wh);
    }

    embed_kernel<<<(BB*SS*(DD/2) + 255) / 256, 256>>>(idx, emb, x, xa);

    for (int l = 0; l < LL; l++) {
        const size_t wqkv = WQKV + (size_t)l * 3*DD*DD;
        const size_t ws   = (size_t)l * DD * DD;
        const size_t wf   = (size_t)l * DFF * DD;
        // fused QKV (N = 3072)
        gemm_tc<0,1><<<dim3(12, 32), 256, GSMEM>>>(xa, wh+wqkv,
                                                   nullptr, qa, ka, va,
                                                   MM, 3*DD, DD);
        flash_tc<<<dim3(SS/128, BB*HH), 256, FSMEM>>>(qa, ka, va, oa);
        gemm_tc<0,0><<<dim3(4, 32), 256, GSMEM>>>(oa, wh+WOO+ws,
                                                  t, nullptr, nullptr, nullptr,
                                                  MM, DD, DD);
        add_ln_kernel<<<MM, 128>>>(x, t, ln1w + l*DD, ln1b + l*DD, xa);
        gemm_tc<1,2><<<dim3(16, 32), 256, GSMEM>>>(xa, wh+W1O+wf,
                                                   nullptr, fa, nullptr, nullptr,
                                                   MM, DFF, DD);
        gemm_tc<0,0><<<dim3(4, 32), 256, GSMEM>>>(fa, wh+W2O+wf,
                                                  t, nullptr, nullptr, nullptr,
                                                  MM, DD, DFF);
        add_ln_kernel<<<MM, 128>>>(x, t, ln2w + l*DD, ln2b + l*DD, xa);
    }
    gemm_tc<0,0><<<dim3(8, 32), 256, GSMEM>>>(xa, wh+WUO,
                                              (float*)d_out, nullptr, nullptr, nullptr,
                                              MM, VV, DD);
}

// round 15
// speedup vs baseline: 6.8653x; 1.0086x over previous
#include <cuda_runtime.h>
#include <cuda_fp16.h>
#include <math.h>
#include <stdint.h>

// Problem constants
#define BB   2
#define SS   2048
#define DD   1024
#define HH   16
#define LL   4
#define VV   2000
#define DK   64
#define DFF  4096
#define MM   (BB*SS)          // 4096 rows

// ------------------------- scratch (static device memory) -------------------
__device__ float g_x[MM*DD];      // activations [B*S, D] fp32 (residual path)
__device__ float g_t[MM*DD];      // temp (pre-LN residual branch)

// single-fp16 weights
#define WQKV 0u                    // [L][Wq;Wk;Wv] each 1024x1024
#define WOO  12582912u
#define W1O  16777216u
#define W2O  33554432u
#define WUO  50331648u
#define WTOT 52379648u
__device__ __half g_wh[WTOT];
// single-fp16 activations
__device__ __half g_xa[MM*DD];     // LN output
__device__ __half g_oa[MM*DD];     // attention out [B,S,D]
__device__ __half g_fa[MM*DFF];    // FFN hidden (post-relu)
__device__ __half g_qa[MM*DD];     // [B,H,S,DK] (pre-scaled by log2e/8)
__device__ __half g_ka[MM*DD];
__device__ __half g_va[MM*DD];

// ------------------------- PTX helpers --------------------------------------
__device__ __forceinline__ uint32_t s2u(const void* p) {
    uint32_t a;
    asm("{ .reg .u64 t; cvta.to.shared.u64 t, %1; cvt.u32.u64 %0, t; }"
        : "=r"(a) : "l"(p));
    return a;
}
__device__ __forceinline__ void cpa16(uint32_t s, const void* g) {
    asm volatile("cp.async.cg.shared.global [%0], [%1], 16;" :: "r"(s), "l"(g));
}
__device__ __forceinline__ void ldsm4(uint32_t* r, uint32_t a) {
    asm volatile("ldmatrix.sync.aligned.m8n8.x4.shared.b16 {%0,%1,%2,%3}, [%4];"
                 : "=r"(r[0]), "=r"(r[1]), "=r"(r[2]), "=r"(r[3]) : "r"(a));
}
__device__ __forceinline__ void ldsm4t(uint32_t* r, uint32_t a) {
    asm volatile("ldmatrix.sync.aligned.m8n8.x4.trans.shared.b16 {%0,%1,%2,%3}, [%4];"
                 : "=r"(r[0]), "=r"(r[1]), "=r"(r[2]), "=r"(r[3]) : "r"(a));
}
__device__ __forceinline__ void mma16816(float* c, const uint32_t* a, const uint32_t* b) {
    asm volatile(
        "mma.sync.aligned.m16n8k16.row.col.f32.f16.f16.f32 "
        "{%0,%1,%2,%3}, {%4,%5,%6,%7}, {%8,%9}, {%0,%1,%2,%3};"
        : "+f"(c[0]), "+f"(c[1]), "+f"(c[2]), "+f"(c[3])
        : "r"(a[0]), "r"(a[1]), "r"(a[2]), "r"(a[3]), "r"(b[0]), "r"(b[1]));
}
__device__ __forceinline__ uint32_t ex2_f16x2(uint32_t x) {
    uint32_t r;
    asm("ex2.approx.f16x2 %0, %1;" : "=r"(r) : "r"(x));
    return r;
}

// ------------------------- convert helpers -----------------------------------
__device__ __forceinline__ uint32_t pack2(float a, float b) {
    __half2 h2 = __floats2half2_rn(a, b);
    return *(uint32_t*)&h2;
}

// single-pass weight conversion for ALL weight tensors
__global__ void wconv_all(const float* __restrict__ Wq, const float* __restrict__ Wk,
                          const float* __restrict__ Wv, const float* __restrict__ Wo,
                          const float* __restrict__ W1, const float* __restrict__ W2,
                          const float* __restrict__ Wout, __half* __restrict__ wh) {
    size_t i = ((size_t)blockIdx.x * blockDim.x + threadIdx.x) * 8;  // half index
    if (i >= WTOT) return;
    const float* src;
    if (i < WOO) {
        size_t l   = i / (3u*DD*DD);
        size_t rem = i - l * (3u*DD*DD);
        size_t j   = rem / ((size_t)DD*DD);
        size_t off = rem - j * ((size_t)DD*DD);
        const float* W = (j == 0) ? Wq : (j == 1) ? Wk : Wv;
        src = W + l * (size_t)DD*DD + off;
    } else if (i < W1O) src = Wo   + (i - WOO);
    else if (i < W2O)   src = W1   + (i - W1O);
    else if (i < WUO)   src = W2   + (i - W2O);
    else                src = Wout + (i - WUO);
    float4 v0 = ((const float4*)src)[0];
    float4 v1 = ((const float4*)src)[1];
    uint4 out;
    out.x = pack2(v0.x, v0.y); out.y = pack2(v0.z, v0.w);
    out.z = pack2(v1.x, v1.y); out.w = pack2(v1.z, v1.w);
    *(uint4*)(wh + i) = out;
}

// ------------------------- embedding + positional encoding ------------------
__global__ void embed_kernel(const int* __restrict__ idx,
                             const float* __restrict__ emb,
                             float* __restrict__ x, __half* __restrict__ xa) {
    int t = blockIdx.x * blockDim.x + threadIdx.x;
    if (t >= BB*SS*(DD/2)) return;
    int dp = t & 511;
    int bs = t >> 9;
    int s  = bs & (SS - 1);
    int d  = dp << 1;
    double freq = exp((double)d * (-9.210340371976184 / 1024.0));
    double ang  = (double)s * freq;
    double sv, cv;
    sincos(ang, &sv, &cv);
    int tok = idx[bs];
    float2 e = ((const float2*)emb)[(size_t)tok * 512 + dp];
    float vx = e.x + (float)sv, vy = e.y + (float)cv;
    ((float2*)x)[t] = make_float2(vx, vy);
    ((__half2*)xa)[t] = __floats2half2_rn(vx, vy);
}

// ------------------------- mma.sync fp16 1-term GEMM -------------------------
// C[M,N] = A[M,K] * B[N,K]^T, A and B single fp16, fp32 accum.
// CTA tile 128x256, K-tile 32, 256 thr, 8 warps (64x64 warp tiles).
// OMODE: 0 = fp32 row-major out
//        1 = fused QKV (N=3072): q(*log2e/8)/k/v single fp16, remap [B,H,S,DK]
//        2 = fp16 single row-major out (with optional relu)
#define LDSB   80            // smem row stride in bytes (40 fp16)
#define ATILE  (128*LDSB)    // 10240
#define BTILE  (256*LDSB)    // 20480
#define STAGEB (ATILE + BTILE)       // 30720
#define NSTAGE 3
#define GSMEM  (NSTAGE*STAGEB)       // 92160

template<int ACT, int OMODE>
__global__ __launch_bounds__(256)
void gemm_tc(const __half* __restrict__ Aq, const __half* __restrict__ Bq,
             float* __restrict__ C,
             __half* __restrict__ P0, __half* __restrict__ P1,
             __half* __restrict__ P2,
             int M, int N, int K)
{
    extern __shared__ __align__(16) char smem[];
    const uint32_t sb = s2u(smem);
    const int tid = threadIdx.x;
    const int wid = tid >> 5, lane = tid & 31;
    const int wm = wid & 1, wn = wid >> 1;
    const int row0 = blockIdx.y * 128, col0 = blockIdx.x * 256;

    const int chunk = tid & 3;
    const int rr    = tid >> 2;
    const int rA0 = row0 + rr, rA1 = rA0 + 64;
    int rB0 = col0 + rr;       if (rB0 > N - 1) rB0 = N - 1;
    int rB1 = col0 + rr + 64;  if (rB1 > N - 1) rB1 = N - 1;
    int rB2 = col0 + rr + 128; if (rB2 > N - 1) rB2 = N - 1;
    int rB3 = col0 + rr + 192; if (rB3 > N - 1) rB3 = N - 1;
    const uint32_t sA0 = (uint32_t)rr * LDSB + (uint32_t)chunk * 16;

    auto issue = [&](int kt, int buf) {
        const int ko = kt * 32 + chunk * 8;
        const uint32_t base = sb + (uint32_t)buf * STAGEB;
        cpa16(base + sA0,            Aq + (size_t)rA0 * K + ko);
        cpa16(base + sA0 + 64u*LDSB, Aq + (size_t)rA1 * K + ko);
        const uint32_t bb = base + ATILE;
        cpa16(bb + sA0,              Bq + (size_t)rB0 * K + ko);
        cpa16(bb + sA0 +  64u*LDSB,  Bq + (size_t)rB1 * K + ko);
        cpa16(bb + sA0 + 128u*LDSB,  Bq + (size_t)rB2 * K + ko);
        cpa16(bb + sA0 + 192u*LDSB,  Bq + (size_t)rB3 * K + ko);
        asm volatile("cp.async.commit_group;" ::: "memory");
    };

    float acc[4][8][4];
#pragma unroll
    for (int i = 0; i < 4; i++)
#pragma unroll
        for (int j = 0; j < 8; j++)
#pragma unroll
            for (int q = 0; q < 4; q++) acc[i][j][q] = 0.f;

    const int KT = K >> 5;
    issue(0, 0);
    issue(1, 1);
    issue(2, 2);

    const uint32_t aoff = (uint32_t)(wm*64 + (lane & 15)) * LDSB + ((lane >> 4) << 4);
    const uint32_t boff = (uint32_t)(wn*64 + (lane & 7) + ((lane >> 4) << 3)) * LDSB
                        + (((lane >> 3) & 1) << 4);

    int buf = 0;
#pragma unroll 1
    for (int kt = 0; kt < KT; kt++) {
        if (kt + 2 < KT)      asm volatile("cp.async.wait_group 2;" ::: "memory");
        else if (kt + 1 < KT) asm volatile("cp.async.wait_group 1;" ::: "memory");
        else                  asm volatile("cp.async.wait_group 0;" ::: "memory");
        __syncthreads();
        const uint32_t base = sb + (uint32_t)buf * STAGEB;
#pragma unroll
        for (int ks = 0; ks < 2; ks++) {
            const uint32_t ka = base + (uint32_t)ks * 32 + aoff;
            const uint32_t kb = base + ATILE + (uint32_t)ks * 32 + boff;
            uint32_t ah[4][4];
#pragma unroll
            for (int mt = 0; mt < 4; mt++)
                ldsm4(ah[mt], ka + (uint32_t)mt * (16*LDSB));
#pragma unroll
            for (int p = 0; p < 4; p++) {
                uint32_t b4[4];
                ldsm4(b4, kb + (uint32_t)p * (16*LDSB));
#pragma unroll
                for (int mt = 0; mt < 4; mt++) {
                    mma16816(acc[mt][2*p],   ah[mt], b4);
                    mma16816(acc[mt][2*p+1], ah[mt], b4 + 2);
                }
            }
        }
        __syncthreads();
        if (kt + 3 < KT) issue(kt + 3, buf);
        buf = (buf == 2) ? 0 : buf + 1;
    }

    const int base_m = row0 + wm*64;
    const int base_n = col0 + wn*64;
#pragma unroll
    for (int mt = 0; mt < 4; mt++) {
#pragma unroll
        for (int nt = 0; nt < 8; nt++) {
            float* c = acc[mt][nt];
            if (ACT == 1) {
                c[0] = fmaxf(c[0], 0.f); c[1] = fmaxf(c[1], 0.f);
                c[2] = fmaxf(c[2], 0.f); c[3] = fmaxf(c[3], 0.f);
            }
            const int r0 = base_m + mt*16 + (lane >> 2);
            const int cc = base_n + nt*8 + (lane & 3)*2;
            if (OMODE == 0) {
                if (cc < N) {
                    *(float2*)(C + (size_t)r0 * N + cc)       = make_float2(c[0], c[1]);
                    *(float2*)(C + (size_t)(r0 + 8) * N + cc) = make_float2(c[2], c[3]);
                }
            } else if (OMODE == 1) {
                // fused QKV: n in [0,3072)
                const int sect = cc >> 10;
                const int nc = cc & 1023;
                const int h = nc >> 6, kk = nc & (DK - 1);
                const int b0i = r0 >> 11, s0r = r0 & (SS - 1);
                const size_t i0 = (((size_t)(b0i*HH + h)*SS + s0r)*DK + kk) >> 1;
                const int r1 = r0 + 8;
                const int b1i = r1 >> 11, s1r = r1 & (SS - 1);
                const size_t i1 = (((size_t)(b1i*HH + h)*SS + s1r)*DK + kk) >> 1;
                __half2* dst = (__half2*)((sect == 0) ? P0 : (sect == 1) ? P1 : P2);
                // Q pre-scaled by log2(e)/sqrt(DK) (flash works in log2 domain)
                const float sc = (sect == 0) ? 0.180336884f : 1.f;
                dst[i0] = __floats2half2_rn(c[0]*sc, c[1]*sc);
                dst[i1] = __floats2half2_rn(c[2]*sc, c[3]*sc);
            } else {
                if (cc < N) {
                    ((__half2*)P0)[((size_t)r0 * N + cc) >> 1]
                        = __floats2half2_rn(c[0], c[1]);
                    ((__half2*)P0)[((size_t)(r0 + 8) * N + cc) >> 1]
                        = __floats2half2_rn(c[2], c[3]);
                }
            }
        }
    }
}

// ------------------------- tensor-core flash attention ----------------------
// Q single fp16 (pre-scaled log2e/8), K/V single fp16 in [B,H,S,DK]. Causal.
// CTA = 128 q-rows, 8 warps (16 q-rows each). k-tile 64. Log2-domain softmax
// with ex2.approx.f16x2 (p computed directly in fp16 pairs = PV A-fragments).
#define FSTR   144                 // smem row stride bytes (64 fp16 + pad)
#define FQSZ   (128*FSTR)          // 18432
#define SKH    0
#define SV     9216
#define FSTAGE 18432
#define FSMEM  (FQSZ + 2*FSTAGE)   // 55296

__global__ __launch_bounds__(256, 2)
void flash_tc(const __half* __restrict__ Qa, const __half* __restrict__ Ka,
              const __half* __restrict__ Va, __half* __restrict__ OA)
{
    extern __shared__ __align__(16) char smem[];
    const uint32_t sb = s2u(smem);
    const int bh  = blockIdx.y;
    const int qt  = gridDim.x - 1 - blockIdx.x;   // heavy blocks first
    const int tid = threadIdx.x, wid = tid >> 5, lane = tid & 31;
    const int q0  = qt * 128;
    const int ntiles = 2*qt + 2;

    // Q tile load: 128 rows x 8 chunks
    {
        const size_t g = ((size_t)bh * SS + q0) * DK;
#pragma unroll
        for (int c = tid; c < 1024; c += 256) {
            const int row = c >> 3, ch = c & 7;
            cpa16(sb + (uint32_t)row * FSTR + (uint32_t)ch * 16,
                  Qa + g + row * DK + ch * 8);
        }
        asm volatile("cp.async.commit_group;" ::: "memory");
    }

    auto loadkv = [&](int kt, int bufi) {
        const uint32_t base = sb + FQSZ + (uint32_t)bufi * FSTAGE;
        const size_t g = ((size_t)bh * SS + kt * 64) * DK;
#pragma unroll
        for (int c = tid; c < 512; c += 256) {
            const int row = c >> 3, ch = c & 7;
            const uint32_t so = (uint32_t)row * FSTR + (uint32_t)ch * 16;
            const size_t go = g + row * DK + ch * 8;
            cpa16(base + SKH + so, Ka + go);
            cpa16(base + SV  + so, Va + go);
        }
        asm volatile("cp.async.commit_group;" ::: "memory");
    };

    loadkv(0, 0);
    loadkv(1, 1);

    asm volatile("cp.async.wait_group 1;" ::: "memory");
    __syncthreads();

    // Q fragments (16 rows per warp)
    uint32_t qf[4][4];
    {
        const uint32_t a0 = sb + (uint32_t)(wid*16 + (lane & 15)) * FSTR + ((lane >> 4) << 4);
#pragma unroll
        for (int kc = 0; kc < 4; kc++)
            ldsm4(qf[kc], a0 + kc*32);
    }

    float o[8][4];
#pragma unroll
    for (int i = 0; i < 8; i++)
#pragma unroll
        for (int j = 0; j < 4; j++) o[i][j] = 0.f;
    float mi0 = -1e30f, mi1 = -1e30f, li0 = 0.f, li1 = 0.f;

    const uint32_t kboff = (uint32_t)((lane & 7) + ((lane >> 4) << 3)) * FSTR
                         + (((lane >> 3) & 1) << 4);
    const uint32_t vboff = (uint32_t)((((lane >> 3) & 1) << 3) + (lane & 7)) * FSTR
                         + ((lane >> 4) << 4);

#pragma unroll 1
    for (int kt = 0; kt < ntiles; kt++) {
        const int bufi = kt & 1;
        if (kt > 0) {
            if (kt < ntiles - 1) asm volatile("cp.async.wait_group 1;" ::: "memory");
            else                 asm volatile("cp.async.wait_group 0;" ::: "memory");
            __syncthreads();
        }
        const uint32_t base = sb + FQSZ + (uint32_t)bufi * FSTAGE;

        // last diagonal tile: warps 0-3 (rows 0-63) fully masked -> skip body
        const bool skip = (kt == ntiles - 1) && (wid < 4);
        if (!skip) {
            // S = Q K^T (1-term); Q pre-scaled into log2 domain
            float s[8][4];
#pragma unroll
            for (int i = 0; i < 8; i++)
#pragma unroll
                for (int j = 0; j < 4; j++) s[i][j] = 0.f;
#pragma unroll
            for (int kc = 0; kc < 4; kc++) {
#pragma unroll
                for (int np = 0; np < 4; np++) {
                    uint32_t kh4[4];
                    ldsm4(kh4, base + SKH + kboff + kc*32 + (uint32_t)np * (16*FSTR));
                    mma16816(s[2*np],   qf[kc], kh4);
                    mma16816(s[2*np+1], qf[kc], kh4 + 2);
                }
            }

            // causal mask (last two k-tiles only)
            if (kt >= ntiles - 2) {
                const int rk = wid*16 + (lane >> 2) - (kt*64 - q0);
                const int cb = (lane & 3) * 2;
#pragma unroll
                for (int nt = 0; nt < 8; nt++) {
                    const int k0 = nt*8 + cb;
                    if (k0     > rk    ) s[nt][0] = -1e30f;
                    if (k0 + 1 > rk    ) s[nt][1] = -1e30f;
                    if (k0     > rk + 8) s[nt][2] = -1e30f;
                    if (k0 + 1 > rk + 8) s[nt][3] = -1e30f;
                }
            }

            // online softmax (log2 domain)
            float m0 = -1e30f, m1 = -1e30f;
#pragma unroll
            for (int nt = 0; nt < 8; nt++) {
                m0 = fmaxf(m0, fmaxf(s[nt][0], s[nt][1]));
                m1 = fmaxf(m1, fmaxf(s[nt][2], s[nt][3]));
            }
            m0 = fmaxf(m0, __shfl_xor_sync(0xffffffffu, m0, 1));
            m0 = fmaxf(m0, __shfl_xor_sync(0xffffffffu, m0, 2));
            m1 = fmaxf(m1, __shfl_xor_sync(0xffffffffu, m1, 1));
            m1 = fmaxf(m1, __shfl_xor_sync(0xffffffffu, m1, 2));
            const float mn0 = fmaxf(mi0, m0), mn1 = fmaxf(mi1, m1);
            const float rs0 = exp2f(mi0 - mn0), rs1 = exp2f(mi1 - mn1);
            mi0 = mn0; mi1 = mn1;
            li0 *= rs0; li1 *= rs1;
#pragma unroll
            for (int nt = 0; nt < 8; nt++) {
                o[nt][0] *= rs0; o[nt][1] *= rs0;
                o[nt][2] *= rs1; o[nt][3] *= rs1;
            }

            // p = exp2(s - mn) directly in fp16 pairs (PV A-fragments)
            uint32_t pex[8][2];
            float ls0 = 0.f, ls1 = 0.f;
#pragma unroll
            for (int nt = 0; nt < 8; nt++) {
                pex[nt][0] = ex2_f16x2(pack2(s[nt][0] - mn0, s[nt][1] - mn0));
                pex[nt][1] = ex2_f16x2(pack2(s[nt][2] - mn1, s[nt][3] - mn1));
                float2 flo = __half22float2(*(__half2*)&pex[nt][0]);
                float2 fhi = __half22float2(*(__half2*)&pex[nt][1]);
                ls0 += flo.x + flo.y;
                ls1 += fhi.x + fhi.y;
            }
            li0 += ls0; li1 += ls1;

            // O += P V (1-term)
#pragma unroll
            for (int kc = 0; kc < 4; kc++) {
                uint32_t pa[4];
                pa[0] = pex[2*kc][0];   pa[1] = pex[2*kc][1];
                pa[2] = pex[2*kc+1][0]; pa[3] = pex[2*kc+1][1];
#pragma unroll
                for (int np = 0; np < 4; np++) {
                    uint32_t vh4[4];
                    ldsm4t(vh4, base + SV + vboff + (uint32_t)kc * (16*FSTR) + np*32);
                    mma16816(o[2*np],   pa, vh4);
                    mma16816(o[2*np+1], pa, vh4 + 2);
                }
            }
        }

        __syncthreads();
        if (kt + 2 < ntiles) loadkv(kt + 2, bufi);
    }

    // final row sums + write O single fp16 [B,S,D]
    li0 += __shfl_xor_sync(0xffffffffu, li0, 1);
    li0 += __shfl_xor_sync(0xffffffffu, li0, 2);
    li1 += __shfl_xor_sync(0xffffffffu, li1, 1);
    li1 += __shfl_xor_sync(0xffffffffu, li1, 2);
    const float inv0 = 1.f / li0, inv1 = 1.f / li1;
    const int b = bh >> 4, h = bh & (HH - 1);
    const int qr = q0 + wid*16 + (lane >> 2);
    const size_t rowA = ((size_t)(b*SS + qr)) * DD + h * DK;
    const size_t rowB = rowA + 8 * DD;
    __half2* OA2 = (__half2*)OA;
#pragma unroll
    for (int nt = 0; nt < 8; nt++) {
        const int dk = nt*8 + (lane & 3)*2;
        OA2[(rowA + dk) >> 1] = __floats2half2_rn(o[nt][0]*inv0, o[nt][1]*inv0);
        OA2[(rowB + dk) >> 1] = __floats2half2_rn(o[nt][2]*inv1, o[nt][3]*inv1);
    }
}

// ------------------------- residual add + layernorm + fp16 out --------------
__global__ __launch_bounds__(128)
void add_ln_kernel(float* __restrict__ x, const float* __restrict__ r,
                   const float* __restrict__ w, const float* __restrict__ bias,
                   __half* __restrict__ xa) {
    __shared__ float sh[4];
    const int row = blockIdx.x;
    const int tid = threadIdx.x;
    float4* xr = (float4*)(x + (size_t)row * DD);
    const float4* rr = (const float4*)(r + (size_t)row * DD);
    float4 v0 = xr[tid], v1 = xr[tid + 128];
    float4 a0 = rr[tid], a1 = rr[tid + 128];
    v0.x += a0.x; v0.y += a0.y; v0.z += a0.z; v0.w += a0.w;
    v1.x += a1.x; v1.y += a1.y; v1.z += a1.z; v1.w += a1.w;

    float s = v0.x+v0.y+v0.z+v0.w + v1.x+v1.y+v1.z+v1.w;
#pragma unroll
    for (int o = 16; o > 0; o >>= 1) s += __shfl_down_sync(0xffffffffu, s, o);
    if ((tid & 31) == 0) sh[tid >> 5] = s;
    __syncthreads();
    float mean = (sh[0]+sh[1]+sh[2]+sh[3]) * (1.f/DD);
    __syncthreads();

    float dx0 = v0.x-mean, dx1 = v0.y-mean, dx2 = v0.z-mean, dx3 = v0.w-mean;
    float dy0 = v1.x-mean, dy1 = v1.y-mean, dy2 = v1.z-mean, dy3 = v1.w-mean;
    float sq = dx0*dx0+dx1*dx1+dx2*dx2+dx3*dx3 + dy0*dy0+dy1*dy1+dy2*dy2+dy3*dy3;
#pragma unroll
    for (int o = 16; o > 0; o >>= 1) sq += __shfl_down_sync(0xffffffffu, sq, o);
    if ((tid & 31) == 0) sh[tid >> 5] = sq;
    __syncthreads();
    float var = (sh[0]+sh[1]+sh[2]+sh[3]) * (1.f/DD);
    float rs = rsqrtf(var + 1e-5f);

    float4 w0 = ((const float4*)w)[tid],     w1 = ((const float4*)w)[tid + 128];
    float4 b0 = ((const float4*)bias)[tid],  b1 = ((const float4*)bias)[tid + 128];
    float4 o0 = make_float4(dx0*rs*w0.x+b0.x, dx1*rs*w0.y+b0.y,
                            dx2*rs*w0.z+b0.z, dx3*rs*w0.w+b0.w);
    float4 o1 = make_float4(dy0*rs*w1.x+b1.x, dy1*rs*w1.y+b1.y,
                            dy2*rs*w1.z+b1.z, dy3*rs*w1.w+b1.w);
    xr[tid]       = o0;
    xr[tid + 128] = o1;

    __half2* H = (__half2*)(xa + (size_t)row * DD);
    H[tid*2]         = __floats2half2_rn(o0.x, o0.y);
    H[tid*2 + 1]     = __floats2half2_rn(o0.z, o0.w);
    H[(tid+128)*2]   = __floats2half2_rn(o1.x, o1.y);
    H[(tid+128)*2+1] = __floats2half2_rn(o1.z, o1.w);
}

// ------------------------- launch ------------------------------------------
extern "C" void kernel_launch(void* const* d_in, const int* in_sizes, int n_in,
                              void* d_out, int out_size) {
    (void)in_sizes; (void)n_in; (void)out_size;
    const int*   idx  = (const int*)  d_in[0];
    const float* emb  = (const float*)d_in[1];
    const float* Wq   = (const float*)d_in[2];
    const float* Wk   = (const float*)d_in[3];
    const float* Wv   = (const float*)d_in[4];
    const float* Wo   = (const float*)d_in[5];
    const float* ln1w = (const float*)d_in[6];
    const float* ln1b = (const float*)d_in[7];
    const float* W1   = (const float*)d_in[8];
    const float* W2   = (const float*)d_in[9];
    const float* ln2w = (const float*)d_in[10];
    const float* ln2b = (const float*)d_in[11];
    const float* Wout = (const float*)d_in[12];

    float *x, *t;
    __half *wh, *xa, *oa, *fa, *qa, *ka, *va;
    cudaGetSymbolAddress((void**)&x, g_x);
    cudaGetSymbolAddress((void**)&t, g_t);
    cudaGetSymbolAddress((void**)&wh, g_wh);
    cudaGetSymbolAddress((void**)&xa, g_xa);
    cudaGetSymbolAddress((void**)&oa, g_oa);
    cudaGetSymbolAddress((void**)&fa, g_fa);
    cudaGetSymbolAddress((void**)&qa, g_qa);
    cudaGetSymbolAddress((void**)&ka, g_ka);
    cudaGetSymbolAddress((void**)&va, g_va);

    cudaFuncSetAttribute(gemm_tc<0,0>, cudaFuncAttributeMaxDynamicSharedMemorySize, GSMEM);
    cudaFuncSetAttribute(gemm_tc<0,1>, cudaFuncAttributeMaxDynamicSharedMemorySize, GSMEM);
    cudaFuncSetAttribute(gemm_tc<1,2>, cudaFuncAttributeMaxDynamicSharedMemorySize, GSMEM);
    cudaFuncSetAttribute(flash_tc, cudaFuncAttributeMaxDynamicSharedMemorySize, FSMEM);

    // weight conversion: single pass over all tensors
    {
        const int nthreads = (int)(WTOT / 8);
        wconv_all<<<(nthreads + 255)/256, 256>>>(Wq, Wk, Wv, Wo, W1, W2, Wout, wh);
    }

    embed_kernel<<<(BB*SS*(DD/2) + 255) / 256, 256>>>(idx, emb, x, xa);

    for (int l = 0; l < LL; l++) {
        const size_t wqkv = WQKV + (size_t)l * 3*DD*DD;
        const size_t ws   = (size_t)l * DD * DD;
        const size_t wf   = (size_t)l * DFF * DD;
        // fused QKV (N = 3072)
        gemm_tc<0,1><<<dim3(12, 32), 256, GSMEM>>>(xa, wh+wqkv,
                                                   nullptr, qa, ka, va,
                                                   MM, 3*DD, DD);
        flash_tc<<<dim3(SS/128, BB*HH), 256, FSMEM>>>(qa, ka, va, oa);
        gemm_tc<0,0><<<dim3(4, 32), 256, GSMEM>>>(oa, wh+WOO+ws,
                                                  t, nullptr, nullptr, nullptr,
                                                  MM, DD, DD);
        add_ln_kernel<<<MM, 128>>>(x, t, ln1w + l*DD, ln1b + l*DD, xa);
        gemm_tc<1,2><<<dim3(16, 32), 256, GSMEM>>>(xa, wh+W1O+wf,
                                                   nullptr, fa, nullptr, nullptr,
                                                   MM, DFF, DD);
        gemm_tc<0,0><<<dim3(4, 32), 256, GSMEM>>>(fa, wh+W2O+wf,
                                                  t, nullptr, nullptr, nullptr,
                                                  MM, DD, DFF);
        add_ln_kernel<<<MM, 128>>>(x, t, ln2w + l*DD, ln2b + l*DD, xa);
    }
    gemm_tc<0,0><<<dim3(8, 32), 256, GSMEM>>>(xa, wh+WUO,
                                              (float*)d_out, nullptr, nullptr, nullptr,
                                              MM, VV, DD);
}

// round 16
// speedup vs baseline: 7.3751x; 1.0743x over previous
#include <cuda_runtime.h>
#include <cuda_fp16.h>
#include <math.h>
#include <stdint.h>

// Problem constants
#define BB   2
#define SS   2048
#define DD   1024
#define HH   16
#define LL   4
#define VV   2000
#define DK   64
#define DFF  4096
#define MM   (BB*SS)          // 4096 rows

// ------------------------- scratch (static device memory) -------------------
__device__ float g_x[MM*DD];      // activations [B*S, D] fp32 (residual path)
__device__ float g_t[MM*DD];      // temp (pre-LN residual branch)

// single-fp16 weights
#define WQKV 0u                    // [L][Wq;Wk;Wv] each 1024x1024
#define WOO  12582912u
#define W1O  16777216u
#define W2O  33554432u
#define WUO  50331648u
#define WTOT 52379648u
__device__ __half g_wh[WTOT];
// single-fp16 activations
__device__ __half g_xa[MM*DD];     // LN output
__device__ __half g_oa[MM*DD];     // attention out [B,S,D]
__device__ __half g_fa[MM*DFF];    // FFN hidden (post-relu)
__device__ __half g_qa[MM*DD];     // [B,H,S,DK] (pre-scaled by log2e/8)
__device__ __half g_ka[MM*DD];
__device__ __half g_va[MM*DD];

// ------------------------- PTX helpers --------------------------------------
__device__ __forceinline__ uint32_t s2u(const void* p) {
    uint32_t a;
    asm("{ .reg .u64 t; cvta.to.shared.u64 t, %1; cvt.u32.u64 %0, t; }"
        : "=r"(a) : "l"(p));
    return a;
}
__device__ __forceinline__ void cpa16(uint32_t s, const void* g) {
    asm volatile("cp.async.cg.shared.global [%0], [%1], 16;" :: "r"(s), "l"(g));
}
__device__ __forceinline__ void ldsm4(uint32_t* r, uint32_t a) {
    asm volatile("ldmatrix.sync.aligned.m8n8.x4.shared.b16 {%0,%1,%2,%3}, [%4];"
                 : "=r"(r[0]), "=r"(r[1]), "=r"(r[2]), "=r"(r[3]) : "r"(a));
}
__device__ __forceinline__ void ldsm4t(uint32_t* r, uint32_t a) {
    asm volatile("ldmatrix.sync.aligned.m8n8.x4.trans.shared.b16 {%0,%1,%2,%3}, [%4];"
                 : "=r"(r[0]), "=r"(r[1]), "=r"(r[2]), "=r"(r[3]) : "r"(a));
}
__device__ __forceinline__ void mma16816(float* c, const uint32_t* a, const uint32_t* b) {
    asm volatile(
        "mma.sync.aligned.m16n8k16.row.col.f32.f16.f16.f32 "
        "{%0,%1,%2,%3}, {%4,%5,%6,%7}, {%8,%9}, {%0,%1,%2,%3};"
        : "+f"(c[0]), "+f"(c[1]), "+f"(c[2]), "+f"(c[3])
        : "r"(a[0]), "r"(a[1]), "r"(a[2]), "r"(a[3]), "r"(b[0]), "r"(b[1]));
}
__device__ __forceinline__ uint32_t ex2_f16x2(uint32_t x) {
    uint32_t r;
    asm("ex2.approx.f16x2 %0, %1;" : "=r"(r) : "r"(x));
    return r;
}

// ------------------------- convert helpers -----------------------------------
__device__ __forceinline__ uint32_t pack2(float a, float b) {
    __half2 h2 = __floats2half2_rn(a, b);
    return *(uint32_t*)&h2;
}

// single-pass weight conversion for ALL weight tensors
__global__ void wconv_all(const float* __restrict__ Wq, const float* __restrict__ Wk,
                          const float* __restrict__ Wv, const float* __restrict__ Wo,
                          const float* __restrict__ W1, const float* __restrict__ W2,
                          const float* __restrict__ Wout, __half* __restrict__ wh) {
    size_t i = ((size_t)blockIdx.x * blockDim.x + threadIdx.x) * 8;  // half index
    if (i >= WTOT) return;
    const float* src;
    if (i < WOO) {
        size_t l   = i / (3u*DD*DD);
        size_t rem = i - l * (3u*DD*DD);
        size_t j   = rem / ((size_t)DD*DD);
        size_t off = rem - j * ((size_t)DD*DD);
        const float* W = (j == 0) ? Wq : (j == 1) ? Wk : Wv;
        src = W + l * (size_t)DD*DD + off;
    } else if (i < W1O) src = Wo   + (i - WOO);
    else if (i < W2O)   src = W1   + (i - W1O);
    else if (i < WUO)   src = W2   + (i - W2O);
    else                src = Wout + (i - WUO);
    float4 v0 = ((const float4*)src)[0];
    float4 v1 = ((const float4*)src)[1];
    uint4 out;
    out.x = pack2(v0.x, v0.y); out.y = pack2(v0.z, v0.w);
    out.z = pack2(v1.x, v1.y); out.w = pack2(v1.z, v1.w);
    *(uint4*)(wh + i) = out;
}

// ------------------------- embedding + positional encoding ------------------
__global__ void embed_kernel(const int* __restrict__ idx,
                             const float* __restrict__ emb,
                             float* __restrict__ x, __half* __restrict__ xa) {
    int t = blockIdx.x * blockDim.x + threadIdx.x;
    if (t >= BB*SS*(DD/2)) return;
    int dp = t & 511;
    int bs = t >> 9;
    int s  = bs & (SS - 1);
    int d  = dp << 1;
    double freq = exp((double)d * (-9.210340371976184 / 1024.0));
    double ang  = (double)s * freq;
    double sv, cv;
    sincos(ang, &sv, &cv);
    int tok = idx[bs];
    float2 e = ((const float2*)emb)[(size_t)tok * 512 + dp];
    float vx = e.x + (float)sv, vy = e.y + (float)cv;
    ((float2*)x)[t] = make_float2(vx, vy);
    ((__half2*)xa)[t] = __floats2half2_rn(vx, vy);
}

// ------------------------- mma.sync fp16 1-term GEMM -------------------------
// C[M,N] = A[M,K] * B[N,K]^T, A and B single fp16, fp32 accum.
// CTA tile 128x128, K-tile 32, 256 thr, 8 warps (64x32 warp tiles), 2 CTAs/SM.
// 4-stage cp.async pipeline.
// OMODE: 0 = fp32 row-major out
//        1 = fused QKV (N=3072): q(*log2e/8)/k/v single fp16, remap [B,H,S,DK]
//        2 = fp16 single row-major out (with optional relu)
#define LDSB   80            // smem row stride in bytes (40 fp16)
#define ATILE  (128*LDSB)    // 10240
#define BTILE  (128*LDSB)    // 10240
#define STAGEB (ATILE + BTILE)       // 20480
#define NSTAGE 4
#define GSMEM  (NSTAGE*STAGEB)       // 81920

template<int ACT, int OMODE>
__global__ __launch_bounds__(256, 2)
void gemm_tc(const __half* __restrict__ Aq, const __half* __restrict__ Bq,
             float* __restrict__ C,
             __half* __restrict__ P0, __half* __restrict__ P1,
             __half* __restrict__ P2,
             int M, int N, int K)
{
    extern __shared__ __align__(16) char smem[];
    const uint32_t sb = s2u(smem);
    const int tid = threadIdx.x;
    const int wid = tid >> 5, lane = tid & 31;
    const int wm = wid & 1, wn = wid >> 1;       // warp 64x32 tile
    const int row0 = blockIdx.y * 128, col0 = blockIdx.x * 128;

    const int chunk = tid & 3;
    const int rr    = tid >> 2;
    const int rA0 = row0 + rr, rA1 = rA0 + 64;
    int rB0 = col0 + rr;      if (rB0 > N - 1) rB0 = N - 1;
    int rB1 = col0 + rr + 64; if (rB1 > N - 1) rB1 = N - 1;
    const uint32_t sA0 = (uint32_t)rr * LDSB + (uint32_t)chunk * 16;

    auto issue = [&](int kt, int buf) {
        const int ko = kt * 32 + chunk * 8;
        const uint32_t base = sb + (uint32_t)buf * STAGEB;
        cpa16(base + sA0,            Aq + (size_t)rA0 * K + ko);
        cpa16(base + sA0 + 64u*LDSB, Aq + (size_t)rA1 * K + ko);
        const uint32_t bb = base + ATILE;
        cpa16(bb + sA0,              Bq + (size_t)rB0 * K + ko);
        cpa16(bb + sA0 + 64u*LDSB,   Bq + (size_t)rB1 * K + ko);
        asm volatile("cp.async.commit_group;" ::: "memory");
    };

    float acc[4][4][4];
#pragma unroll
    for (int i = 0; i < 4; i++)
#pragma unroll
        for (int j = 0; j < 4; j++)
#pragma unroll
            for (int q = 0; q < 4; q++) acc[i][j][q] = 0.f;

    const int KT = K >> 5;
    issue(0, 0);
    issue(1, 1);
    issue(2, 2);
    issue(3, 3);

    const uint32_t aoff = (uint32_t)(wm*64 + (lane & 15)) * LDSB + ((lane >> 4) << 4);
    const uint32_t boff = (uint32_t)(wn*32 + (lane & 7) + ((lane >> 4) << 3)) * LDSB
                        + (((lane >> 3) & 1) << 4);

    int buf = 0;
#pragma unroll 1
    for (int kt = 0; kt < KT; kt++) {
        if (kt + 3 < KT)      asm volatile("cp.async.wait_group 3;" ::: "memory");
        else if (kt + 2 < KT) asm volatile("cp.async.wait_group 2;" ::: "memory");
        else if (kt + 1 < KT) asm volatile("cp.async.wait_group 1;" ::: "memory");
        else                  asm volatile("cp.async.wait_group 0;" ::: "memory");
        __syncthreads();
        const uint32_t base = sb + (uint32_t)buf * STAGEB;
#pragma unroll
        for (int ks = 0; ks < 2; ks++) {
            const uint32_t ka = base + (uint32_t)ks * 32 + aoff;
            const uint32_t kb = base + ATILE + (uint32_t)ks * 32 + boff;
            uint32_t ah[4][4];
#pragma unroll
            for (int mt = 0; mt < 4; mt++)
                ldsm4(ah[mt], ka + (uint32_t)mt * (16*LDSB));
#pragma unroll
            for (int p = 0; p < 2; p++) {
                uint32_t b4[4];
                ldsm4(b4, kb + (uint32_t)p * (16*LDSB));
#pragma unroll
                for (int mt = 0; mt < 4; mt++) {
                    mma16816(acc[mt][2*p],   ah[mt], b4);
                    mma16816(acc[mt][2*p+1], ah[mt], b4 + 2);
                }
            }
        }
        __syncthreads();
        if (kt + 4 < KT) issue(kt + 4, buf);
        buf = (buf + 1) & 3;
    }

    const int base_m = row0 + wm*64;
    const int base_n = col0 + wn*32;
#pragma unroll
    for (int mt = 0; mt < 4; mt++) {
#pragma unroll
        for (int nt = 0; nt < 4; nt++) {
            float* c = acc[mt][nt];
            if (ACT == 1) {
                c[0] = fmaxf(c[0], 0.f); c[1] = fmaxf(c[1], 0.f);
                c[2] = fmaxf(c[2], 0.f); c[3] = fmaxf(c[3], 0.f);
            }
            const int r0 = base_m + mt*16 + (lane >> 2);
            const int cc = base_n + nt*8 + (lane & 3)*2;
            if (OMODE == 0) {
                if (cc < N) {
                    *(float2*)(C + (size_t)r0 * N + cc)       = make_float2(c[0], c[1]);
                    *(float2*)(C + (size_t)(r0 + 8) * N + cc) = make_float2(c[2], c[3]);
                }
            } else if (OMODE == 1) {
                // fused QKV: n in [0,3072)
                const int sect = cc >> 10;
                const int nc = cc & 1023;
                const int h = nc >> 6, kk = nc & (DK - 1);
                const int b0i = r0 >> 11, s0r = r0 & (SS - 1);
                const size_t i0 = (((size_t)(b0i*HH + h)*SS + s0r)*DK + kk) >> 1;
                const int r1 = r0 + 8;
                const int b1i = r1 >> 11, s1r = r1 & (SS - 1);
                const size_t i1 = (((size_t)(b1i*HH + h)*SS + s1r)*DK + kk) >> 1;
                __half2* dst = (__half2*)((sect == 0) ? P0 : (sect == 1) ? P1 : P2);
                // Q pre-scaled by log2(e)/sqrt(DK) (flash works in log2 domain)
                const float sc = (sect == 0) ? 0.180336884f : 1.f;
                dst[i0] = __floats2half2_rn(c[0]*sc, c[1]*sc);
                dst[i1] = __floats2half2_rn(c[2]*sc, c[3]*sc);
            } else {
                if (cc < N) {
                    ((__half2*)P0)[((size_t)r0 * N + cc) >> 1]
                        = __floats2half2_rn(c[0], c[1]);
                    ((__half2*)P0)[((size_t)(r0 + 8) * N + cc) >> 1]
                        = __floats2half2_rn(c[2], c[3]);
                }
            }
        }
    }
}

// ------------------------- tensor-core flash attention ----------------------
// Q single fp16 (pre-scaled log2e/8), K/V single fp16 in [B,H,S,DK]. Causal.
// CTA = 128 q-rows, 8 warps (16 q-rows each). k-tile 64. Log2-domain softmax
// with ex2.approx.f16x2 (p computed directly in fp16 pairs = PV A-fragments).
#define FSTR   144                 // smem row stride bytes (64 fp16 + pad)
#define FQSZ   (128*FSTR)          // 18432
#define SKH    0
#define SV     9216
#define FSTAGE 18432
#define FSMEM  (FQSZ + 2*FSTAGE)   // 55296

__global__ __launch_bounds__(256, 2)
void flash_tc(const __half* __restrict__ Qa, const __half* __restrict__ Ka,
              const __half* __restrict__ Va, __half* __restrict__ OA)
{
    extern __shared__ __align__(16) char smem[];
    const uint32_t sb = s2u(smem);
    const int bh  = blockIdx.y;
    const int qt  = gridDim.x - 1 - blockIdx.x;   // heavy blocks first
    const int tid = threadIdx.x, wid = tid >> 5, lane = tid & 31;
    const int q0  = qt * 128;
    const int ntiles = 2*qt + 2;

    // Q tile load: 128 rows x 8 chunks
    {
        const size_t g = ((size_t)bh * SS + q0) * DK;
#pragma unroll
        for (int c = tid; c < 1024; c += 256) {
            const int row = c >> 3, ch = c & 7;
            cpa16(sb + (uint32_t)row * FSTR + (uint32_t)ch * 16,
                  Qa + g + row * DK + ch * 8);
        }
        asm volatile("cp.async.commit_group;" ::: "memory");
    }

    auto loadkv = [&](int kt, int bufi) {
        const uint32_t base = sb + FQSZ + (uint32_t)bufi * FSTAGE;
        const size_t g = ((size_t)bh * SS + kt * 64) * DK;
#pragma unroll
        for (int c = tid; c < 512; c += 256) {
            const int row = c >> 3, ch = c & 7;
            const uint32_t so = (uint32_t)row * FSTR + (uint32_t)ch * 16;
            const size_t go = g + row * DK + ch * 8;
            cpa16(base + SKH + so, Ka + go);
            cpa16(base + SV  + so, Va + go);
        }
        asm volatile("cp.async.commit_group;" ::: "memory");
    };

    loadkv(0, 0);
    loadkv(1, 1);

    asm volatile("cp.async.wait_group 1;" ::: "memory");
    __syncthreads();

    // Q fragments (16 rows per warp)
    uint32_t qf[4][4];
    {
        const uint32_t a0 = sb + (uint32_t)(wid*16 + (lane & 15)) * FSTR + ((lane >> 4) << 4);
#pragma unroll
        for (int kc = 0; kc < 4; kc++)
            ldsm4(qf[kc], a0 + kc*32);
    }

    float o[8][4];
#pragma unroll
    for (int i = 0; i < 8; i++)
#pragma unroll
        for (int j = 0; j < 4; j++) o[i][j] = 0.f;
    float mi0 = -1e30f, mi1 = -1e30f, li0 = 0.f, li1 = 0.f;

    const uint32_t kboff = (uint32_t)((lane & 7) + ((lane >> 4) << 3)) * FSTR
                         + (((lane >> 3) & 1) << 4);
    const uint32_t vboff = (uint32_t)((((lane >> 3) & 1) << 3) + (lane & 7)) * FSTR
                         + ((lane >> 4) << 4);

#pragma unroll 1
    for (int kt = 0; kt < ntiles; kt++) {
        const int bufi = kt & 1;
        if (kt > 0) {
            if (kt < ntiles - 1) asm volatile("cp.async.wait_group 1;" ::: "memory");
            else                 asm volatile("cp.async.wait_group 0;" ::: "memory");
            __syncthreads();
        }
        const uint32_t base = sb + FQSZ + (uint32_t)bufi * FSTAGE;

        // last diagonal tile: warps 0-3 (rows 0-63) fully masked -> skip body
        const bool skip = (kt == ntiles - 1) && (wid < 4);
        if (!skip) {
            // S = Q K^T (1-term); Q pre-scaled into log2 domain
            float s[8][4];
#pragma unroll
            for (int i = 0; i < 8; i++)
#pragma unroll
                for (int j = 0; j < 4; j++) s[i][j] = 0.f;
#pragma unroll
            for (int kc = 0; kc < 4; kc++) {
#pragma unroll
                for (int np = 0; np < 4; np++) {
                    uint32_t kh4[4];
                    ldsm4(kh4, base + SKH + kboff + kc*32 + (uint32_t)np * (16*FSTR));
                    mma16816(s[2*np],   qf[kc], kh4);
                    mma16816(s[2*np+1], qf[kc], kh4 + 2);
                }
            }

            // causal mask (last two k-tiles only)
            if (kt >= ntiles - 2) {
                const int rk = wid*16 + (lane >> 2) - (kt*64 - q0);
                const int cb = (lane & 3) * 2;
#pragma unroll
                for (int nt = 0; nt < 8; nt++) {
                    const int k0 = nt*8 + cb;
                    if (k0     > rk    ) s[nt][0] = -1e30f;
                    if (k0 + 1 > rk    ) s[nt][1] = -1e30f;
                    if (k0     > rk + 8) s[nt][2] = -1e30f;
                    if (k0 + 1 > rk + 8) s[nt][3] = -1e30f;
                }
            }

            // online softmax (log2 domain)
            float m0 = -1e30f, m1 = -1e30f;
#pragma unroll
            for (int nt = 0; nt < 8; nt++) {
                m0 = fmaxf(m0, fmaxf(s[nt][0], s[nt][1]));
                m1 = fmaxf(m1, fmaxf(s[nt][2], s[nt][3]));
            }
            m0 = fmaxf(m0, __shfl_xor_sync(0xffffffffu, m0, 1));
            m0 = fmaxf(m0, __shfl_xor_sync(0xffffffffu, m0, 2));
            m1 = fmaxf(m1, __shfl_xor_sync(0xffffffffu, m1, 1));
            m1 = fmaxf(m1, __shfl_xor_sync(0xffffffffu, m1, 2));
            const float mn0 = fmaxf(mi0, m0), mn1 = fmaxf(mi1, m1);
            const float rs0 = exp2f(mi0 - mn0), rs1 = exp2f(mi1 - mn1);
            mi0 = mn0; mi1 = mn1;
            li0 *= rs0; li1 *= rs1;
#pragma unroll
            for (int nt = 0; nt < 8; nt++) {
                o[nt][0] *= rs0; o[nt][1] *= rs0;
                o[nt][2] *= rs1; o[nt][3] *= rs1;
            }

            // p = exp2(s - mn) directly in fp16 pairs (PV A-fragments)
            uint32_t pex[8][2];
            float ls0 = 0.f, ls1 = 0.f;
#pragma unroll
            for (int nt = 0; nt < 8; nt++) {
                pex[nt][0] = ex2_f16x2(pack2(s[nt][0] - mn0, s[nt][1] - mn0));
                pex[nt][1] = ex2_f16x2(pack2(s[nt][2] - mn1, s[nt][3] - mn1));
                float2 flo = __half22float2(*(__half2*)&pex[nt][0]);
                float2 fhi = __half22float2(*(__half2*)&pex[nt][1]);
                ls0 += flo.x + flo.y;
                ls1 += fhi.x + fhi.y;
            }
            li0 += ls0; li1 += ls1;

            // O += P V (1-term)
#pragma unroll
            for (int kc = 0; kc < 4; kc++) {
                uint32_t pa[4];
                pa[0] = pex[2*kc][0];   pa[1] = pex[2*kc][1];
                pa[2] = pex[2*kc+1][0]; pa[3] = pex[2*kc+1][1];
#pragma unroll
                for (int np = 0; np < 4; np++) {
                    uint32_t vh4[4];
                    ldsm4t(vh4, base + SV + vboff + (uint32_t)kc * (16*FSTR) + np*32);
                    mma16816(o[2*np],   pa, vh4);
                    mma16816(o[2*np+1], pa, vh4 + 2);
                }
            }
        }

        __syncthreads();
        if (kt + 2 < ntiles) loadkv(kt + 2, bufi);
    }

    // final row sums + write O single fp16 [B,S,D]
    li0 += __shfl_xor_sync(0xffffffffu, li0, 1);
    li0 += __shfl_xor_sync(0xffffffffu, li0, 2);
    li1 += __shfl_xor_sync(0xffffffffu, li1, 1);
    li1 += __shfl_xor_sync(0xffffffffu, li1, 2);
    const float inv0 = 1.f / li0, inv1 = 1.f / li1;
    const int b = bh >> 4, h = bh & (HH - 1);
    const int qr = q0 + wid*16 + (lane >> 2);
    const size_t rowA = ((size_t)(b*SS + qr)) * DD + h * DK;
    const size_t rowB = rowA + 8 * DD;
    __half2* OA2 = (__half2*)OA;
#pragma unroll
    for (int nt = 0; nt < 8; nt++) {
        const int dk = nt*8 + (lane & 3)*2;
        OA2[(rowA + dk) >> 1] = __floats2half2_rn(o[nt][0]*inv0, o[nt][1]*inv0);
        OA2[(rowB + dk) >> 1] = __floats2half2_rn(o[nt][2]*inv1, o[nt][3]*inv1);
    }
}

// ------------------------- residual add + layernorm + fp16 out --------------
__global__ __launch_bounds__(128)
void add_ln_kernel(float* __restrict__ x, const float* __restrict__ r,
                   const float* __restrict__ w, const float* __restrict__ bias,
                   __half* __restrict__ xa) {
    __shared__ float sh[4];
    const int row = blockIdx.x;
    const int tid = threadIdx.x;
    float4* xr = (float4*)(x + (size_t)row * DD);
    const float4* rr = (const float4*)(r + (size_t)row * DD);
    float4 v0 = xr[tid], v1 = xr[tid + 128];
    float4 a0 = rr[tid], a1 = rr[tid + 128];
    v0.x += a0.x; v0.y += a0.y; v0.z += a0.z; v0.w += a0.w;
    v1.x += a1.x; v1.y += a1.y; v1.z += a1.z; v1.w += a1.w;

    float s = v0.x+v0.y+v0.z+v0.w + v1.x+v1.y+v1.z+v1.w;
#pragma unroll
    for (int o = 16; o > 0; o >>= 1) s += __shfl_down_sync(0xffffffffu, s, o);
    if ((tid & 31) == 0) sh[tid >> 5] = s;
    __syncthreads();
    float mean = (sh[0]+sh[1]+sh[2]+sh[3]) * (1.f/DD);
    __syncthreads();

    float dx0 = v0.x-mean, dx1 = v0.y-mean, dx2 = v0.z-mean, dx3 = v0.w-mean;
    float dy0 = v1.x-mean, dy1 = v1.y-mean, dy2 = v1.z-mean, dy3 = v1.w-mean;
    float sq = dx0*dx0+dx1*dx1+dx2*dx2+dx3*dx3 + dy0*dy0+dy1*dy1+dy2*dy2+dy3*dy3;
#pragma unroll
    for (int o = 16; o > 0; o >>= 1) sq += __shfl_down_sync(0xffffffffu, sq, o);
    if ((tid & 31) == 0) sh[tid >> 5] = sq;
    __syncthreads();
    float var = (sh[0]+sh[1]+sh[2]+sh[3]) * (1.f/DD);
    float rs = rsqrtf(var + 1e-5f);

    float4 w0 = ((const float4*)w)[tid],     w1 = ((const float4*)w)[tid + 128];
    float4 b0 = ((const float4*)bias)[tid],  b1 = ((const float4*)bias)[tid + 128];
    float4 o0 = make_float4(dx0*rs*w0.x+b0.x, dx1*rs*w0.y+b0.y,
                            dx2*rs*w0.z+b0.z, dx3*rs*w0.w+b0.w);
    float4 o1 = make_float4(dy0*rs*w1.x+b1.x, dy1*rs*w1.y+b1.y,
                            dy2*rs*w1.z+b1.z, dy3*rs*w1.w+b1.w);
    xr[tid]       = o0;
    xr[tid + 128] = o1;

    __half2* H = (__half2*)(xa + (size_t)row * DD);
    H[tid*2]         = __floats2half2_rn(o0.x, o0.y);
    H[tid*2 + 1]     = __floats2half2_rn(o0.z, o0.w);
    H[(tid+128)*2]   = __floats2half2_rn(o1.x, o1.y);
    H[(tid+128)*2+1] = __floats2half2_rn(o1.z, o1.w);
}

// ------------------------- launch ------------------------------------------
extern "C" void kernel_launch(void* const* d_in, const int* in_sizes, int n_in,
                              void* d_out, int out_size) {
    (void)in_sizes; (void)n_in; (void)out_size;
    const int*   idx  = (const int*)  d_in[0];
    const float* emb  = (const float*)d_in[1];
    const float* Wq   = (const float*)d_in[2];
    const float* Wk   = (const float*)d_in[3];
    const float* Wv   = (const float*)d_in[4];
    const float* Wo   = (const float*)d_in[5];
    const float* ln1w = (const float*)d_in[6];
    const float* ln1b = (const float*)d_in[7];
    const float* W1   = (const float*)d_in[8];
    const float* W2   = (const float*)d_in[9];
    const float* ln2w = (const float*)d_in[10];
    const float* ln2b = (const float*)d_in[11];
    const float* Wout = (const float*)d_in[12];

    float *x, *t;
    __half *wh, *xa, *oa, *fa, *qa, *ka, *va;
    cudaGetSymbolAddress((void**)&x, g_x);
    cudaGetSymbolAddress((void**)&t, g_t);
    cudaGetSymbolAddress((void**)&wh, g_wh);
    cudaGetSymbolAddress((void**)&xa, g_xa);
    cudaGetSymbolAddress((void**)&oa, g_oa);
    cudaGetSymbolAddress((void**)&fa, g_fa);
    cudaGetSymbolAddress((void**)&qa, g_qa);
    cudaGetSymbolAddress((void**)&ka, g_ka);
    cudaGetSymbolAddress((void**)&va, g_va);

    cudaFuncSetAttribute(gemm_tc<0,0>, cudaFuncAttributeMaxDynamicSharedMemorySize, GSMEM);
    cudaFuncSetAttribute(gemm_tc<0,1>, cudaFuncAttributeMaxDynamicSharedMemorySize, GSMEM);
    cudaFuncSetAttribute(gemm_tc<1,2>, cudaFuncAttributeMaxDynamicSharedMemorySize, GSMEM);
    cudaFuncSetAttribute(flash_tc, cudaFuncAttributeMaxDynamicSharedMemorySize, FSMEM);

    // weight conversion: single pass over all tensors
    {
        const int nthreads = (int)(WTOT / 8);
        wconv_all<<<(nthreads + 255)/256, 256>>>(Wq, Wk, Wv, Wo, W1, W2, Wout, wh);
    }

    embed_kernel<<<(BB*SS*(DD/2) + 255) / 256, 256>>>(idx, emb, x, xa);

    for (int l = 0; l < LL; l++) {
        const size_t wqkv = WQKV + (size_t)l * 3*DD*DD;
        const size_t ws   = (size_t)l * DD * DD;
        const size_t wf   = (size_t)l * DFF * DD;
        // fused QKV (N = 3072)
        gemm_tc<0,1><<<dim3(24, 32), 256, GSMEM>>>(xa, wh+wqkv,
                                                   nullptr, qa, ka, va,
                                                   MM, 3*DD, DD);
        flash_tc<<<dim3(SS/128, BB*HH), 256, FSMEM>>>(qa, ka, va, oa);
        gemm_tc<0,0><<<dim3(8, 32), 256, GSMEM>>>(oa, wh+WOO+ws,
                                                  t, nullptr, nullptr, nullptr,
                                                  MM, DD, DD);
        add_ln_kernel<<<MM, 128>>>(x, t, ln1w + l*DD, ln1b + l*DD, xa);
        gemm_tc<1,2><<<dim3(32, 32), 256, GSMEM>>>(xa, wh+W1O+wf,
                                                   nullptr, fa, nullptr, nullptr,
                                                   MM, DFF, DD);
        gemm_tc<0,0><<<dim3(8, 32), 256, GSMEM>>>(fa, wh+W2O+wf,
                                                  t, nullptr, nullptr, nullptr,
                                                  MM, DD, DFF);
        add_ln_kernel<<<MM, 128>>>(x, t, ln2w + l*DD, ln2b + l*DD, xa);
    }
    gemm_tc<0,0><<<dim3(16, 32), 256, GSMEM>>>(xa, wh+WUO,
                                               (float*)d_out, nullptr, nullptr, nullptr,
                                               MM, VV, DD);
}

// round 17
// speedup vs baseline: 7.4788x; 1.0141x over previous
#include <cuda_runtime.h>
#include <cuda_fp16.h>
#include <math.h>
#include <stdint.h>

// Problem constants
#define BB   2
#define SS   2048
#define DD   1024
#define HH   16
#define LL   4
#define VV   2000
#define DK   64
#define DFF  4096
#define MM   (BB*SS)          // 4096 rows

// ------------------------- scratch (static device memory) -------------------
__device__ float g_x[MM*DD];      // activations [B*S, D] fp32 (residual path)
__device__ float g_t[MM*DD];      // temp (pre-LN residual branch)

// single-fp16 weights
#define WQKV 0u                    // [L][Wq;Wk;Wv] each 1024x1024
#define WOO  12582912u
#define W1O  16777216u
#define W2O  33554432u
#define WUO  50331648u
#define WTOT 52379648u
__device__ __half g_wh[WTOT];
// single-fp16 activations
__device__ __half g_xa[MM*DD];     // LN output
__device__ __half g_oa[MM*DD];     // attention out [B,S,D]
__device__ __half g_fa[MM*DFF];    // FFN hidden (post-relu)
__device__ __half g_qa[MM*DD];     // [B,H,S,DK] (pre-scaled by log2e/8)
__device__ __half g_ka[MM*DD];
__device__ __half g_va[MM*DD];

// ------------------------- PTX helpers --------------------------------------
__device__ __forceinline__ uint32_t s2u(const void* p) {
    uint32_t a;
    asm("{ .reg .u64 t; cvta.to.shared.u64 t, %1; cvt.u32.u64 %0, t; }"
        : "=r"(a) : "l"(p));
    return a;
}
__device__ __forceinline__ void cpa16(uint32_t s, const void* g) {
    asm volatile("cp.async.cg.shared.global [%0], [%1], 16;" :: "r"(s), "l"(g));
}
__device__ __forceinline__ void ldsm4(uint32_t* r, uint32_t a) {
    asm volatile("ldmatrix.sync.aligned.m8n8.x4.shared.b16 {%0,%1,%2,%3}, [%4];"
                 : "=r"(r[0]), "=r"(r[1]), "=r"(r[2]), "=r"(r[3]) : "r"(a));
}
__device__ __forceinline__ void ldsm4t(uint32_t* r, uint32_t a) {
    asm volatile("ldmatrix.sync.aligned.m8n8.x4.trans.shared.b16 {%0,%1,%2,%3}, [%4];"
                 : "=r"(r[0]), "=r"(r[1]), "=r"(r[2]), "=r"(r[3]) : "r"(a));
}
__device__ __forceinline__ void mma16816(float* c, const uint32_t* a, const uint32_t* b) {
    asm volatile(
        "mma.sync.aligned.m16n8k16.row.col.f32.f16.f16.f32 "
        "{%0,%1,%2,%3}, {%4,%5,%6,%7}, {%8,%9}, {%0,%1,%2,%3};"
        : "+f"(c[0]), "+f"(c[1]), "+f"(c[2]), "+f"(c[3])
        : "r"(a[0]), "r"(a[1]), "r"(a[2]), "r"(a[3]), "r"(b[0]), "r"(b[1]));
}
__device__ __forceinline__ uint32_t ex2_f16x2(uint32_t x) {
    uint32_t r;
    asm("ex2.approx.f16x2 %0, %1;" : "=r"(r) : "r"(x));
    return r;
}

// ------------------------- convert helpers -----------------------------------
__device__ __forceinline__ uint32_t pack2(float a, float b) {
    __half2 h2 = __floats2half2_rn(a, b);
    return *(uint32_t*)&h2;
}

// single-pass weight conversion for ALL weight tensors (16 halves per thread)
__global__ void wconv_all(const float* __restrict__ Wq, const float* __restrict__ Wk,
                          const float* __restrict__ Wv, const float* __restrict__ Wo,
                          const float* __restrict__ W1, const float* __restrict__ W2,
                          const float* __restrict__ Wout, __half* __restrict__ wh) {
    size_t i = ((size_t)blockIdx.x * blockDim.x + threadIdx.x) * 16;  // half index
    if (i >= WTOT) return;
    const float* src;
    if (i < WOO) {
        size_t l   = i / (3u*DD*DD);
        size_t rem = i - l * (3u*DD*DD);
        size_t j   = rem / ((size_t)DD*DD);
        size_t off = rem - j * ((size_t)DD*DD);
        const float* W = (j == 0) ? Wq : (j == 1) ? Wk : Wv;
        src = W + l * (size_t)DD*DD + off;
    } else if (i < W1O) src = Wo   + (i - WOO);
    else if (i < W2O)   src = W1   + (i - W1O);
    else if (i < WUO)   src = W2   + (i - W2O);
    else                src = Wout + (i - WUO);
    float4 v0 = ((const float4*)src)[0];
    float4 v1 = ((const float4*)src)[1];
    float4 v2 = ((const float4*)src)[2];
    float4 v3 = ((const float4*)src)[3];
    uint4 o0, o1;
    o0.x = pack2(v0.x, v0.y); o0.y = pack2(v0.z, v0.w);
    o0.z = pack2(v1.x, v1.y); o0.w = pack2(v1.z, v1.w);
    o1.x = pack2(v2.x, v2.y); o1.y = pack2(v2.z, v2.w);
    o1.z = pack2(v3.x, v3.y); o1.w = pack2(v3.z, v3.w);
    *(uint4*)(wh + i)     = o0;
    *(uint4*)(wh + i + 8) = o1;
}

// ------------------------- embedding + positional encoding ------------------
__global__ void embed_kernel(const int* __restrict__ idx,
                             const float* __restrict__ emb,
                             float* __restrict__ x, __half* __restrict__ xa) {
    int t = blockIdx.x * blockDim.x + threadIdx.x;
    if (t >= BB*SS*(DD/2)) return;
    int dp = t & 511;
    int bs = t >> 9;
    int s  = bs & (SS - 1);
    int d  = dp << 1;
    double freq = exp((double)d * (-9.210340371976184 / 1024.0));
    double ang  = (double)s * freq;
    double sv, cv;
    sincos(ang, &sv, &cv);
    int tok = idx[bs];
    float2 e = ((const float2*)emb)[(size_t)tok * 512 + dp];
    float vx = e.x + (float)sv, vy = e.y + (float)cv;
    ((float2*)x)[t] = make_float2(vx, vy);
    ((__half2*)xa)[t] = __floats2half2_rn(vx, vy);
}

// ------------------------- mma.sync fp16 1-term GEMM -------------------------
// C[M,N] = A[M,K] * B[N,K]^T, A and B single fp16, fp32 accum.
// CTA tile 128x128, K-tile 32, 256 thr, 8 warps (64x32 warp tiles), 2 CTAs/SM.
// 4-buffer cp.async pipeline, ONE barrier per k-tile.
// OMODE: 0 = fp32 row-major out
//        1 = fused QKV (N=3072): q(*log2e/8)/k/v single fp16, remap [B,H,S,DK]
//        2 = fp16 single row-major out (with optional relu)
#define LDSB   80            // smem row stride in bytes (40 fp16)
#define ATILE  (128*LDSB)    // 10240
#define BTILE  (128*LDSB)    // 10240
#define STAGEB (ATILE + BTILE)       // 20480
#define NSTAGE 4
#define GSMEM  (NSTAGE*STAGEB)       // 81920

template<int ACT, int OMODE>
__global__ __launch_bounds__(256, 2)
void gemm_tc(const __half* __restrict__ Aq, const __half* __restrict__ Bq,
             float* __restrict__ C,
             __half* __restrict__ P0, __half* __restrict__ P1,
             __half* __restrict__ P2,
             int M, int N, int K)
{
    extern __shared__ __align__(16) char smem[];
    const uint32_t sb = s2u(smem);
    const int tid = threadIdx.x;
    const int wid = tid >> 5, lane = tid & 31;
    const int wm = wid & 1, wn = wid >> 1;       // warp 64x32 tile
    const int row0 = blockIdx.y * 128, col0 = blockIdx.x * 128;

    const int chunk = tid & 3;
    const int rr    = tid >> 2;
    const int rA0 = row0 + rr, rA1 = rA0 + 64;
    int rB0 = col0 + rr;      if (rB0 > N - 1) rB0 = N - 1;
    int rB1 = col0 + rr + 64; if (rB1 > N - 1) rB1 = N - 1;
    const uint32_t sA0 = (uint32_t)rr * LDSB + (uint32_t)chunk * 16;

    auto issue = [&](int kt, int buf) {
        const int ko = kt * 32 + chunk * 8;
        const uint32_t base = sb + (uint32_t)buf * STAGEB;
        cpa16(base + sA0,            Aq + (size_t)rA0 * K + ko);
        cpa16(base + sA0 + 64u*LDSB, Aq + (size_t)rA1 * K + ko);
        const uint32_t bb = base + ATILE;
        cpa16(bb + sA0,              Bq + (size_t)rB0 * K + ko);
        cpa16(bb + sA0 + 64u*LDSB,   Bq + (size_t)rB1 * K + ko);
        asm volatile("cp.async.commit_group;" ::: "memory");
    };

    float acc[4][4][4];
#pragma unroll
    for (int i = 0; i < 4; i++)
#pragma unroll
        for (int j = 0; j < 4; j++)
#pragma unroll
            for (int q = 0; q < 4; q++) acc[i][j][q] = 0.f;

    const int KT = K >> 5;
    issue(0, 0);
    issue(1, 1);
    issue(2, 2);

    const uint32_t aoff = (uint32_t)(wm*64 + (lane & 15)) * LDSB + ((lane >> 4) << 4);
    const uint32_t boff = (uint32_t)(wn*32 + (lane & 7) + ((lane >> 4) << 3)) * LDSB
                        + (((lane >> 3) & 1) << 4);

    int buf = 0;
#pragma unroll 1
    for (int kt = 0; kt < KT; kt++) {
        // wait for stage kt: leave at most (#groups issued beyond kt) outstanding
        if (kt + 2 < KT)      asm volatile("cp.async.wait_group 2;" ::: "memory");
        else if (kt + 1 < KT) asm volatile("cp.async.wait_group 1;" ::: "memory");
        else                  asm volatile("cp.async.wait_group 0;" ::: "memory");
        __syncthreads();
        // issue stage kt+3 into buf[(kt+3)&3] = buf[(kt-1)&3] (consumed at kt-1)
        if (kt + 3 < KT) issue(kt + 3, (kt + 3) & 3);
        const uint32_t base = sb + (uint32_t)buf * STAGEB;
#pragma unroll
        for (int ks = 0; ks < 2; ks++) {
            const uint32_t ka = base + (uint32_t)ks * 32 + aoff;
            const uint32_t kb = base + ATILE + (uint32_t)ks * 32 + boff;
            uint32_t ah[4][4];
#pragma unroll
            for (int mt = 0; mt < 4; mt++)
                ldsm4(ah[mt], ka + (uint32_t)mt * (16*LDSB));
#pragma unroll
            for (int p = 0; p < 2; p++) {
                uint32_t b4[4];
                ldsm4(b4, kb + (uint32_t)p * (16*LDSB));
#pragma unroll
                for (int mt = 0; mt < 4; mt++) {
                    mma16816(acc[mt][2*p],   ah[mt], b4);
                    mma16816(acc[mt][2*p+1], ah[mt], b4 + 2);
                }
            }
        }
        buf = (buf + 1) & 3;
    }

    const int base_m = row0 + wm*64;
    const int base_n = col0 + wn*32;
#pragma unroll
    for (int mt = 0; mt < 4; mt++) {
#pragma unroll
        for (int nt = 0; nt < 4; nt++) {
            float* c = acc[mt][nt];
            if (ACT == 1) {
                c[0] = fmaxf(c[0], 0.f); c[1] = fmaxf(c[1], 0.f);
                c[2] = fmaxf(c[2], 0.f); c[3] = fmaxf(c[3], 0.f);
            }
            const int r0 = base_m + mt*16 + (lane >> 2);
            const int cc = base_n + nt*8 + (lane & 3)*2;
            if (OMODE == 0) {
                if (cc < N) {
                    *(float2*)(C + (size_t)r0 * N + cc)       = make_float2(c[0], c[1]);
                    *(float2*)(C + (size_t)(r0 + 8) * N + cc) = make_float2(c[2], c[3]);
                }
            } else if (OMODE == 1) {
                // fused QKV: n in [0,3072)
                const int sect = cc >> 10;
                const int nc = cc & 1023;
                const int h = nc >> 6, kk = nc & (DK - 1);
                const int b0i = r0 >> 11, s0r = r0 & (SS - 1);
                const size_t i0 = (((size_t)(b0i*HH + h)*SS + s0r)*DK + kk) >> 1;
                const int r1 = r0 + 8;
                const int b1i = r1 >> 11, s1r = r1 & (SS - 1);
                const size_t i1 = (((size_t)(b1i*HH + h)*SS + s1r)*DK + kk) >> 1;
                __half2* dst = (__half2*)((sect == 0) ? P0 : (sect == 1) ? P1 : P2);
                // Q pre-scaled by log2(e)/sqrt(DK) (flash works in log2 domain)
                const float sc = (sect == 0) ? 0.180336884f : 1.f;
                dst[i0] = __floats2half2_rn(c[0]*sc, c[1]*sc);
                dst[i1] = __floats2half2_rn(c[2]*sc, c[3]*sc);
            } else {
                if (cc < N) {
                    ((__half2*)P0)[((size_t)r0 * N + cc) >> 1]
                        = __floats2half2_rn(c[0], c[1]);
                    ((__half2*)P0)[((size_t)(r0 + 8) * N + cc) >> 1]
                        = __floats2half2_rn(c[2], c[3]);
                }
            }
        }
    }
}

// ------------------------- tensor-core flash attention ----------------------
// Q single fp16 (pre-scaled log2e/8), K/V single fp16 in [B,H,S,DK]. Causal.
// CTA = 128 q-rows, 8 warps (16 q-rows each). k-tile 64. Log2-domain softmax
// with ex2.approx.f16x2. 3-stage KV ring, ONE barrier per k-tile.
#define FSTR   144                 // smem row stride bytes (64 fp16 + pad)
#define FQSZ   (128*FSTR)          // 18432
#define SKH    0
#define SV     9216
#define FSTAGE 18432
#define FSMEM  (FQSZ + 3*FSTAGE)   // 73728

__global__ __launch_bounds__(256, 2)
void flash_tc(const __half* __restrict__ Qa, const __half* __restrict__ Ka,
              const __half* __restrict__ Va, __half* __restrict__ OA)
{
    extern __shared__ __align__(16) char smem[];
    const uint32_t sb = s2u(smem);
    const int bh  = blockIdx.y;
    const int qt  = gridDim.x - 1 - blockIdx.x;   // heavy blocks first
    const int tid = threadIdx.x, wid = tid >> 5, lane = tid & 31;
    const int q0  = qt * 128;
    const int ntiles = 2*qt + 2;

    // Q tile load (own commit group)
    {
        const size_t g = ((size_t)bh * SS + q0) * DK;
#pragma unroll
        for (int c = tid; c < 1024; c += 256) {
            const int row = c >> 3, ch = c & 7;
            cpa16(sb + (uint32_t)row * FSTR + (uint32_t)ch * 16,
                  Qa + g + row * DK + ch * 8);
        }
        asm volatile("cp.async.commit_group;" ::: "memory");
    }

    auto loadkv = [&](int kt, int bufi) {
        const uint32_t base = sb + FQSZ + (uint32_t)bufi * FSTAGE;
        const size_t g = ((size_t)bh * SS + kt * 64) * DK;
#pragma unroll
        for (int c = tid; c < 512; c += 256) {
            const int row = c >> 3, ch = c & 7;
            const uint32_t so = (uint32_t)row * FSTR + (uint32_t)ch * 16;
            const size_t go = g + row * DK + ch * 8;
            cpa16(base + SKH + so, Ka + go);
            cpa16(base + SV  + so, Va + go);
        }
        asm volatile("cp.async.commit_group;" ::: "memory");
    };

    loadkv(0, 0);
    if (ntiles > 1) loadkv(1, 1);

    // Q + kv0 ready (kv1 may remain outstanding)
    if (ntiles > 1) asm volatile("cp.async.wait_group 1;" ::: "memory");
    else            asm volatile("cp.async.wait_group 0;" ::: "memory");
    __syncthreads();

    // Q fragments (16 rows per warp)
    uint32_t qf[4][4];
    {
        const uint32_t a0 = sb + (uint32_t)(wid*16 + (lane & 15)) * FSTR + ((lane >> 4) << 4);
#pragma unroll
        for (int kc = 0; kc < 4; kc++)
            ldsm4(qf[kc], a0 + kc*32);
    }

    float o[8][4];
#pragma unroll
    for (int i = 0; i < 8; i++)
#pragma unroll
        for (int j = 0; j < 4; j++) o[i][j] = 0.f;
    float mi0 = -1e30f, mi1 = -1e30f, li0 = 0.f, li1 = 0.f;

    const uint32_t kboff = (uint32_t)((lane & 7) + ((lane >> 4) << 3)) * FSTR
                         + (((lane >> 3) & 1) << 4);
    const uint32_t vboff = (uint32_t)((((lane >> 3) & 1) << 3) + (lane & 7)) * FSTR
                         + ((lane >> 4) << 4);

    int bufi = 0;
#pragma unroll 1
    for (int kt = 0; kt < ntiles; kt++) {
        if (kt > 0) {
            if (kt + 1 < ntiles) asm volatile("cp.async.wait_group 1;" ::: "memory");
            else                 asm volatile("cp.async.wait_group 0;" ::: "memory");
            __syncthreads();
        }
        // issue kv(kt+2) into buf[(kt+2)%3] = buf[(kt-1)%3] (consumed at kt-1)
        if (kt + 2 < ntiles) loadkv(kt + 2, (kt + 2) % 3);
        const uint32_t base = sb + FQSZ + (uint32_t)bufi * FSTAGE;

        // last diagonal tile: warps 0-3 (rows 0-63) fully masked -> skip body
        const bool skip = (kt == ntiles - 1) && (wid < 4);
        if (!skip) {
            // S = Q K^T (1-term); Q pre-scaled into log2 domain
            float s[8][4];
#pragma unroll
            for (int i = 0; i < 8; i++)
#pragma unroll
                for (int j = 0; j < 4; j++) s[i][j] = 0.f;
#pragma unroll
            for (int kc = 0; kc < 4; kc++) {
#pragma unroll
                for (int np = 0; np < 4; np++) {
                    uint32_t kh4[4];
                    ldsm4(kh4, base + SKH + kboff + kc*32 + (uint32_t)np * (16*FSTR));
                    mma16816(s[2*np],   qf[kc], kh4);
                    mma16816(s[2*np+1], qf[kc], kh4 + 2);
                }
            }

            // causal mask (last two k-tiles only)
            if (kt >= ntiles - 2) {
                const int rk = wid*16 + (lane >> 2) - (kt*64 - q0);
                const int cb = (lane & 3) * 2;
#pragma unroll
                for (int nt = 0; nt < 8; nt++) {
                    const int k0 = nt*8 + cb;
                    if (k0     > rk    ) s[nt][0] = -1e30f;
                    if (k0 + 1 > rk    ) s[nt][1] = -1e30f;
                    if (k0     > rk + 8) s[nt][2] = -1e30f;
                    if (k0 + 1 > rk + 8) s[nt][3] = -1e30f;
                }
            }

            // online softmax (log2 domain)
            float m0 = -1e30f, m1 = -1e30f;
#pragma unroll
            for (int nt = 0; nt < 8; nt++) {
                m0 = fmaxf(m0, fmaxf(s[nt][0], s[nt][1]));
                m1 = fmaxf(m1, fmaxf(s[nt][2], s[nt][3]));
            }
            m0 = fmaxf(m0, __shfl_xor_sync(0xffffffffu, m0, 1));
            m0 = fmaxf(m0, __shfl_xor_sync(0xffffffffu, m0, 2));
            m1 = fmaxf(m1, __shfl_xor_sync(0xffffffffu, m1, 1));
            m1 = fmaxf(m1, __shfl_xor_sync(0xffffffffu, m1, 2));
            const float mn0 = fmaxf(mi0, m0), mn1 = fmaxf(mi1, m1);
            const float rs0 = exp2f(mi0 - mn0), rs1 = exp2f(mi1 - mn1);
            mi0 = mn0; mi1 = mn1;
            li0 *= rs0; li1 *= rs1;
#pragma unroll
            for (int nt = 0; nt < 8; nt++) {
                o[nt][0] *= rs0; o[nt][1] *= rs0;
                o[nt][2] *= rs1; o[nt][3] *= rs1;
            }

            // p = exp2(s - mn) directly in fp16 pairs (PV A-fragments)
            uint32_t pex[8][2];
            float ls0 = 0.f, ls1 = 0.f;
#pragma unroll
            for (int nt = 0; nt < 8; nt++) {
                pex[nt][0] = ex2_f16x2(pack2(s[nt][0] - mn0, s[nt][1] - mn0));
                pex[nt][1] = ex2_f16x2(pack2(s[nt][2] - mn1, s[nt][3] - mn1));
                float2 flo = __half22float2(*(__half2*)&pex[nt][0]);
                float2 fhi = __half22float2(*(__half2*)&pex[nt][1]);
                ls0 += flo.x + flo.y;
                ls1 += fhi.x + fhi.y;
            }
            li0 += ls0; li1 += ls1;

            // O += P V (1-term)
#pragma unroll
            for (int kc = 0; kc < 4; kc++) {
                uint32_t pa[4];
                pa[0] = pex[2*kc][0];   pa[1] = pex[2*kc][1];
                pa[2] = pex[2*kc+1][0]; pa[3] = pex[2*kc+1][1];
#pragma unroll
                for (int np = 0; np < 4; np++) {
                    uint32_t vh4[4];
                    ldsm4t(vh4, base + SV + vboff + (uint32_t)kc * (16*FSTR) + np*32);
                    mma16816(o[2*np],   pa, vh4);
                    mma16816(o[2*np+1], pa, vh4 + 2);
                }
            }
        }

        bufi = (bufi == 2) ? 0 : bufi + 1;
    }

    // final row sums + write O single fp16 [B,S,D]
    li0 += __shfl_xor_sync(0xffffffffu, li0, 1);
    li0 += __shfl_xor_sync(0xffffffffu, li0, 2);
    li1 += __shfl_xor_sync(0xffffffffu, li1, 1);
    li1 += __shfl_xor_sync(0xffffffffu, li1, 2);
    const float inv0 = 1.f / li0, inv1 = 1.f / li1;
    const int b = bh >> 4, h = bh & (HH - 1);
    const int qr = q0 + wid*16 + (lane >> 2);
    const size_t rowA = ((size_t)(b*SS + qr)) * DD + h * DK;
    const size_t rowB = rowA + 8 * DD;
    __half2* OA2 = (__half2*)OA;
#pragma unroll
    for (int nt = 0; nt < 8; nt++) {
        const int dk = nt*8 + (lane & 3)*2;
        OA2[(rowA + dk) >> 1] = __floats2half2_rn(o[nt][0]*inv0, o[nt][1]*inv0);
        OA2[(rowB + dk) >> 1] = __floats2half2_rn(o[nt][2]*inv1, o[nt][3]*inv1);
    }
}

// ------------------------- residual add + layernorm + fp16 out --------------
__global__ __launch_bounds__(128)
void add_ln_kernel(float* __restrict__ x, const float* __restrict__ r,
                   const float* __restrict__ w, const float* __restrict__ bias,
                   __half* __restrict__ xa) {
    __shared__ float sh[4];
    const int row = blockIdx.x;
    const int tid = threadIdx.x;
    float4* xr = (float4*)(x + (size_t)row * DD);
    const float4* rr = (const float4*)(r + (size_t)row * DD);
    float4 v0 = xr[tid], v1 = xr[tid + 128];
    float4 a0 = rr[tid], a1 = rr[tid + 128];
    v0.x += a0.x; v0.y += a0.y; v0.z += a0.z; v0.w += a0.w;
    v1.x += a1.x; v1.y += a1.y; v1.z += a1.z; v1.w += a1.w;

    float s = v0.x+v0.y+v0.z+v0.w + v1.x+v1.y+v1.z+v1.w;
#pragma unroll
    for (int o = 16; o > 0; o >>= 1) s += __shfl_down_sync(0xffffffffu, s, o);
    if ((tid & 31) == 0) sh[tid >> 5] = s;
    __syncthreads();
    float mean = (sh[0]+sh[1]+sh[2]+sh[3]) * (1.f/DD);
    __syncthreads();

    float dx0 = v0.x-mean, dx1 = v0.y-mean, dx2 = v0.z-mean, dx3 = v0.w-mean;
    float dy0 = v1.x-mean, dy1 = v1.y-mean, dy2 = v1.z-mean, dy3 = v1.w-mean;
    float sq = dx0*dx0+dx1*dx1+dx2*dx2+dx3*dx3 + dy0*dy0+dy1*dy1+dy2*dy2+dy3*dy3;
#pragma unroll
    for (int o = 16; o > 0; o >>= 1) sq += __shfl_down_sync(0xffffffffu, sq, o);
    if ((tid & 31) == 0) sh[tid >> 5] = sq;
    __syncthreads();
    float var = (sh[0]+sh[1]+sh[2]+sh[3]) * (1.f/DD);
    float rs = rsqrtf(var + 1e-5f);

    float4 w0 = ((const float4*)w)[tid],     w1 = ((const float4*)w)[tid + 128];
    float4 b0 = ((const float4*)bias)[tid],  b1 = ((const float4*)bias)[tid + 128];
    float4 o0 = make_float4(dx0*rs*w0.x+b0.x, dx1*rs*w0.y+b0.y,
                            dx2*rs*w0.z+b0.z, dx3*rs*w0.w+b0.w);
    float4 o1 = make_float4(dy0*rs*w1.x+b1.x, dy1*rs*w1.y+b1.y,
                            dy2*rs*w1.z+b1.z, dy3*rs*w1.w+b1.w);
    xr[tid]       = o0;
    xr[tid + 128] = o1;

    __half2* H = (__half2*)(xa + (size_t)row * DD);
    H[tid*2]         = __floats2half2_rn(o0.x, o0.y);
    H[tid*2 + 1]     = __floats2half2_rn(o0.z, o0.w);
    H[(tid+128)*2]   = __floats2half2_rn(o1.x, o1.y);
    H[(tid+128)*2+1] = __floats2half2_rn(o1.z, o1.w);
}

// ------------------------- launch ------------------------------------------
extern "C" void kernel_launch(void* const* d_in, const int* in_sizes, int n_in,
                              void* d_out, int out_size) {
    (void)in_sizes; (void)n_in; (void)out_size;
    const int*   idx  = (const int*)  d_in[0];
    const float* emb  = (const float*)d_in[1];
    const float* Wq   = (const float*)d_in[2];
    const float* Wk   = (const float*)d_in[3];
    const float* Wv   = (const float*)d_in[4];
    const float* Wo   = (const float*)d_in[5];
    const float* ln1w = (const float*)d_in[6];
    const float* ln1b = (const float*)d_in[7];
    const float* W1   = (const float*)d_in[8];
    const float* W2   = (const float*)d_in[9];
    const float* ln2w = (const float*)d_in[10];
    const float* ln2b = (const float*)d_in[11];
    const float* Wout = (const float*)d_in[12];

    float *x, *t;
    __half *wh, *xa, *oa, *fa, *qa, *ka, *va;
    cudaGetSymbolAddress((void**)&x, g_x);
    cudaGetSymbolAddress((void**)&t, g_t);
    cudaGetSymbolAddress((void**)&wh, g_wh);
    cudaGetSymbolAddress((void**)&xa, g_xa);
    cudaGetSymbolAddress((void**)&oa, g_oa);
    cudaGetSymbolAddress((void**)&fa, g_fa);
    cudaGetSymbolAddress((void**)&qa, g_qa);
    cudaGetSymbolAddress((void**)&ka, g_ka);
    cudaGetSymbolAddress((void**)&va, g_va);

    cudaFuncSetAttribute(gemm_tc<0,0>, cudaFuncAttributeMaxDynamicSharedMemorySize, GSMEM);
    cudaFuncSetAttribute(gemm_tc<0,1>, cudaFuncAttributeMaxDynamicSharedMemorySize, GSMEM);
    cudaFuncSetAttribute(gemm_tc<1,2>, cudaFuncAttributeMaxDynamicSharedMemorySize, GSMEM);
    cudaFuncSetAttribute(flash_tc, cudaFuncAttributeMaxDynamicSharedMemorySize, FSMEM);

    // weight conversion: single pass over all tensors
    {
        const int nthreads = (int)(WTOT / 16);
        wconv_all<<<(nthreads + 255)/256, 256>>>(Wq, Wk, Wv, Wo, W1, W2, Wout, wh);
    }

    embed_kernel<<<(BB*SS*(DD/2) + 255) / 256, 256>>>(idx, emb, x, xa);

    for (int l = 0; l < LL; l++) {
        const size_t wqkv = WQKV + (size_t)l * 3*DD*DD;
        const size_t ws   = (size_t)l * DD * DD;
        const size_t wf   = (size_t)l * DFF * DD;
        // fused QKV (N = 3072)
        gemm_tc<0,1><<<dim3(24, 32), 256, GSMEM>>>(xa, wh+wqkv,
                                                   nullptr, qa, ka, va,
                                                   MM, 3*DD, DD);
        flash_tc<<<dim3(SS/128, BB*HH), 256, FSMEM>>>(qa, ka, va, oa);
        gemm_tc<0,0><<<dim3(8, 32), 256, GSMEM>>>(oa, wh+WOO+ws,
                                                  t, nullptr, nullptr, nullptr,
                                                  MM, DD, DD);
        add_ln_kernel<<<MM, 128>>>(x, t, ln1w + l*DD, ln1b + l*DD, xa);
        gemm_tc<1,2><<<dim3(32, 32), 256, GSMEM>>>(xa, wh+W1O+wf,
                                                   nullptr, fa, nullptr, nullptr,
                                                   MM, DFF, DD);
        gemm_tc<0,0><<<dim3(8, 32), 256, GSMEM>>>(fa, wh+W2O+wf,
                                                  t, nullptr, nullptr, nullptr,
                                                  MM, DD, DFF);
        add_ln_kernel<<<MM, 128>>>(x, t, ln2w + l*DD, ln2b + l*DD, xa);
    }
    gemm_tc<0,0><<<dim3(16, 32), 256, GSMEM>>>(xa, wh+WUO,
                                               (float*)d_out, nullptr, nullptr, nullptr,
                                               MM, VV, DD);
}